// round 2
// baseline (speedup 1.0000x reference)
#include <cuda_runtime.h>
#include <cuda_bf16.h>
#include <math.h>

// ============================================================================
// Attention-LSTM decoder (teacher forced), B=64, T_out=31, T_in=60, U=512,
// EMB=300, VOCAB=34004.
//
// Structure:
//   setup (parallel): zero attn0; gather embeddings; zpre = embAll @ Wk[0:300] + bk;
//                     keys = memory @ Wm
//   per step t (sequential, 5 launches):
//     z       = zpre[t] + attn_prev @ Wk[300:812] + h @ Uk        (dual GEMM)
//     h,c     = LSTM pointwise(z, c)
//     q       = h @ Wq                                            (small GEMM)
//     ctx     = softmax(v . tanh(keys + q)) @ memory              (fused)
//     state_t = [h | ctx] @ Wa  -> g_states[b][t][:]              (dual GEMM)
//   final: out = g_states @ Wfc + bfc   (one [1984 x 34004 x 512] SGEMM)
// ============================================================================

#define B64   64
#define TOUT  31
#define TIN   60
#define UNITS 512
#define EMB   300
#define VOCAB 34004
#define ROWS  (B64 * TOUT)   // 1984

// ---------------- scratch (device globals; no allocation allowed) -----------
__device__ float g_keys  [B64 * TIN * UNITS];     // [b][t_in][u]
__device__ float g_embA  [ROWS * EMB];            // rows r = t*64 + b
__device__ float g_zpre  [ROWS * 4 * UNITS];      // rows r = t*64 + b
__device__ float g_z     [B64 * 4 * UNITS];
__device__ float g_hbuf  [2][B64 * UNITS];
__device__ float g_cbuf  [2][B64 * UNITS];
__device__ float g_q     [B64 * UNITS];
__device__ float g_ctx   [B64 * UNITS];
__device__ float g_attn0 [B64 * UNITS];
__device__ float g_states[ROWS * UNITS];          // [b][t][u] : row = b*31 + t

// ---------------------------------------------------------------------------
__global__ void zero_kernel(float* p, int n) {
    int i = blockIdx.x * blockDim.x + threadIdx.x;
    if (i < n) p[i] = 0.f;
}

// g_embA[r = t*64+b][e] = embedding[dec[b][t]][e]
__global__ void gather_emb_kernel(const int* __restrict__ dec,
                                  const float* __restrict__ emb,
                                  float* __restrict__ out) {
    int r = blockIdx.x;          // 0..1983
    int t = r >> 6;
    int b = r & 63;
    int tok = dec[b * TOUT + t];
    const float* src = emb + (size_t)tok * EMB;
    float* dst = out + (size_t)r * EMB;
    for (int e = threadIdx.x; e < EMB; e += blockDim.x) dst[e] = src[e];
}

// ---------------------------------------------------------------------------
// Generic tiled SGEMM: C[M,N] = A[M,K] @ B[K,N] (+ bias[n]); row-major, lda/ldb/ldc.
template<int BM, int BN, int BK, int TM, int TN>
__global__ void sgemm_kernel(const float* __restrict__ A, int lda,
                             const float* __restrict__ B, int ldb,
                             const float* __restrict__ bias,
                             float* __restrict__ C, int ldc,
                             int M, int N, int K)
{
    constexpr int THREADS = (BM / TM) * (BN / TN);
    __shared__ __align__(16) float As[BK][BM];
    __shared__ __align__(16) float Bs[BK][BN];
    const int bm = blockIdx.y * BM;
    const int bn = blockIdx.x * BN;
    const int tid = threadIdx.x;
    const int tx = tid % (BN / TN);
    const int ty = tid / (BN / TN);

    float acc[TM][TN];
#pragma unroll
    for (int i = 0; i < TM; i++)
#pragma unroll
        for (int j = 0; j < TN; j++) acc[i][j] = 0.f;

    for (int k0 = 0; k0 < K; k0 += BK) {
        // A tile (BM x BK): float4 along K, stored transposed into As[k][m]
        for (int i = tid; i < BM * BK / 4; i += THREADS) {
            int r  = i / (BK / 4);
            int cq = i % (BK / 4);
            int gm = bm + r;
            int gk = k0 + cq * 4;
            float4 v;
            if (gm < M && gk + 3 < K) {
                v = *(const float4*)(A + (size_t)gm * lda + gk);
            } else {
                v.x = (gm < M && gk + 0 < K) ? A[(size_t)gm * lda + gk + 0] : 0.f;
                v.y = (gm < M && gk + 1 < K) ? A[(size_t)gm * lda + gk + 1] : 0.f;
                v.z = (gm < M && gk + 2 < K) ? A[(size_t)gm * lda + gk + 2] : 0.f;
                v.w = (gm < M && gk + 3 < K) ? A[(size_t)gm * lda + gk + 3] : 0.f;
            }
            As[cq * 4 + 0][r] = v.x;
            As[cq * 4 + 1][r] = v.y;
            As[cq * 4 + 2][r] = v.z;
            As[cq * 4 + 3][r] = v.w;
        }
        // B tile (BK x BN): float4 along N
        for (int i = tid; i < BK * BN / 4; i += THREADS) {
            int r  = i / (BN / 4);
            int cq = i % (BN / 4);
            int gk = k0 + r;
            int gn = bn + cq * 4;
            float4 v;
            if (gk < K && gn + 3 < N) {
                v = *(const float4*)(B + (size_t)gk * ldb + gn);
            } else {
                v.x = (gk < K && gn + 0 < N) ? B[(size_t)gk * ldb + gn + 0] : 0.f;
                v.y = (gk < K && gn + 1 < N) ? B[(size_t)gk * ldb + gn + 1] : 0.f;
                v.z = (gk < K && gn + 2 < N) ? B[(size_t)gk * ldb + gn + 2] : 0.f;
                v.w = (gk < K && gn + 3 < N) ? B[(size_t)gk * ldb + gn + 3] : 0.f;
            }
            *(float4*)&Bs[r][cq * 4] = v;
        }
        __syncthreads();
#pragma unroll
        for (int kk = 0; kk < BK; kk++) {
            float a[TM], b[TN];
            if constexpr (TM % 4 == 0) {
#pragma unroll
                for (int i = 0; i < TM; i += 4)
                    *(float4*)&a[i] = *(const float4*)&As[kk][ty * TM + i];
            } else {
#pragma unroll
                for (int i = 0; i < TM; i++) a[i] = As[kk][ty * TM + i];
            }
            if constexpr (TN % 4 == 0) {
#pragma unroll
                for (int j = 0; j < TN; j += 4)
                    *(float4*)&b[j] = *(const float4*)&Bs[kk][tx * TN + j];
            } else {
#pragma unroll
                for (int j = 0; j < TN; j++) b[j] = Bs[kk][tx * TN + j];
            }
#pragma unroll
            for (int i = 0; i < TM; i++)
#pragma unroll
                for (int j = 0; j < TN; j++)
                    acc[i][j] = fmaf(a[i], b[j], acc[i][j]);
        }
        __syncthreads();
    }
#pragma unroll
    for (int i = 0; i < TM; i++) {
        int gm = bm + ty * TM + i;
        if (gm >= M) continue;
#pragma unroll
        for (int j = 0; j < TN; j++) {
            int gn = bn + tx * TN + j;
            if (gn < N)
                C[(size_t)gm * ldc + gn] = acc[i][j] + (bias ? bias[gn] : 0.f);
        }
    }
}

// ---------------------------------------------------------------------------
// Dual GEMM: C[64,N] = A1[64,512]@B1 + A2[64,512]@B2 (+ addend[64,N]).
// BM=64 (full batch), BN=16, BK=16, 256 threads, TM=4/TN=1.
__global__ void dual_gemm_kernel(const float* __restrict__ A1, int lda1,
                                 const float* __restrict__ B1, int ldb,
                                 const float* __restrict__ A2, int lda2,
                                 const float* __restrict__ B2,
                                 const float* __restrict__ addend, int ldadd,
                                 float* __restrict__ C, int ldc)
{
    constexpr int BN = 16, BK = 16;
    __shared__ __align__(16) float As[BK][64];
    __shared__ __align__(16) float Bs[BK][BN];
    const int bn = blockIdx.x * BN;
    const int tid = threadIdx.x;
    const int tx = tid % 16;   // n
    const int ty = tid / 16;   // row group (4 rows each)
    float acc[4] = {0.f, 0.f, 0.f, 0.f};

#pragma unroll 1
    for (int half = 0; half < 2; half++) {
        const float* A = half ? A2 : A1;
        const int lda  = half ? lda2 : lda1;
        const float* B = half ? B2 : B1;
        for (int k0 = 0; k0 < UNITS; k0 += BK) {
            {   // A tile 64x16 : 256 float4 loads, transposed store
                int r  = tid >> 2;
                int cq = tid & 3;
                float4 v = *(const float4*)(A + (size_t)r * lda + k0 + cq * 4);
                As[cq * 4 + 0][r] = v.x;
                As[cq * 4 + 1][r] = v.y;
                As[cq * 4 + 2][r] = v.z;
                As[cq * 4 + 3][r] = v.w;
            }
            if (tid < 64) {  // B tile 16x16
                int r  = tid >> 2;
                int cq = tid & 3;
                *(float4*)&Bs[r][cq * 4] =
                    *(const float4*)(B + (size_t)(k0 + r) * ldb + bn + cq * 4);
            }
            __syncthreads();
#pragma unroll
            for (int kk = 0; kk < BK; kk++) {
                float w  = Bs[kk][tx];
                float4 a = *(const float4*)&As[kk][ty * 4];
                acc[0] = fmaf(a.x, w, acc[0]);
                acc[1] = fmaf(a.y, w, acc[1]);
                acc[2] = fmaf(a.z, w, acc[2]);
                acc[3] = fmaf(a.w, w, acc[3]);
            }
            __syncthreads();
        }
    }
#pragma unroll
    for (int i = 0; i < 4; i++) {
        int bb = ty * 4 + i;
        int n  = bn + tx;
        float v = acc[i];
        if (addend) v += addend[(size_t)bb * ldadd + n];
        C[(size_t)bb * ldc + n] = v;
    }
}

// ---------------------------------------------------------------------------
__global__ void lstm_kernel(const float* __restrict__ z,
                            const float* __restrict__ c_in,
                            float* __restrict__ h_out,
                            float* __restrict__ c_out)
{
    int b = blockIdx.x;
    int k = threadIdx.x;   // 512
    const float* zr = z + (size_t)b * (4 * UNITS);
    float zi = zr[k];
    float zf = zr[UNITS + k];
    float zg = zr[2 * UNITS + k];
    float zo = zr[3 * UNITS + k];
    float si = 1.f / (1.f + expf(-zi));
    float sf = 1.f / (1.f + expf(-zf));
    float so = 1.f / (1.f + expf(-zo));
    float tg = tanhf(zg);
    float cn = sf * c_in[(size_t)b * UNITS + k] + si * tg;
    float hn = so * tanhf(cn);
    c_out[(size_t)b * UNITS + k] = cn;
    h_out[(size_t)b * UNITS + k] = hn;
}

// ---------------------------------------------------------------------------
// Bahdanau attention, one block per batch row. q precomputed.
// score[t] = sum_u tanh(keys[b][t][u] + q[b][u]) * v[u]; softmax; ctx = align@memory.
__global__ void attention_kernel(const float* __restrict__ q,
                                 const float* __restrict__ keys,
                                 const float* __restrict__ memory,
                                 const float* __restrict__ v_att,
                                 float* __restrict__ context)
{
    int b = blockIdx.x;
    __shared__ float sq[UNITS];
    __shared__ float sscore[64];
    int tid  = threadIdx.x;       // 256
    int warp = tid >> 5;
    int lane = tid & 31;

    for (int u = tid; u < UNITS; u += 256) sq[u] = q[(size_t)b * UNITS + u];
    __syncthreads();

    for (int t = warp; t < TIN; t += 8) {
        const float* krow = keys + ((size_t)b * TIN + t) * UNITS;
        float s = 0.f;
        for (int u = lane; u < UNITS; u += 32)
            s += tanhf(krow[u] + sq[u]) * v_att[u];
#pragma unroll
        for (int off = 16; off; off >>= 1)
            s += __shfl_xor_sync(0xffffffffu, s, off);
        if (lane == 0) sscore[t] = s;
    }
    __syncthreads();

    if (tid < 32) {
        float m = -1e30f;
        for (int t = lane; t < TIN; t += 32) m = fmaxf(m, sscore[t]);
#pragma unroll
        for (int off = 16; off; off >>= 1)
            m = fmaxf(m, __shfl_xor_sync(0xffffffffu, m, off));
        float ssum = 0.f;
        for (int t = lane; t < TIN; t += 32) {
            float e = expf(sscore[t] - m);
            sscore[t] = e;
            ssum += e;
        }
#pragma unroll
        for (int off = 16; off; off >>= 1)
            ssum += __shfl_xor_sync(0xffffffffu, ssum, off);
        float inv = 1.f / ssum;
        for (int t = lane; t < TIN; t += 32) sscore[t] *= inv;
    }
    __syncthreads();

    const float* mrow = memory + (size_t)b * TIN * UNITS;
    for (int d = tid; d < UNITS; d += 256) {
        float acc = 0.f;
#pragma unroll 4
        for (int t = 0; t < TIN; t++)
            acc = fmaf(sscore[t], mrow[(size_t)t * UNITS + d], acc);
        context[(size_t)b * UNITS + d] = acc;
    }
}

// ---------------------------------------------------------------------------
static inline float* sym_addr(const void* sym) {
    void* p = nullptr;
    cudaGetSymbolAddress(&p, sym);
    return (float*)p;
}

#define DIVUP(a, b) (((a) + (b) - 1) / (b))

extern "C" void kernel_launch(void* const* d_in, const int* in_sizes, int n_in,
                              void* d_out, int out_size)
{
    const int*   dec  = (const int*)  d_in[0];
    const float* h0   = (const float*)d_in[1];
    const float* c0   = (const float*)d_in[2];
    const float* mem  = (const float*)d_in[3];
    const float* emb  = (const float*)d_in[4];
    const float* Wk   = (const float*)d_in[5];   // [812, 2048]
    const float* Uk   = (const float*)d_in[6];   // [512, 2048]
    const float* bk   = (const float*)d_in[7];
    const float* Wm   = (const float*)d_in[8];   // [512, 512]
    const float* Wq   = (const float*)d_in[9];   // [512, 512]
    const float* vat  = (const float*)d_in[10];  // [512]
    const float* Wa   = (const float*)d_in[11];  // [1024, 512]
    const float* Wfc  = (const float*)d_in[12];  // [512, 34004]
    const float* bfc  = (const float*)d_in[13];  // [34004]
    float* out = (float*)d_out;

    float* keys   = sym_addr(g_keys);
    float* embA   = sym_addr(g_embA);
    float* zpre   = sym_addr(g_zpre);
    float* z      = sym_addr(g_z);
    float* hbuf   = sym_addr(g_hbuf);   // [2][64*512]
    float* cbuf   = sym_addr(g_cbuf);
    float* q      = sym_addr(g_q);
    float* ctx    = sym_addr(g_ctx);
    float* attn0  = sym_addr(g_attn0);
    float* states = sym_addr(g_states);

    // ---- setup (parallel work) ----
    zero_kernel<<<32, 1024>>>(attn0, B64 * UNITS);
    gather_emb_kernel<<<ROWS, 128>>>(dec, emb, embA);
    // zpre[r, 0:2048] = embA[r] @ Wk[0:300] + bk     (r = t*64+b)
    sgemm_kernel<128, 64, 16, 8, 4><<<dim3(DIVUP(4 * UNITS, 64), DIVUP(ROWS, 128)), 256>>>(
        embA, EMB, Wk, 4 * UNITS, bk, zpre, 4 * UNITS, ROWS, 4 * UNITS, EMB);
    // keys = memory @ Wm   ([3840,512] = [3840,512] @ [512,512])
    sgemm_kernel<128, 64, 16, 8, 4><<<dim3(UNITS / 64, (B64 * TIN) / 128), 256>>>(
        mem, UNITS, Wm, UNITS, nullptr, keys, UNITS, B64 * TIN, UNITS, UNITS);

    // ---- sequential recurrence ----
    for (int t = 0; t < TOUT; t++) {
        const float* attn_prev = t ? (states + (size_t)(t - 1) * UNITS) : attn0;
        const int lda_attn     = t ? (TOUT * UNITS) : UNITS;
        const float* hp = t ? (hbuf + (size_t)((t - 1) & 1) * B64 * UNITS) : h0;
        const float* cp = t ? (cbuf + (size_t)((t - 1) & 1) * B64 * UNITS) : c0;
        float* hn = hbuf + (size_t)(t & 1) * B64 * UNITS;
        float* cn = cbuf + (size_t)(t & 1) * B64 * UNITS;

        // z = zpre[t] + attn_prev @ Wk[300:812] + h @ Uk
        dual_gemm_kernel<<<(4 * UNITS) / 16, 256>>>(
            attn_prev, lda_attn, Wk + (size_t)EMB * 4 * UNITS, 4 * UNITS,
            hp, UNITS, Uk,
            zpre + (size_t)t * B64 * 4 * UNITS, 4 * UNITS,
            z, 4 * UNITS);

        lstm_kernel<<<B64, UNITS>>>(z, cp, hn, cn);

        // q = h_new @ Wq
        sgemm_kernel<64, 16, 16, 4, 1><<<dim3(UNITS / 16, 1), 256>>>(
            hn, UNITS, Wq, UNITS, nullptr, q, UNITS, B64, UNITS, UNITS);

        attention_kernel<<<B64, 256>>>(q, keys, mem, vat, ctx);

        // states[b][t][:] = [h_new | ctx] @ Wa
        dual_gemm_kernel<<<UNITS / 16, 256>>>(
            hn, UNITS, Wa, UNITS,
            ctx, UNITS, Wa + (size_t)UNITS * UNITS,
            nullptr, 0,
            states + (size_t)t * UNITS, TOUT * UNITS);
    }

    // ---- final vocab projection: out[b][t][:] = states[b*31+t] @ Wfc + bfc ----
    sgemm_kernel<128, 64, 16, 8, 4><<<dim3(DIVUP(VOCAB, 64), DIVUP(ROWS, 128)), 256>>>(
        states, UNITS, Wfc, VOCAB, bfc, out, VOCAB, ROWS, VOCAB, UNITS);
}

// round 4
// speedup vs baseline: 1.1930x; 1.1930x over previous
#include <cuda_runtime.h>
#include <cuda.h>
#include <cuda_bf16.h>
#include <math.h>
#include <stdint.h>

// ============================================================================
// Attention-LSTM decoder. B=64, T_out=31, T_in=60, U=512, EMB=300, VOCAB=34004.
//   setup:  gather emb; zpre = embAll@Wk[0:300]+bk; keys = memory@Wm  (fp32)
//   step t: fused dual-GEMM gates + LSTM epilogue -> h,c ; q = h@Wq ;
//           fused attention ; states_t = [h|ctx]@Wa
//   final:  split-bf16 mma.sync GEMM: out = states @ Wfc + bfc
// (tcgen05 is unavailable: harness ptxas target rejects sm_100a features.)
// ============================================================================

#define B64   64
#define TOUT  31
#define TIN   60
#define UNITS 512
#define EMB   300
#define VOCAB 34004
#define ROWS  (B64 * TOUT)     // 1984
#define MPAD  2048             // 16 * 128
#define VPAD  34048            // 266 * 128

// ---------------- scratch ----------------------------------------------------
__device__ float g_keys  [B64 * TIN * UNITS];
__device__ float g_embA  [ROWS * EMB];
__device__ float g_zpre  [ROWS * 4 * UNITS];
__device__ float g_hbuf  [2][B64 * UNITS];
__device__ float g_cbuf  [2][B64 * UNITS];
__device__ float g_q     [B64 * UNITS];
__device__ float g_ctx   [B64 * UNITS];
__device__ float g_states[ROWS * UNITS];           // row = b*31 + t
__device__ __nv_bfloat16 g_sA_hi[MPAD * UNITS];
__device__ __nv_bfloat16 g_sA_lo[MPAD * UNITS];
__device__ __nv_bfloat16 g_wT_hi[(size_t)VPAD * UNITS];   // [n][k]
__device__ __nv_bfloat16 g_wT_lo[(size_t)VPAD * UNITS];

// ---------------------------------------------------------------------------
__device__ __forceinline__ uint32_t smem_u32(const void* p) {
    uint32_t a;
    asm("{ .reg .u64 t; cvta.to.shared.u64 t, %1; cvt.u32.u64 %0, t; }" : "=r"(a) : "l"(p));
    return a;
}
__device__ __forceinline__ void ldm_x4(uint32_t& r0, uint32_t& r1, uint32_t& r2,
                                       uint32_t& r3, uint32_t addr) {
    asm volatile("ldmatrix.sync.aligned.m8n8.x4.shared.b16 {%0,%1,%2,%3}, [%4];"
                 : "=r"(r0), "=r"(r1), "=r"(r2), "=r"(r3) : "r"(addr));
}
__device__ __forceinline__ void mma_bf16(float* c, const uint32_t* a, const uint32_t* b) {
    asm volatile("mma.sync.aligned.m16n8k16.row.col.f32.bf16.bf16.f32 "
                 "{%0,%1,%2,%3}, {%4,%5,%6,%7}, {%8,%9}, {%0,%1,%2,%3};"
                 : "+f"(c[0]), "+f"(c[1]), "+f"(c[2]), "+f"(c[3])
                 : "r"(a[0]), "r"(a[1]), "r"(a[2]), "r"(a[3]), "r"(b[0]), "r"(b[1]));
}

// ---------------------------------------------------------------------------
__global__ void gather_emb_kernel(const int* __restrict__ dec,
                                  const float* __restrict__ emb,
                                  float* __restrict__ out) {
    int r = blockIdx.x;          // r = t*64 + b
    int t = r >> 6, b = r & 63;
    int tok = dec[b * TOUT + t];
    const float* src = emb + (size_t)tok * EMB;
    float* dst = out + (size_t)r * EMB;
    for (int e = threadIdx.x; e < EMB; e += blockDim.x) dst[e] = src[e];
}

// ---------------------------------------------------------------------------
// fp32 SGEMM 128x128x16, 8x8/thread, 256 threads (setup GEMMs only).
__global__ void sgemm128_kernel(const float* __restrict__ A, int lda,
                                const float* __restrict__ B, int ldb,
                                const float* __restrict__ bias,
                                float* __restrict__ C, int ldc,
                                int M, int N, int K)
{
    __shared__ __align__(16) float As[16][128];
    __shared__ __align__(16) float Bs[16][128];
    const int bm = blockIdx.y * 128, bn = blockIdx.x * 128;
    const int tid = threadIdx.x;
    const int tx = tid & 15, ty = tid >> 4;

    float acc[8][8];
#pragma unroll
    for (int i = 0; i < 8; i++)
#pragma unroll
        for (int j = 0; j < 8; j++) acc[i][j] = 0.f;

    for (int k0 = 0; k0 < K; k0 += 16) {
#pragma unroll
        for (int l = 0; l < 2; l++) {
            int q = tid + l * 256;
            int r = q >> 2, kq = (q & 3) * 4;
            int gm = bm + r, gk = k0 + kq;
            float4 v = make_float4(0.f, 0.f, 0.f, 0.f);
            if (gm < M) {
                if (gk + 3 < K) v = *(const float4*)(A + (size_t)gm * lda + gk);
                else {
                    if (gk + 0 < K) v.x = A[(size_t)gm * lda + gk + 0];
                    if (gk + 1 < K) v.y = A[(size_t)gm * lda + gk + 1];
                    if (gk + 2 < K) v.z = A[(size_t)gm * lda + gk + 2];
                }
            }
            As[kq + 0][r] = v.x; As[kq + 1][r] = v.y;
            As[kq + 2][r] = v.z; As[kq + 3][r] = v.w;
        }
#pragma unroll
        for (int l = 0; l < 2; l++) {
            int q = tid + l * 256;
            int r = q >> 5, cq = (q & 31) * 4;
            int gk = k0 + r, gn = bn + cq;
            float4 v = make_float4(0.f, 0.f, 0.f, 0.f);
            if (gk < K) {
                if (gn + 3 < N) v = *(const float4*)(B + (size_t)gk * ldb + gn);
                else {
                    if (gn + 0 < N) v.x = B[(size_t)gk * ldb + gn + 0];
                    if (gn + 1 < N) v.y = B[(size_t)gk * ldb + gn + 1];
                    if (gn + 2 < N) v.z = B[(size_t)gk * ldb + gn + 2];
                }
            }
            *(float4*)&Bs[r][cq] = v;
        }
        __syncthreads();
#pragma unroll
        for (int kk = 0; kk < 16; kk++) {
            float a[8], b[8];
            *(float4*)&a[0] = *(const float4*)&As[kk][ty * 8];
            *(float4*)&a[4] = *(const float4*)&As[kk][ty * 8 + 4];
            *(float4*)&b[0] = *(const float4*)&Bs[kk][tx * 8];
            *(float4*)&b[4] = *(const float4*)&Bs[kk][tx * 8 + 4];
#pragma unroll
            for (int i = 0; i < 8; i++)
#pragma unroll
                for (int j = 0; j < 8; j++)
                    acc[i][j] = fmaf(a[i], b[j], acc[i][j]);
        }
        __syncthreads();
    }
#pragma unroll
    for (int i = 0; i < 8; i++) {
        int gm = bm + ty * 8 + i;
        if (gm >= M) continue;
#pragma unroll
        for (int j = 0; j < 8; j++) {
            int gn = bn + tx * 8 + j;
            if (gn < N)
                C[(size_t)gm * ldc + gn] = acc[i][j] + (bias ? bias[gn] : 0.f);
        }
    }
}

// ---------------------------------------------------------------------------
// Step GEMM: 16 batches x 64 cols per block, K split into (A1,B1:K1)+(A2,B2:K2).
template<bool GATED>
__global__ void step_gemm_kernel(const float* __restrict__ A1, int lda1,
                                 const float* __restrict__ B1, int ldb1, int K1,
                                 const float* __restrict__ A2, int lda2,
                                 const float* __restrict__ B2, int ldb2, int K2,
                                 const float* __restrict__ addend, int ldadd,
                                 const float* __restrict__ c_in,
                                 float* __restrict__ Cout, int ldc,
                                 float* __restrict__ c_out)
{
    constexpr int BK = 32;
    __shared__ __align__(16) float As[BK][16];
    __shared__ __align__(16) float Bs[BK][64];
    const int u0  = GATED ? blockIdx.x * 16 : blockIdx.x * 64;
    const int b0  = blockIdx.y * 16;
    const int tid = threadIdx.x;
    const int tx  = tid & 15, ty = tid >> 4;
    float acc[4] = {0.f, 0.f, 0.f, 0.f};

    const int Ktot = K1 + K2;
    for (int k0 = 0; k0 < Ktot; k0 += BK) {
        const float* A; int lda; const float* Bsrc; int ldb; int kl;
        if (k0 < K1) { A = A1; lda = lda1; Bsrc = B1; ldb = ldb1; kl = k0; }
        else         { A = A2; lda = lda2; Bsrc = B2; ldb = ldb2; kl = k0 - K1; }
#pragma unroll
        for (int l = 0; l < 2; l++) {
            int e = tid + l * 256;
            int r = e >> 5, k = e & 31;
            As[k][r] = A ? A[(size_t)(b0 + r) * lda + kl + k] : 0.f;
        }
#pragma unroll
        for (int l = 0; l < 8; l++) {
            int e = tid + l * 256;
            int k = e >> 6, c = e & 63;
            int col = GATED ? ((c & 3) * UNITS + u0 + (c >> 2)) : (u0 + c);
            Bs[k][c] = Bsrc[(size_t)(kl + k) * ldb + col];
        }
        __syncthreads();
#pragma unroll
        for (int kk = 0; kk < BK; kk++) {
            float a  = As[kk][ty];
            float4 b = *(const float4*)&Bs[kk][tx * 4];
            acc[0] = fmaf(a, b.x, acc[0]);
            acc[1] = fmaf(a, b.y, acc[1]);
            acc[2] = fmaf(a, b.z, acc[2]);
            acc[3] = fmaf(a, b.w, acc[3]);
        }
        __syncthreads();
    }

    const int b = b0 + ty;
    if (GATED) {
        const int u = u0 + tx;
        const float* ad = addend + (size_t)b * ldadd;
        float zi = acc[0] + ad[u];
        float zf = acc[1] + ad[UNITS + u];
        float zg = acc[2] + ad[2 * UNITS + u];
        float zo = acc[3] + ad[3 * UNITS + u];
        float si = 1.f / (1.f + expf(-zi));
        float sf = 1.f / (1.f + expf(-zf));
        float so = 1.f / (1.f + expf(-zo));
        float tg = tanhf(zg);
        float cn = sf * c_in[(size_t)b * UNITS + u] + si * tg;
        float hn = so * tanhf(cn);
        c_out[(size_t)b * UNITS + u] = cn;
        Cout [(size_t)b * ldc   + u] = hn;
    } else {
#pragma unroll
        for (int j = 0; j < 4; j++)
            Cout[(size_t)b * ldc + u0 + tx * 4 + j] = acc[j];
    }
}

// ---------------------------------------------------------------------------
__global__ void attention_kernel(const float* __restrict__ q,
                                 const float* __restrict__ keys,
                                 const float* __restrict__ memory,
                                 const float* __restrict__ v_att,
                                 float* __restrict__ context)
{
    int b = blockIdx.x;
    __shared__ float sq[UNITS];
    __shared__ float sscore[64];
    int tid = threadIdx.x, warp = tid >> 5, lane = tid & 31;

    for (int u = tid; u < UNITS; u += 256) sq[u] = q[(size_t)b * UNITS + u];
    __syncthreads();

    for (int t = warp; t < TIN; t += 8) {
        const float* krow = keys + ((size_t)b * TIN + t) * UNITS;
        float s = 0.f;
        for (int u = lane; u < UNITS; u += 32)
            s += tanhf(krow[u] + sq[u]) * v_att[u];
#pragma unroll
        for (int off = 16; off; off >>= 1) s += __shfl_xor_sync(~0u, s, off);
        if (lane == 0) sscore[t] = s;
    }
    __syncthreads();

    if (tid < 32) {
        float m = -1e30f;
        for (int t = lane; t < TIN; t += 32) m = fmaxf(m, sscore[t]);
#pragma unroll
        for (int off = 16; off; off >>= 1) m = fmaxf(m, __shfl_xor_sync(~0u, m, off));
        float ssum = 0.f;
        for (int t = lane; t < TIN; t += 32) {
            float e = expf(sscore[t] - m);
            sscore[t] = e; ssum += e;
        }
#pragma unroll
        for (int off = 16; off; off >>= 1) ssum += __shfl_xor_sync(~0u, ssum, off);
        float inv = 1.f / ssum;
        for (int t = lane; t < TIN; t += 32) sscore[t] *= inv;
    }
    __syncthreads();

    const float* mrow = memory + (size_t)b * TIN * UNITS;
    for (int d = tid; d < UNITS; d += 256) {
        float acc = 0.f;
#pragma unroll 4
        for (int t = 0; t < TIN; t++)
            acc = fmaf(sscore[t], mrow[(size_t)t * UNITS + d], acc);
        context[(size_t)b * UNITS + d] = acc;
    }
}

// ---------------------------------------------------------------------------
__global__ void convert_states_kernel(const float* __restrict__ s,
                                      __nv_bfloat16* __restrict__ hi,
                                      __nv_bfloat16* __restrict__ lo) {
    int i = blockIdx.x * 256 + threadIdx.x;
    float v = (i < ROWS * UNITS) ? s[i] : 0.f;
    __nv_bfloat16 h = __float2bfloat16(v);
    hi[i] = h;
    lo[i] = __float2bfloat16(v - __bfloat162float(h));
}

__global__ void convert_wfc_kernel(const float* __restrict__ W,
                                   __nv_bfloat16* __restrict__ hiT,
                                   __nv_bfloat16* __restrict__ loT) {
    __shared__ float tile[32][33];
    int n0 = blockIdx.x * 32, k0 = blockIdx.y * 32;
    int txx = threadIdx.x & 31, tyy = threadIdx.x >> 5;   // 32 x 8
    for (int j = tyy; j < 32; j += 8) {
        int n = n0 + txx;
        tile[j][txx] = (n < VOCAB) ? W[(size_t)(k0 + j) * VOCAB + n] : 0.f;
    }
    __syncthreads();
    for (int j = tyy; j < 32; j += 8) {
        int n = n0 + j, k = k0 + txx;
        float v = tile[txx][j];
        __nv_bfloat16 h = __float2bfloat16(v);
        hiT[(size_t)n * UNITS + k] = h;
        loT[(size_t)n * UNITS + k] = __float2bfloat16(v - __bfloat162float(h));
    }
}

// ---------------------------------------------------------------------------
// Split-bf16 mma.sync GEMM: out[1984,34004] = states @ WfcT^T + bias.
// CTA tile 128x128, BK=32, 8 warps of 64x32, 3 accumulation terms.
// Smem row stride 40 bf16 (80B) -> conflict-free ldmatrix.
#define TSTRIDE 40
__global__ void __launch_bounds__(256)
gemm_mma_kernel(const __nv_bfloat16* __restrict__ Ah,
                const __nv_bfloat16* __restrict__ Al,
                const __nv_bfloat16* __restrict__ Bh,
                const __nv_bfloat16* __restrict__ Bl,
                const float* __restrict__ bias,
                float* __restrict__ out)
{
    __shared__ __align__(16) __nv_bfloat16 sm[4][128 * TSTRIDE];
    const int m0 = blockIdx.x * 128;     // m fastest -> B tiles L2-shared
    const int n0 = blockIdx.y * 128;
    const int tid  = threadIdx.x;
    const int wid  = tid >> 5, lane = tid & 31;
    const int wm   = wid & 1,  wn   = wid >> 1;
    const int mbase = wm * 64, nbase = wn * 32;

    const uint32_t sb[4] = { smem_u32(sm[0]), smem_u32(sm[1]),
                             smem_u32(sm[2]), smem_u32(sm[3]) };

    float acc[16][4];
#pragma unroll
    for (int i = 0; i < 16; i++)
#pragma unroll
        for (int j = 0; j < 4; j++) acc[i][j] = 0.f;

    for (int kc = 0; kc < UNITS / 32; kc++) {
        // ---- load 4 tiles (128 rows x 32 bf16 each) ----
#pragma unroll
        for (int arr = 0; arr < 4; arr++) {
            const __nv_bfloat16* src = (arr == 0) ? Ah : (arr == 1) ? Al
                                     : (arr == 2) ? Bh : Bl;
            const int rbase = (arr < 2) ? m0 : n0;
#pragma unroll
            for (int l = 0; l < 2; l++) {
                int q = tid + l * 256;        // 512 uint4
                int r = q >> 2, c8 = (q & 3) * 8;
                uint4 v = *(const uint4*)(src + ((size_t)(rbase + r) * UNITS + kc * 32 + c8));
                *(uint4*)(&sm[arr][r * TSTRIDE + c8]) = v;
            }
        }
        __syncthreads();

        // ---- compute: two k16 steps ----
#pragma unroll
        for (int ks = 0; ks < 2; ks++) {
            const uint32_t a_off =
                (uint32_t)(((mbase + (lane & 15)) * TSTRIDE + ks * 16 + (lane >> 4) * 8) * 2);
            uint32_t aH[4][4], aL[4][4];
#pragma unroll
            for (int i = 0; i < 4; i++) {
                uint32_t off = a_off + (uint32_t)(i * 16 * TSTRIDE * 2);
                ldm_x4(aH[i][0], aH[i][1], aH[i][2], aH[i][3], sb[0] + off);
                ldm_x4(aL[i][0], aL[i][1], aL[i][2], aL[i][3], sb[1] + off);
            }
            const uint32_t b_off =
                (uint32_t)(((nbase + (lane & 7) + ((lane >> 4) * 8)) * TSTRIDE
                            + ks * 16 + ((lane >> 3) & 1) * 8) * 2);
            uint32_t bH[4][2], bL[4][2];
#pragma unroll
            for (int jp = 0; jp < 2; jp++) {
                uint32_t off = b_off + (uint32_t)(jp * 16 * TSTRIDE * 2);
                ldm_x4(bH[jp * 2][0], bH[jp * 2][1], bH[jp * 2 + 1][0], bH[jp * 2 + 1][1],
                       sb[2] + off);
                ldm_x4(bL[jp * 2][0], bL[jp * 2][1], bL[jp * 2 + 1][0], bL[jp * 2 + 1][1],
                       sb[3] + off);
            }
#pragma unroll
            for (int i = 0; i < 4; i++)
#pragma unroll
                for (int j = 0; j < 4; j++) {
                    mma_bf16(acc[i * 4 + j], aH[i], bH[j]);
                    mma_bf16(acc[i * 4 + j], aH[i], bL[j]);
                    mma_bf16(acc[i * 4 + j], aL[i], bH[j]);
                }
        }
        __syncthreads();
    }

    // ---- epilogue: fragment -> gmem with bias ----
#pragma unroll
    for (int i = 0; i < 4; i++) {
        int row0 = m0 + mbase + i * 16 + (lane >> 2);
#pragma unroll
        for (int j = 0; j < 4; j++) {
            int col = n0 + nbase + j * 8 + (lane & 3) * 2;
            if (col >= VOCAB) continue;
            float b0 = bias[col], b1 = bias[col + 1];
            const float* c = acc[i * 4 + j];
            if (row0 < ROWS) {
                out[(size_t)row0 * VOCAB + col]     = c[0] + b0;
                out[(size_t)row0 * VOCAB + col + 1] = c[1] + b1;
            }
            if (row0 + 8 < ROWS) {
                out[(size_t)(row0 + 8) * VOCAB + col]     = c[2] + b0;
                out[(size_t)(row0 + 8) * VOCAB + col + 1] = c[3] + b1;
            }
        }
    }
}

// ---------------------------------------------------------------------------
static inline float* sym_addr(const void* sym) {
    void* p = nullptr;
    cudaGetSymbolAddress(&p, sym);
    return (float*)p;
}
static inline __nv_bfloat16* sym_addr_bf(const void* sym) {
    void* p = nullptr;
    cudaGetSymbolAddress(&p, sym);
    return (__nv_bfloat16*)p;
}
#define DIVUP(a, b) (((a) + (b) - 1) / (b))

extern "C" void kernel_launch(void* const* d_in, const int* in_sizes, int n_in,
                              void* d_out, int out_size)
{
    const int*   dec = (const int*)  d_in[0];
    const float* h0  = (const float*)d_in[1];
    const float* c0  = (const float*)d_in[2];
    const float* mem = (const float*)d_in[3];
    const float* emb = (const float*)d_in[4];
    const float* Wk  = (const float*)d_in[5];
    const float* Uk  = (const float*)d_in[6];
    const float* bk  = (const float*)d_in[7];
    const float* Wm  = (const float*)d_in[8];
    const float* Wq  = (const float*)d_in[9];
    const float* vat = (const float*)d_in[10];
    const float* Wa  = (const float*)d_in[11];
    const float* Wfc = (const float*)d_in[12];
    const float* bfc = (const float*)d_in[13];
    float* out = (float*)d_out;

    float* keys   = sym_addr(g_keys);
    float* embA   = sym_addr(g_embA);
    float* zpre   = sym_addr(g_zpre);
    float* hbuf   = sym_addr(g_hbuf);
    float* cbuf   = sym_addr(g_cbuf);
    float* q      = sym_addr(g_q);
    float* ctx    = sym_addr(g_ctx);
    float* states = sym_addr(g_states);
    __nv_bfloat16* sA_hi = sym_addr_bf(g_sA_hi);
    __nv_bfloat16* sA_lo = sym_addr_bf(g_sA_lo);
    __nv_bfloat16* wT_hi = sym_addr_bf(g_wT_hi);
    __nv_bfloat16* wT_lo = sym_addr_bf(g_wT_lo);

    // ---- setup ----
    gather_emb_kernel<<<ROWS, 128>>>(dec, emb, embA);
    sgemm128_kernel<<<dim3(DIVUP(4 * UNITS, 128), DIVUP(ROWS, 128)), 256>>>(
        embA, EMB, Wk, 4 * UNITS, bk, zpre, 4 * UNITS, ROWS, 4 * UNITS, EMB);
    sgemm128_kernel<<<dim3(DIVUP(UNITS, 128), DIVUP(B64 * TIN, 128)), 256>>>(
        mem, UNITS, Wm, UNITS, nullptr, keys, UNITS, B64 * TIN, UNITS, UNITS);
    convert_wfc_kernel<<<dim3(VPAD / 32, UNITS / 32), 256>>>(Wfc, wT_hi, wT_lo);

    // ---- recurrence ----
    for (int t = 0; t < TOUT; t++) {
        const float* attn_prev = t ? (states + (size_t)(t - 1) * UNITS) : nullptr;
        const int lda_attn     = TOUT * UNITS;
        const float* hp = t ? (hbuf + (size_t)((t - 1) & 1) * B64 * UNITS) : h0;
        const float* cp = t ? (cbuf + (size_t)((t - 1) & 1) * B64 * UNITS) : c0;
        float* hn = hbuf + (size_t)(t & 1) * B64 * UNITS;
        float* cn = cbuf + (size_t)(t & 1) * B64 * UNITS;

        step_gemm_kernel<true><<<dim3(32, 4), 256>>>(
            attn_prev, lda_attn, Wk + (size_t)EMB * 4 * UNITS, 4 * UNITS, UNITS,
            hp, UNITS, Uk, 4 * UNITS, UNITS,
            zpre + (size_t)t * B64 * 4 * UNITS, 4 * UNITS,
            cp, hn, UNITS, cn);

        step_gemm_kernel<false><<<dim3(8, 4), 256>>>(
            hn, UNITS, Wq, UNITS, UNITS,
            nullptr, 0, nullptr, 0, 0,
            nullptr, 0, nullptr, q, UNITS, nullptr);

        attention_kernel<<<B64, 256>>>(q, keys, mem, vat, ctx);

        step_gemm_kernel<false><<<dim3(8, 4), 256>>>(
            hn, UNITS, Wa, UNITS, UNITS,
            ctx, UNITS, Wa + (size_t)UNITS * UNITS, UNITS, UNITS,
            nullptr, 0, nullptr, states + (size_t)t * UNITS, TOUT * UNITS, nullptr);
    }

    // ---- final vocab projection on tensor cores (mma.sync) ----
    convert_states_kernel<<<MPAD * UNITS / 256, 256>>>(states, sA_hi, sA_lo);
    gemm_mma_kernel<<<dim3(MPAD / 128, VPAD / 128), 256>>>(
        sA_hi, sA_lo, wT_hi, wT_lo, bfc, out);
}

// round 5
// speedup vs baseline: 1.2459x; 1.0443x over previous
#include <cuda_runtime.h>
#include <cuda.h>
#include <cuda_bf16.h>
#include <math.h>
#include <stdint.h>

// ============================================================================
// Attention-LSTM decoder. B=64, T_out=31, T_in=60, U=512, EMB=300, VOCAB=34004.
//   setup:  gather emb; zpre = embAll@Wk[0:300]+bk; keys = memory@Wm;
//           convert Wfc -> split-bf16 [n][k]; convert [Wk';Uk] -> split-bf16
//           gate-interleaved [n'][k]; transpose Wq.
//   step t: (1) gates: split-bf16 mma + fused LSTM epilogue -> h,c
//           (2) attention (q = h@WqT fused) -> ctx
//           (3) states_t = [h|ctx]@Wa (fp32 step GEMM)
//   final:  convert states -> split-bf16 ; pipelined split-bf16 mma GEMM:
//           out = states @ Wfc + bfc
// ============================================================================

#define B64   64
#define TOUT  31
#define TIN   60
#define UNITS 512
#define EMB   300
#define VOCAB 34004
#define ROWS  (B64 * TOUT)     // 1984
#define MPAD  2048
#define VPAD  34048            // 266 * 128
#define SLD   (TOUT * UNITS)   // states row stride = 15872

// ---------------- scratch ----------------------------------------------------
__device__ float g_keys  [B64 * TIN * UNITS];
__device__ float g_embA  [ROWS * EMB];
__device__ float g_zpre  [ROWS * 4 * UNITS];
__device__ float g_hbuf  [2][B64 * UNITS];
__device__ float g_cbuf  [2][B64 * UNITS];
__device__ float g_ctx   [B64 * UNITS];
__device__ float g_states[ROWS * UNITS];                      // row = b*31 + t
__device__ float g_wqT   [UNITS * UNITS];                     // [n][k]
__device__ __align__(16) __nv_bfloat16 g_sA_hi[MPAD * UNITS];
__device__ __align__(16) __nv_bfloat16 g_sA_lo[MPAD * UNITS];
__device__ __align__(16) __nv_bfloat16 g_wT_hi[(size_t)VPAD * UNITS];   // [n][k]
__device__ __align__(16) __nv_bfloat16 g_wT_lo[(size_t)VPAD * UNITS];
__device__ __align__(16) __nv_bfloat16 g_wkuH[2048 * 1024];   // [n'=u*4+g][k]
__device__ __align__(16) __nv_bfloat16 g_wkuL[2048 * 1024];

// ---------------- PTX helpers -------------------------------------------------
__device__ __forceinline__ uint32_t smem_u32(const void* p) {
    uint32_t a;
    asm("{ .reg .u64 t; cvta.to.shared.u64 t, %1; cvt.u32.u64 %0, t; }" : "=r"(a) : "l"(p));
    return a;
}
__device__ __forceinline__ void ldm_x4(uint32_t& r0, uint32_t& r1, uint32_t& r2,
                                       uint32_t& r3, uint32_t addr) {
    asm volatile("ldmatrix.sync.aligned.m8n8.x4.shared.b16 {%0,%1,%2,%3}, [%4];"
                 : "=r"(r0), "=r"(r1), "=r"(r2), "=r"(r3) : "r"(addr));
}
__device__ __forceinline__ void mma_bf16(float* c, const uint32_t* a, const uint32_t* b) {
    asm volatile("mma.sync.aligned.m16n8k16.row.col.f32.bf16.bf16.f32 "
                 "{%0,%1,%2,%3}, {%4,%5,%6,%7}, {%8,%9}, {%0,%1,%2,%3};"
                 : "+f"(c[0]), "+f"(c[1]), "+f"(c[2]), "+f"(c[3])
                 : "r"(a[0]), "r"(a[1]), "r"(a[2]), "r"(a[3]), "r"(b[0]), "r"(b[1]));
}
__device__ __forceinline__ void cp_async16(uint32_t dst, const void* src) {
    asm volatile("cp.async.cg.shared.global [%0], [%1], 16;" :: "r"(dst), "l"(src));
}
__device__ __forceinline__ void cp_commit() { asm volatile("cp.async.commit_group;"); }
template<int N> __device__ __forceinline__ void cp_wait() {
    asm volatile("cp.async.wait_group %0;" :: "n"(N));
}
__device__ __forceinline__ uint32_t pack_bf2(float a, float b) {
    __nv_bfloat162 t = __floats2bfloat162_rn(a, b);
    return *reinterpret_cast<uint32_t*>(&t);
}
__device__ __forceinline__ float bf_res(float a) {   // residual a - bf16(a)
    return a - __bfloat162float(__float2bfloat16(a));
}

// ---------------------------------------------------------------------------
__global__ void gather_emb_kernel(const int* __restrict__ dec,
                                  const float* __restrict__ emb,
                                  float* __restrict__ out) {
    int r = blockIdx.x;          // r = t*64 + b
    int t = r >> 6, b = r & 63;
    int tok = dec[b * TOUT + t];
    const float* src = emb + (size_t)tok * EMB;
    float* dst = out + (size_t)r * EMB;
    for (int e = threadIdx.x; e < EMB; e += blockDim.x) dst[e] = src[e];
}

// ---------------------------------------------------------------------------
// fp32 SGEMM 128x128x16, 8x8/thread, 256 threads (setup GEMMs only).
__global__ void sgemm128_kernel(const float* __restrict__ A, int lda,
                                const float* __restrict__ B, int ldb,
                                const float* __restrict__ bias,
                                float* __restrict__ C, int ldc,
                                int M, int N, int K)
{
    __shared__ __align__(16) float As[16][128];
    __shared__ __align__(16) float Bs[16][128];
    const int bm = blockIdx.y * 128, bn = blockIdx.x * 128;
    const int tid = threadIdx.x;
    const int tx = tid & 15, ty = tid >> 4;

    float acc[8][8];
#pragma unroll
    for (int i = 0; i < 8; i++)
#pragma unroll
        for (int j = 0; j < 8; j++) acc[i][j] = 0.f;

    for (int k0 = 0; k0 < K; k0 += 16) {
#pragma unroll
        for (int l = 0; l < 2; l++) {
            int q = tid + l * 256;
            int r = q >> 2, kq = (q & 3) * 4;
            int gm = bm + r, gk = k0 + kq;
            float4 v = make_float4(0.f, 0.f, 0.f, 0.f);
            if (gm < M) {
                if (gk + 3 < K) v = *(const float4*)(A + (size_t)gm * lda + gk);
                else {
                    if (gk + 0 < K) v.x = A[(size_t)gm * lda + gk + 0];
                    if (gk + 1 < K) v.y = A[(size_t)gm * lda + gk + 1];
                    if (gk + 2 < K) v.z = A[(size_t)gm * lda + gk + 2];
                }
            }
            As[kq + 0][r] = v.x; As[kq + 1][r] = v.y;
            As[kq + 2][r] = v.z; As[kq + 3][r] = v.w;
        }
#pragma unroll
        for (int l = 0; l < 2; l++) {
            int q = tid + l * 256;
            int r = q >> 5, cq = (q & 31) * 4;
            int gk = k0 + r, gn = bn + cq;
            float4 v = make_float4(0.f, 0.f, 0.f, 0.f);
            if (gk < K) {
                if (gn + 3 < N) v = *(const float4*)(B + (size_t)gk * ldb + gn);
                else {
                    if (gn + 0 < N) v.x = B[(size_t)gk * ldb + gn + 0];
                    if (gn + 1 < N) v.y = B[(size_t)gk * ldb + gn + 1];
                    if (gn + 2 < N) v.z = B[(size_t)gk * ldb + gn + 2];
                }
            }
            *(float4*)&Bs[r][cq] = v;
        }
        __syncthreads();
#pragma unroll
        for (int kk = 0; kk < 16; kk++) {
            float a[8], b[8];
            *(float4*)&a[0] = *(const float4*)&As[kk][ty * 8];
            *(float4*)&a[4] = *(const float4*)&As[kk][ty * 8 + 4];
            *(float4*)&b[0] = *(const float4*)&Bs[kk][tx * 8];
            *(float4*)&b[4] = *(const float4*)&Bs[kk][tx * 8 + 4];
#pragma unroll
            for (int i = 0; i < 8; i++)
#pragma unroll
                for (int j = 0; j < 8; j++)
                    acc[i][j] = fmaf(a[i], b[j], acc[i][j]);
        }
        __syncthreads();
    }
#pragma unroll
    for (int i = 0; i < 8; i++) {
        int gm = bm + ty * 8 + i;
        if (gm >= M) continue;
#pragma unroll
        for (int j = 0; j < 8; j++) {
            int gn = bn + tx * 8 + j;
            if (gn < N)
                C[(size_t)gm * ldc + gn] = acc[i][j] + (bias ? bias[gn] : 0.f);
        }
    }
}

// ---------------------------------------------------------------------------
// fp32 step GEMM (Wa only): 16 batches x 64 cols per block, dual-K.
template<bool GATED>
__global__ void step_gemm_kernel(const float* __restrict__ A1, int lda1,
                                 const float* __restrict__ B1, int ldb1, int K1,
                                 const float* __restrict__ A2, int lda2,
                                 const float* __restrict__ B2, int ldb2, int K2,
                                 float* __restrict__ Cout, int ldc)
{
    constexpr int BK = 32;
    __shared__ __align__(16) float As[BK][16];
    __shared__ __align__(16) float Bs[BK][64];
    const int u0  = blockIdx.x * 64;
    const int b0  = blockIdx.y * 16;
    const int tid = threadIdx.x;
    const int tx  = tid & 15, ty = tid >> 4;
    float acc[4] = {0.f, 0.f, 0.f, 0.f};

    const int Ktot = K1 + K2;
    for (int k0 = 0; k0 < Ktot; k0 += BK) {
        const float* A; int lda; const float* Bsrc; int ldb; int kl;
        if (k0 < K1) { A = A1; lda = lda1; Bsrc = B1; ldb = ldb1; kl = k0; }
        else         { A = A2; lda = lda2; Bsrc = B2; ldb = ldb2; kl = k0 - K1; }
#pragma unroll
        for (int l = 0; l < 2; l++) {
            int e = tid + l * 256;
            int r = e >> 5, k = e & 31;
            As[k][r] = A[(size_t)(b0 + r) * lda + kl + k];
        }
#pragma unroll
        for (int l = 0; l < 8; l++) {
            int e = tid + l * 256;
            int k = e >> 6, c = e & 63;
            Bs[k][c] = Bsrc[(size_t)(kl + k) * ldb + u0 + c];
        }
        __syncthreads();
#pragma unroll
        for (int kk = 0; kk < BK; kk++) {
            float a  = As[kk][ty];
            float4 b = *(const float4*)&Bs[kk][tx * 4];
            acc[0] = fmaf(a, b.x, acc[0]);
            acc[1] = fmaf(a, b.y, acc[1]);
            acc[2] = fmaf(a, b.z, acc[2]);
            acc[3] = fmaf(a, b.w, acc[3]);
        }
        __syncthreads();
    }
    const int b = b0 + ty;
#pragma unroll
    for (int j = 0; j < 4; j++)
        Cout[(size_t)b * ldc + u0 + tx * 4 + j] = acc[j];
}

// ---------------------------------------------------------------------------
// Gates: split-bf16 mma, CTA tile 64m x 64n' (n' = u*4+g), BK=64, 2-stage
// cp.async for B; A ([attn|h] fp32) converted on the fly. Fused LSTM epilogue.
#define GTS     72
#define G_ARR   (64 * GTS * 2)          // 9216 B
#define G_STAGE (4 * G_ARR)             // 36864 B
#define G_SMEM  (2 * G_STAGE)           // 73728 B

__global__ void __launch_bounds__(128)
gates_mma_kernel(const float* __restrict__ attnp,   // may be null (t=0), ld=SLD
                 const float* __restrict__ hp,      // [64][512]
                 const float* __restrict__ cp,      // [64][512]
                 const __nv_bfloat16* __restrict__ wkuH,
                 const __nv_bfloat16* __restrict__ wkuL,
                 const float* __restrict__ zpre_t,  // [64][2048] original layout
                 float* __restrict__ hn, float* __restrict__ cn)
{
    extern __shared__ char dsm[];
    const int n0   = blockIdx.x * 64;       // n' base
    const int tid  = threadIdx.x;
    const int wid  = tid >> 5, lane = tid & 31;
    const int wm   = wid & 1,  wn = wid >> 1;
    const int mbase = wm * 32, nbase = wn * 32;
    const uint32_t sb = smem_u32(dsm);

    float acc[2][4][4];
#pragma unroll
    for (int i = 0; i < 2; i++)
#pragma unroll
        for (int j = 0; j < 4; j++)
#pragma unroll
            for (int e = 0; e < 4; e++) acc[i][j][e] = 0.f;

    // ---- helpers ----
    auto issueB = [&](int it, int stage) {
        int koff = it * 64;
#pragma unroll
        for (int arr = 0; arr < 2; arr++) {
            const __nv_bfloat16* src = arr ? wkuL : wkuH;
#pragma unroll
            for (int l = 0; l < 4; l++) {
                int q = tid + l * 128;               // 512 chunks
                int r = q >> 3, c8 = (q & 7) * 8;
                uint32_t dst = sb + stage * G_STAGE + (2 + arr) * G_ARR
                             + (uint32_t)(r * GTS + c8) * 2;
                cp_async16(dst, src + (size_t)(n0 + r) * 1024 + koff + c8);
            }
        }
        cp_commit();
    };
    float4 Areg[8];
    auto loadA = [&](int it) {
        int koff = it * 64;
#pragma unroll
        for (int l = 0; l < 8; l++) {
            int q = tid + l * 128;                   // 1024 float4
            int r = q >> 4, c4 = (q & 15) * 4;
            float4 v = make_float4(0.f, 0.f, 0.f, 0.f);
            if (koff < 512) {
                if (attnp) v = *(const float4*)(attnp + (size_t)r * SLD + koff + c4);
            } else {
                v = *(const float4*)(hp + (size_t)r * UNITS + (koff - 512) + c4);
            }
            Areg[l] = v;
        }
    };
    auto storeA = [&](int stage) {
#pragma unroll
        for (int l = 0; l < 8; l++) {
            int q = tid + l * 128;
            int r = q >> 4, c4 = (q & 15) * 4;
            float4 v = Areg[l];
            uint32_t off = (uint32_t)(r * GTS + c4) * 2;
            uint2 hi = make_uint2(pack_bf2(v.x, v.y), pack_bf2(v.z, v.w));
            uint2 lo = make_uint2(pack_bf2(bf_res(v.x), bf_res(v.y)),
                                  pack_bf2(bf_res(v.z), bf_res(v.w)));
            *(uint2*)(dsm + stage * G_STAGE + 0 * G_ARR + off) = hi;
            *(uint2*)(dsm + stage * G_STAGE + 1 * G_ARR + off) = lo;
        }
    };
    auto compute = [&](int stage) {
        uint32_t aHb = sb + stage * G_STAGE;
        uint32_t aLb = aHb + G_ARR;
        uint32_t bHb = aHb + 2 * G_ARR;
        uint32_t bLb = aHb + 3 * G_ARR;
#pragma unroll
        for (int ks = 0; ks < 4; ks++) {
            uint32_t a_off = (uint32_t)(((mbase + (lane & 15)) * GTS
                              + ks * 16 + (lane >> 4) * 8) * 2);
            uint32_t aH[2][4], aL[2][4];
#pragma unroll
            for (int i = 0; i < 2; i++) {
                uint32_t o = a_off + (uint32_t)(i * 16 * GTS * 2);
                ldm_x4(aH[i][0], aH[i][1], aH[i][2], aH[i][3], aHb + o);
                ldm_x4(aL[i][0], aL[i][1], aL[i][2], aL[i][3], aLb + o);
            }
            uint32_t b_off = (uint32_t)(((nbase + (lane & 7) + (lane >> 4) * 8) * GTS
                              + ks * 16 + ((lane >> 3) & 1) * 8) * 2);
            uint32_t bH[4][2], bL[4][2];
#pragma unroll
            for (int jp = 0; jp < 2; jp++) {
                uint32_t o = b_off + (uint32_t)(jp * 16 * GTS * 2);
                ldm_x4(bH[jp*2][0], bH[jp*2][1], bH[jp*2+1][0], bH[jp*2+1][1], bHb + o);
                ldm_x4(bL[jp*2][0], bL[jp*2][1], bL[jp*2+1][0], bL[jp*2+1][1], bLb + o);
            }
#pragma unroll
            for (int i = 0; i < 2; i++)
#pragma unroll
                for (int j = 0; j < 4; j++) {
                    mma_bf16(acc[i][j], aH[i], bH[j]);
                    mma_bf16(acc[i][j], aH[i], bL[j]);
                    mma_bf16(acc[i][j], aL[i], bH[j]);
                }
        }
    };

    // ---- pipeline: 16 iters of BK=64 over K=1024 ----
    loadA(0);
    issueB(0, 0);
    issueB(1, 1);
    for (int it = 0; it < 16; it++) {
        int stage = it & 1;
        if (it == 15) cp_wait<0>(); else cp_wait<1>();
        storeA(stage);
        __syncthreads();
        if (it + 1 < 16) loadA(it + 1);
        compute(stage);
        __syncthreads();
        if (it + 2 < 16) issueB(it + 2, stage);
    }

    // ---- LSTM epilogue ----
    float* zbuf = (float*)dsm;                       // [64][68]
#pragma unroll
    for (int i = 0; i < 2; i++) {
        int row = mbase + i * 16 + (lane >> 2);
#pragma unroll
        for (int j = 0; j < 4; j++) {
            int col = nbase + j * 8 + (lane & 3) * 2;
            zbuf[row * 68 + col]       = acc[i][j][0];
            zbuf[row * 68 + col + 1]   = acc[i][j][1];
            zbuf[(row + 8) * 68 + col]     = acc[i][j][2];
            zbuf[(row + 8) * 68 + col + 1] = acc[i][j][3];
        }
    }
    __syncthreads();
#pragma unroll
    for (int l = 0; l < 8; l++) {
        int idx = tid + l * 128;                     // 1024 = 64 b x 16 u
        int b = idx >> 4, ul = idx & 15;
        int u = (n0 >> 2) + ul;
        const float* ad = zpre_t + (size_t)b * 2048;
        float zi = zbuf[b * 68 + ul * 4 + 0] + ad[u];
        float zf = zbuf[b * 68 + ul * 4 + 1] + ad[512 + u];
        float zg = zbuf[b * 68 + ul * 4 + 2] + ad[1024 + u];
        float zo = zbuf[b * 68 + ul * 4 + 3] + ad[1536 + u];
        float si = 1.f / (1.f + expf(-zi));
        float sf = 1.f / (1.f + expf(-zf));
        float so = 1.f / (1.f + expf(-zo));
        float tg = tanhf(zg);
        float c  = sf * cp[(size_t)b * UNITS + u] + si * tg;
        float h  = so * tanhf(c);
        cn[(size_t)b * UNITS + u] = c;
        hn[(size_t)b * UNITS + u] = h;
    }
}

// ---------------------------------------------------------------------------
// Attention with fused q = h @ WqT^T. One block per batch row.
__global__ void attention_kernel(const float* __restrict__ h,
                                 const float* __restrict__ wqT,   // [n][k]
                                 const float* __restrict__ keys,
                                 const float* __restrict__ memory,
                                 const float* __restrict__ v_att,
                                 float* __restrict__ context)
{
    int b = blockIdx.x;
    __shared__ __align__(16) float sh[UNITS];
    __shared__ float sq[UNITS];
    __shared__ float sscore[64];
    int tid = threadIdx.x, warp = tid >> 5, lane = tid & 31;

    for (int u = tid; u < UNITS; u += 256) sh[u] = h[(size_t)b * UNITS + u];
    __syncthreads();

    // q[n] = sum_k sh[k] * wqT[n][k]   (two n per thread)
    {
        int n1 = tid, n2 = tid + 256;
        float a1 = 0.f, a2 = 0.f;
        const float* w1 = wqT + (size_t)n1 * UNITS;
        const float* w2 = wqT + (size_t)n2 * UNITS;
#pragma unroll 4
        for (int k = 0; k < UNITS; k += 4) {
            float4 hv = *(const float4*)&sh[k];
            float4 x1 = *(const float4*)&w1[k];
            float4 x2 = *(const float4*)&w2[k];
            a1 = fmaf(hv.x, x1.x, fmaf(hv.y, x1.y, fmaf(hv.z, x1.z, fmaf(hv.w, x1.w, a1))));
            a2 = fmaf(hv.x, x2.x, fmaf(hv.y, x2.y, fmaf(hv.z, x2.z, fmaf(hv.w, x2.w, a2))));
        }
        sq[n1] = a1; sq[n2] = a2;
    }
    __syncthreads();

    for (int t = warp; t < TIN; t += 8) {
        const float* krow = keys + ((size_t)b * TIN + t) * UNITS;
        float s = 0.f;
        for (int u = lane; u < UNITS; u += 32)
            s += tanhf(krow[u] + sq[u]) * v_att[u];
#pragma unroll
        for (int off = 16; off; off >>= 1) s += __shfl_xor_sync(~0u, s, off);
        if (lane == 0) sscore[t] = s;
    }
    __syncthreads();

    if (tid < 32) {
        float m = -1e30f;
        for (int t = lane; t < TIN; t += 32) m = fmaxf(m, sscore[t]);
#pragma unroll
        for (int off = 16; off; off >>= 1) m = fmaxf(m, __shfl_xor_sync(~0u, m, off));
        float ssum = 0.f;
        for (int t = lane; t < TIN; t += 32) {
            float e = expf(sscore[t] - m);
            sscore[t] = e; ssum += e;
        }
#pragma unroll
        for (int off = 16; off; off >>= 1) ssum += __shfl_xor_sync(~0u, ssum, off);
        float inv = 1.f / ssum;
        for (int t = lane; t < TIN; t += 32) sscore[t] *= inv;
    }
    __syncthreads();

    const float* mrow = memory + (size_t)b * TIN * UNITS;
    for (int d = tid; d < UNITS; d += 256) {
        float acc = 0.f;
#pragma unroll 4
        for (int t = 0; t < TIN; t++)
            acc = fmaf(sscore[t], mrow[(size_t)t * UNITS + d], acc);
        context[(size_t)b * UNITS + d] = acc;
    }
}

// ---------------------------------------------------------------------------
// conversions / transposes (setup, one-time)
__global__ void convert_states_kernel(const float* __restrict__ s,
                                      __nv_bfloat16* __restrict__ hi,
                                      __nv_bfloat16* __restrict__ lo) {
    int i = blockIdx.x * 256 + threadIdx.x;
    float v = (i < ROWS * UNITS) ? s[i] : 0.f;
    __nv_bfloat16 h = __float2bfloat16(v);
    hi[i] = h;
    lo[i] = __float2bfloat16(v - __bfloat162float(h));
}

__global__ void convert_wfc_kernel(const float* __restrict__ W,
                                   __nv_bfloat16* __restrict__ hiT,
                                   __nv_bfloat16* __restrict__ loT) {
    __shared__ float tile[32][33];
    int n0 = blockIdx.x * 32, k0 = blockIdx.y * 32;
    int txx = threadIdx.x & 31, tyy = threadIdx.x >> 5;   // 32 x 8
    for (int j = tyy; j < 32; j += 8) {
        int n = n0 + txx;
        tile[j][txx] = (n < VOCAB) ? W[(size_t)(k0 + j) * VOCAB + n] : 0.f;
    }
    __syncthreads();
    for (int j = tyy; j < 32; j += 8) {
        int n = n0 + j, k = k0 + txx;
        float v = tile[txx][j];
        __nv_bfloat16 h = __float2bfloat16(v);
        hiT[(size_t)n * UNITS + k] = h;
        loT[(size_t)n * UNITS + k] = __float2bfloat16(v - __bfloat162float(h));
    }
}

// [Wk rows 300..811 ; Uk] (k=0..1023, n=0..2047) -> [n'=(n&511)*4+(n>>9)][k]
__global__ void convert_wku_kernel(const float* __restrict__ Wk,
                                   const float* __restrict__ Uk,
                                   __nv_bfloat16* __restrict__ hi,
                                   __nv_bfloat16* __restrict__ lo) {
    __shared__ float tile[32][33];
    int n0 = blockIdx.x * 32, k0 = blockIdx.y * 32;
    int txx = threadIdx.x & 31, tyy = threadIdx.x >> 5;
    for (int j = tyy; j < 32; j += 8) {
        int k = k0 + j, n = n0 + txx;
        float v = (k < 512) ? Wk[(size_t)(300 + k) * 2048 + n]
                            : Uk[(size_t)(k - 512) * 2048 + n];
        tile[j][txx] = v;
    }
    __syncthreads();
    for (int j = tyy; j < 32; j += 8) {
        int n = n0 + j, k = k0 + txx;
        int np = (n & 511) * 4 + (n >> 9);
        float v = tile[txx][j];
        __nv_bfloat16 h = __float2bfloat16(v);
        hi[(size_t)np * 1024 + k] = h;
        lo[(size_t)np * 1024 + k] = __float2bfloat16(v - __bfloat162float(h));
    }
}

__global__ void transpose_wq_kernel(const float* __restrict__ Wq,
                                    float* __restrict__ WqT) {
    __shared__ float tile[32][33];
    int n0 = blockIdx.x * 32, k0 = blockIdx.y * 32;
    int txx = threadIdx.x & 31, tyy = threadIdx.x >> 5;
    for (int j = tyy; j < 32; j += 8)
        tile[j][txx] = Wq[(size_t)(k0 + j) * UNITS + n0 + txx];
    __syncthreads();
    for (int j = tyy; j < 32; j += 8)
        WqT[(size_t)(n0 + j) * UNITS + k0 + txx] = tile[txx][j];
}

// ---------------------------------------------------------------------------
// Pipelined split-bf16 mma GEMM: out[1984,34004] = states @ WfcT^T + bias.
// 128x128 tile, BK=64, 2-stage cp.async, 8 warps of 64x32.
#define FTS     72
#define F_ARR   (128 * FTS * 2)        // 18432 B
#define F_STAGE (4 * F_ARR)            // 73728 B
#define F_SMEM  (2 * F_STAGE)          // 147456 B

__global__ void __launch_bounds__(256)
gemm_mma_pipe(const __nv_bfloat16* __restrict__ Ah,
              const __nv_bfloat16* __restrict__ Al,
              const __nv_bfloat16* __restrict__ Bh,
              const __nv_bfloat16* __restrict__ Bl,
              const float* __restrict__ bias,
              float* __restrict__ out)
{
    extern __shared__ char dsm[];
    const int m0 = blockIdx.x * 128;     // m fastest -> B tiles L2-shared
    const int n0 = blockIdx.y * 128;
    const int tid  = threadIdx.x;
    const int wid  = tid >> 5, lane = tid & 31;
    const int wm   = wid & 1,  wn   = wid >> 1;
    const int mbase = wm * 64, nbase = wn * 32;
    const uint32_t sb = smem_u32(dsm);

    float acc[16][4];
#pragma unroll
    for (int i = 0; i < 16; i++)
#pragma unroll
        for (int j = 0; j < 4; j++) acc[i][j] = 0.f;

    auto issue = [&](int it, int stage) {
        int koff = it * 64;
#pragma unroll
        for (int arr = 0; arr < 4; arr++) {
            const __nv_bfloat16* src = (arr == 0) ? Ah : (arr == 1) ? Al
                                     : (arr == 2) ? Bh : Bl;
            const int rbase = (arr < 2) ? m0 : n0;
#pragma unroll
            for (int l = 0; l < 4; l++) {
                int q = tid + l * 256;               // 1024 chunks
                int r = q >> 3, c8 = (q & 7) * 8;
                uint32_t dst = sb + stage * F_STAGE + arr * F_ARR
                             + (uint32_t)(r * FTS + c8) * 2;
                cp_async16(dst, src + (size_t)(rbase + r) * UNITS + koff + c8);
            }
        }
        cp_commit();
    };
    auto compute = [&](int stage) {
        uint32_t aHb = sb + stage * F_STAGE;
        uint32_t aLb = aHb + F_ARR;
        uint32_t bHb = aHb + 2 * F_ARR;
        uint32_t bLb = aHb + 3 * F_ARR;
#pragma unroll
        for (int ks = 0; ks < 4; ks++) {
            uint32_t a_off = (uint32_t)(((mbase + (lane & 15)) * FTS
                              + ks * 16 + (lane >> 4) * 8) * 2);
            uint32_t aH[4][4], aL[4][4];
#pragma unroll
            for (int i = 0; i < 4; i++) {
                uint32_t o = a_off + (uint32_t)(i * 16 * FTS * 2);
                ldm_x4(aH[i][0], aH[i][1], aH[i][2], aH[i][3], aHb + o);
                ldm_x4(aL[i][0], aL[i][1], aL[i][2], aL[i][3], aLb + o);
            }
            uint32_t b_off = (uint32_t)(((nbase + (lane & 7) + (lane >> 4) * 8) * FTS
                              + ks * 16 + ((lane >> 3) & 1) * 8) * 2);
            uint32_t bH[4][2], bL[4][2];
#pragma unroll
            for (int jp = 0; jp < 2; jp++) {
                uint32_t o = b_off + (uint32_t)(jp * 16 * FTS * 2);
                ldm_x4(bH[jp*2][0], bH[jp*2][1], bH[jp*2+1][0], bH[jp*2+1][1], bHb + o);
                ldm_x4(bL[jp*2][0], bL[jp*2][1], bL[jp*2+1][0], bL[jp*2+1][1], bLb + o);
            }
#pragma unroll
            for (int i = 0; i < 4; i++)
#pragma unroll
                for (int j = 0; j < 4; j++) {
                    mma_bf16(acc[i * 4 + j], aH[i], bH[j]);
                    mma_bf16(acc[i * 4 + j], aH[i], bL[j]);
                    mma_bf16(acc[i * 4 + j], aL[i], bH[j]);
                }
        }
    };

    issue(0, 0);
    issue(1, 1);
    for (int it = 0; it < 8; it++) {
        int stage = it & 1;
        if (it == 7) cp_wait<0>(); else cp_wait<1>();
        __syncthreads();
        compute(stage);
        __syncthreads();
        if (it + 2 < 8) issue(it + 2, stage);
    }

    // epilogue
#pragma unroll
    for (int i = 0; i < 4; i++) {
        int row0 = m0 + mbase + i * 16 + (lane >> 2);
#pragma unroll
        for (int j = 0; j < 4; j++) {
            int col = n0 + nbase + j * 8 + (lane & 3) * 2;
            if (col >= VOCAB) continue;
            float b0 = bias[col], b1 = bias[col + 1];
            const float* c = acc[i * 4 + j];
            if (row0 < ROWS) {
                out[(size_t)row0 * VOCAB + col]     = c[0] + b0;
                out[(size_t)row0 * VOCAB + col + 1] = c[1] + b1;
            }
            if (row0 + 8 < ROWS) {
                out[(size_t)(row0 + 8) * VOCAB + col]     = c[2] + b0;
                out[(size_t)(row0 + 8) * VOCAB + col + 1] = c[3] + b1;
            }
        }
    }
}

// ---------------------------------------------------------------------------
static inline float* sym_addr(const void* sym) {
    void* p = nullptr;
    cudaGetSymbolAddress(&p, sym);
    return (float*)p;
}
static inline __nv_bfloat16* sym_addr_bf(const void* sym) {
    void* p = nullptr;
    cudaGetSymbolAddress(&p, sym);
    return (__nv_bfloat16*)p;
}
#define DIVUP(a, b) (((a) + (b) - 1) / (b))

extern "C" void kernel_launch(void* const* d_in, const int* in_sizes, int n_in,
                              void* d_out, int out_size)
{
    const int*   dec = (const int*)  d_in[0];
    const float* h0  = (const float*)d_in[1];
    const float* c0  = (const float*)d_in[2];
    const float* mem = (const float*)d_in[3];
    const float* emb = (const float*)d_in[4];
    const float* Wk  = (const float*)d_in[5];
    const float* Uk  = (const float*)d_in[6];
    const float* bk  = (const float*)d_in[7];
    const float* Wm  = (const float*)d_in[8];
    const float* Wq  = (const float*)d_in[9];
    const float* vat = (const float*)d_in[10];
    const float* Wa  = (const float*)d_in[11];
    const float* Wfc = (const float*)d_in[12];
    const float* bfc = (const float*)d_in[13];
    float* out = (float*)d_out;

    float* keys   = sym_addr(g_keys);
    float* embA   = sym_addr(g_embA);
    float* zpre   = sym_addr(g_zpre);
    float* hbuf   = sym_addr(g_hbuf);
    float* cbuf   = sym_addr(g_cbuf);
    float* ctx    = sym_addr(g_ctx);
    float* states = sym_addr(g_states);
    float* wqT    = sym_addr(g_wqT);
    __nv_bfloat16* sA_hi = sym_addr_bf(g_sA_hi);
    __nv_bfloat16* sA_lo = sym_addr_bf(g_sA_lo);
    __nv_bfloat16* wT_hi = sym_addr_bf(g_wT_hi);
    __nv_bfloat16* wT_lo = sym_addr_bf(g_wT_lo);
    __nv_bfloat16* wkuH  = sym_addr_bf(g_wkuH);
    __nv_bfloat16* wkuL  = sym_addr_bf(g_wkuL);

    static bool attr_done = false;
    if (!attr_done) {
        cudaFuncSetAttribute(gates_mma_kernel,
                             cudaFuncAttributeMaxDynamicSharedMemorySize, G_SMEM);
        cudaFuncSetAttribute(gemm_mma_pipe,
                             cudaFuncAttributeMaxDynamicSharedMemorySize, F_SMEM);
        attr_done = true;
    }

    // ---- setup (independent) ----
    gather_emb_kernel<<<ROWS, 128>>>(dec, emb, embA);
    sgemm128_kernel<<<dim3(DIVUP(4 * UNITS, 128), DIVUP(ROWS, 128)), 256>>>(
        embA, EMB, Wk, 4 * UNITS, bk, zpre, 4 * UNITS, ROWS, 4 * UNITS, EMB);
    sgemm128_kernel<<<dim3(DIVUP(UNITS, 128), DIVUP(B64 * TIN, 128)), 256>>>(
        mem, UNITS, Wm, UNITS, nullptr, keys, UNITS, B64 * TIN, UNITS, UNITS);
    convert_wfc_kernel<<<dim3(VPAD / 32, UNITS / 32), 256>>>(Wfc, wT_hi, wT_lo);
    convert_wku_kernel<<<dim3(2048 / 32, 1024 / 32), 256>>>(Wk, Uk, wkuH, wkuL);
    transpose_wq_kernel<<<dim3(UNITS / 32, UNITS / 32), 256>>>(Wq, wqT);

    // ---- recurrence: 3 kernels per step ----
    for (int t = 0; t < TOUT; t++) {
        const float* attn_prev = t ? (states + (size_t)(t - 1) * UNITS) : nullptr;
        const float* hp = t ? (hbuf + (size_t)((t - 1) & 1) * B64 * UNITS) : h0;
        const float* cp = t ? (cbuf + (size_t)((t - 1) & 1) * B64 * UNITS) : c0;
        float* hn = hbuf + (size_t)(t & 1) * B64 * UNITS;
        float* cn = cbuf + (size_t)(t & 1) * B64 * UNITS;

        gates_mma_kernel<<<32, 128, G_SMEM>>>(
            attn_prev, hp, cp, wkuH, wkuL,
            zpre + (size_t)t * B64 * 4 * UNITS, hn, cn);

        attention_kernel<<<B64, 256>>>(hn, wqT, keys, mem, vat, ctx);

        step_gemm_kernel<false><<<dim3(8, 4), 256>>>(
            hn, UNITS, Wa, UNITS, UNITS,
            ctx, UNITS, Wa + (size_t)UNITS * UNITS, UNITS, UNITS,
            states + (size_t)t * UNITS, SLD);
    }

    // ---- final vocab projection ----
    convert_states_kernel<<<MPAD * UNITS / 256, 256>>>(states, sA_hi, sA_lo);
    gemm_mma_pipe<<<dim3(MPAD / 128, VPAD / 128), 256, F_SMEM>>>(
        sA_hi, sA_lo, wT_hi, wT_lo, bfc, out);
}

// round 6
// speedup vs baseline: 1.7120x; 1.3741x over previous
#include <cuda_runtime.h>
#include <cuda.h>
#include <cuda_bf16.h>
#include <math.h>
#include <stdint.h>

// ============================================================================
// Attention-LSTM decoder. B=64, T_out=31, T_in=60, U=512, EMB=300, VOCAB=34004.
// Weight folding: attn = [h|ctx]@Wa, so next-step gates input
//   z = attn@Wk' + h@Uk = [h|ctx] @ (Wa@Wk' + [Uk;0])  (precomputed Wbig)
// Per step: (1) gates mma (split-bf16, fused LSTM) -> h into hctx
//           (2) attention (q fused, fast tanh) -> ctx into hctx
// After loop: states = hctx@Wa (one GEMM); out = states@Wfc + bfc (mma pipe).
// ============================================================================

#define B64   64
#define TOUT  31
#define TIN   60
#define UNITS 512
#define EMB   300
#define VOCAB 34004
#define ROWS  (B64 * TOUT)     // 1984
#define MPAD  2048
#define VPAD  34048            // 266 * 128
#define HLD   (TOUT * 1024)    // hctx batch stride = 31744

// ---------------- scratch ----------------------------------------------------
__device__ float g_keys  [B64 * TIN * UNITS];
__device__ float g_embA  [ROWS * EMB];
__device__ float g_zpre  [ROWS * 4 * UNITS];
__device__ float g_cbuf  [2][B64 * UNITS];
__device__ float g_hctx  [ROWS * 1024];            // row = b*31+t : [h|ctx]
__device__ float g_states[ROWS * UNITS];           // row = b*31+t
__device__ float g_wqT   [UNITS * UNITS];          // [n][k]
__device__ float g_wbig  [1024 * 2048];            // Wa@Wk' + [Uk;0]
__device__ __align__(16) __nv_bfloat16 g_sA_hi[MPAD * UNITS];
__device__ __align__(16) __nv_bfloat16 g_sA_lo[MPAD * UNITS];
__device__ __align__(16) __nv_bfloat16 g_wT_hi[(size_t)VPAD * UNITS];  // [n][k]
__device__ __align__(16) __nv_bfloat16 g_wT_lo[(size_t)VPAD * UNITS];
__device__ __align__(16) __nv_bfloat16 g_wkuH[2048 * 1024];   // [n'=u*4+g][k=1024]
__device__ __align__(16) __nv_bfloat16 g_wkuL[2048 * 1024];
__device__ __align__(16) __nv_bfloat16 g_uk0H[2048 * 512];    // [n'][k=512]
__device__ __align__(16) __nv_bfloat16 g_uk0L[2048 * 512];

// ---------------- PTX helpers -------------------------------------------------
__device__ __forceinline__ uint32_t smem_u32(const void* p) {
    uint32_t a;
    asm("{ .reg .u64 t; cvta.to.shared.u64 t, %1; cvt.u32.u64 %0, t; }" : "=r"(a) : "l"(p));
    return a;
}
__device__ __forceinline__ void ldm_x4(uint32_t& r0, uint32_t& r1, uint32_t& r2,
                                       uint32_t& r3, uint32_t addr) {
    asm volatile("ldmatrix.sync.aligned.m8n8.x4.shared.b16 {%0,%1,%2,%3}, [%4];"
                 : "=r"(r0), "=r"(r1), "=r"(r2), "=r"(r3) : "r"(addr));
}
__device__ __forceinline__ void mma_bf16(float* c, const uint32_t* a, const uint32_t* b) {
    asm volatile("mma.sync.aligned.m16n8k16.row.col.f32.bf16.bf16.f32 "
                 "{%0,%1,%2,%3}, {%4,%5,%6,%7}, {%8,%9}, {%0,%1,%2,%3};"
                 : "+f"(c[0]), "+f"(c[1]), "+f"(c[2]), "+f"(c[3])
                 : "r"(a[0]), "r"(a[1]), "r"(a[2]), "r"(a[3]), "r"(b[0]), "r"(b[1]));
}
__device__ __forceinline__ void cp_async16(uint32_t dst, const void* src) {
    asm volatile("cp.async.cg.shared.global [%0], [%1], 16;" :: "r"(dst), "l"(src));
}
__device__ __forceinline__ void cp_commit() { asm volatile("cp.async.commit_group;"); }
template<int N> __device__ __forceinline__ void cp_wait() {
    asm volatile("cp.async.wait_group %0;" :: "n"(N));
}
__device__ __forceinline__ uint32_t pack_bf2(float a, float b) {
    __nv_bfloat162 t = __floats2bfloat162_rn(a, b);
    return *reinterpret_cast<uint32_t*>(&t);
}
__device__ __forceinline__ float bf_res(float a) {
    return a - __bfloat162float(__float2bfloat16(a));
}
// tanh via ex2.approx + rcp.approx: rel err ~1e-6, robust at +-inf.
__device__ __forceinline__ float fast_tanh(float x) {
    float e = __expf(2.f * x);
    return 1.f - __fdividef(2.f, e + 1.f);
}
__device__ __forceinline__ float fast_sigmoid(float x) {
    return __fdividef(1.f, 1.f + __expf(-x));
}

// ---------------------------------------------------------------------------
__global__ void gather_emb_kernel(const int* __restrict__ dec,
                                  const float* __restrict__ emb,
                                  float* __restrict__ out) {
    int r = blockIdx.x;          // r = t*64 + b
    int t = r >> 6, b = r & 63;
    int tok = dec[b * TOUT + t];
    const float* src = emb + (size_t)tok * EMB;
    float* dst = out + (size_t)r * EMB;
    for (int e = threadIdx.x; e < EMB; e += blockDim.x) dst[e] = src[e];
}

// ---------------------------------------------------------------------------
// fp32 SGEMM 128x128x16, 8x8/thread, 256 threads (setup / post GEMMs).
__global__ void sgemm128_kernel(const float* __restrict__ A, int lda,
                                const float* __restrict__ B, int ldb,
                                const float* __restrict__ bias,
                                float* __restrict__ C, int ldc,
                                int M, int N, int K)
{
    __shared__ __align__(16) float As[16][128];
    __shared__ __align__(16) float Bs[16][128];
    const int bm = blockIdx.y * 128, bn = blockIdx.x * 128;
    const int tid = threadIdx.x;
    const int tx = tid & 15, ty = tid >> 4;

    float acc[8][8];
#pragma unroll
    for (int i = 0; i < 8; i++)
#pragma unroll
        for (int j = 0; j < 8; j++) acc[i][j] = 0.f;

    for (int k0 = 0; k0 < K; k0 += 16) {
#pragma unroll
        for (int l = 0; l < 2; l++) {
            int q = tid + l * 256;
            int r = q >> 2, kq = (q & 3) * 4;
            int gm = bm + r, gk = k0 + kq;
            float4 v = make_float4(0.f, 0.f, 0.f, 0.f);
            if (gm < M) {
                if (gk + 3 < K) v = *(const float4*)(A + (size_t)gm * lda + gk);
                else {
                    if (gk + 0 < K) v.x = A[(size_t)gm * lda + gk + 0];
                    if (gk + 1 < K) v.y = A[(size_t)gm * lda + gk + 1];
                    if (gk + 2 < K) v.z = A[(size_t)gm * lda + gk + 2];
                }
            }
            As[kq + 0][r] = v.x; As[kq + 1][r] = v.y;
            As[kq + 2][r] = v.z; As[kq + 3][r] = v.w;
        }
#pragma unroll
        for (int l = 0; l < 2; l++) {
            int q = tid + l * 256;
            int r = q >> 5, cq = (q & 31) * 4;
            int gk = k0 + r, gn = bn + cq;
            float4 v = make_float4(0.f, 0.f, 0.f, 0.f);
            if (gk < K) {
                if (gn + 3 < N) v = *(const float4*)(B + (size_t)gk * ldb + gn);
                else {
                    if (gn + 0 < N) v.x = B[(size_t)gk * ldb + gn + 0];
                    if (gn + 1 < N) v.y = B[(size_t)gk * ldb + gn + 1];
                    if (gn + 2 < N) v.z = B[(size_t)gk * ldb + gn + 2];
                }
            }
            *(float4*)&Bs[r][cq] = v;
        }
        __syncthreads();
#pragma unroll
        for (int kk = 0; kk < 16; kk++) {
            float a[8], b[8];
            *(float4*)&a[0] = *(const float4*)&As[kk][ty * 8];
            *(float4*)&a[4] = *(const float4*)&As[kk][ty * 8 + 4];
            *(float4*)&b[0] = *(const float4*)&Bs[kk][tx * 8];
            *(float4*)&b[4] = *(const float4*)&Bs[kk][tx * 8 + 4];
#pragma unroll
            for (int i = 0; i < 8; i++)
#pragma unroll
                for (int j = 0; j < 8; j++)
                    acc[i][j] = fmaf(a[i], b[j], acc[i][j]);
        }
        __syncthreads();
    }
#pragma unroll
    for (int i = 0; i < 8; i++) {
        int gm = bm + ty * 8 + i;
        if (gm >= M) continue;
#pragma unroll
        for (int j = 0; j < 8; j++) {
            int gn = bn + tx * 8 + j;
            if (gn < N)
                C[(size_t)gm * ldc + gn] = acc[i][j] + (bias ? bias[gn] : 0.f);
        }
    }
}

// ---------------------------------------------------------------------------
// Gates: split-bf16 mma, CTA tile 64m x 64n' (n'=u*4+g), BK=64, 2-stage
// cp.async for B; A (fp32) converted on the fly. Fused LSTM epilogue.
#define GTS     72
#define G_ARR   (64 * GTS * 2)          // 9216 B
#define G_STAGE (4 * G_ARR)             // 36864 B
#define G_SMEM  (2 * G_STAGE)           // 73728 B

__global__ void __launch_bounds__(128)
gates_mma_kernel(const float* __restrict__ Aptr, int astride, int K,
                 const __nv_bfloat16* __restrict__ BH,
                 const __nv_bfloat16* __restrict__ BL,
                 const float* __restrict__ cprev,
                 const float* __restrict__ zpre_t,   // [64][2048]
                 float* __restrict__ hout, int hstride,
                 float* __restrict__ cnew)
{
    extern __shared__ char dsm[];
    const int n0   = blockIdx.x * 64;
    const int tid  = threadIdx.x;
    const int wid  = tid >> 5, lane = tid & 31;
    const int wm   = wid & 1,  wn = wid >> 1;
    const int mbase = wm * 32, nbase = wn * 32;
    const uint32_t sb = smem_u32(dsm);
    const int NIT = K >> 6;

    float acc[2][4][4];
#pragma unroll
    for (int i = 0; i < 2; i++)
#pragma unroll
        for (int j = 0; j < 4; j++)
#pragma unroll
            for (int e = 0; e < 4; e++) acc[i][j][e] = 0.f;

    auto issueB = [&](int it, int stage) {
        int koff = it * 64;
#pragma unroll
        for (int arr = 0; arr < 2; arr++) {
            const __nv_bfloat16* src = arr ? BL : BH;
#pragma unroll
            for (int l = 0; l < 4; l++) {
                int q = tid + l * 128;               // 512 chunks
                int r = q >> 3, c8 = (q & 7) * 8;
                uint32_t dst = sb + stage * G_STAGE + (2 + arr) * G_ARR
                             + (uint32_t)(r * GTS + c8) * 2;
                cp_async16(dst, src + (size_t)(n0 + r) * K + koff + c8);
            }
        }
        cp_commit();
    };
    float4 Areg[8];
    auto loadA = [&](int it) {
        int koff = it * 64;
#pragma unroll
        for (int l = 0; l < 8; l++) {
            int q = tid + l * 128;                   // 1024 float4
            int r = q >> 4, c4 = (q & 15) * 4;
            Areg[l] = *(const float4*)(Aptr + (size_t)r * astride + koff + c4);
        }
    };
    auto storeA = [&](int stage) {
#pragma unroll
        for (int l = 0; l < 8; l++) {
            int q = tid + l * 128;
            int r = q >> 4, c4 = (q & 15) * 4;
            float4 v = Areg[l];
            uint32_t off = (uint32_t)(r * GTS + c4) * 2;
            uint2 hi = make_uint2(pack_bf2(v.x, v.y), pack_bf2(v.z, v.w));
            uint2 lo = make_uint2(pack_bf2(bf_res(v.x), bf_res(v.y)),
                                  pack_bf2(bf_res(v.z), bf_res(v.w)));
            *(uint2*)(dsm + stage * G_STAGE + 0 * G_ARR + off) = hi;
            *(uint2*)(dsm + stage * G_STAGE + 1 * G_ARR + off) = lo;
        }
    };
    auto compute = [&](int stage) {
        uint32_t aHb = sb + stage * G_STAGE;
        uint32_t aLb = aHb + G_ARR;
        uint32_t bHb = aHb + 2 * G_ARR;
        uint32_t bLb = aHb + 3 * G_ARR;
#pragma unroll
        for (int ks = 0; ks < 4; ks++) {
            uint32_t a_off = (uint32_t)(((mbase + (lane & 15)) * GTS
                              + ks * 16 + (lane >> 4) * 8) * 2);
            uint32_t aH[2][4], aL[2][4];
#pragma unroll
            for (int i = 0; i < 2; i++) {
                uint32_t o = a_off + (uint32_t)(i * 16 * GTS * 2);
                ldm_x4(aH[i][0], aH[i][1], aH[i][2], aH[i][3], aHb + o);
                ldm_x4(aL[i][0], aL[i][1], aL[i][2], aL[i][3], aLb + o);
            }
            uint32_t b_off = (uint32_t)(((nbase + (lane & 7) + (lane >> 4) * 8) * GTS
                              + ks * 16 + ((lane >> 3) & 1) * 8) * 2);
            uint32_t bH[4][2], bL[4][2];
#pragma unroll
            for (int jp = 0; jp < 2; jp++) {
                uint32_t o = b_off + (uint32_t)(jp * 16 * GTS * 2);
                ldm_x4(bH[jp*2][0], bH[jp*2][1], bH[jp*2+1][0], bH[jp*2+1][1], bHb + o);
                ldm_x4(bL[jp*2][0], bL[jp*2][1], bL[jp*2+1][0], bL[jp*2+1][1], bLb + o);
            }
#pragma unroll
            for (int i = 0; i < 2; i++)
#pragma unroll
                for (int j = 0; j < 4; j++) {
                    mma_bf16(acc[i][j], aH[i], bH[j]);
                    mma_bf16(acc[i][j], aH[i], bL[j]);
                    mma_bf16(acc[i][j], aL[i], bH[j]);
                }
        }
    };

    loadA(0);
    issueB(0, 0);
    issueB(1, 1);
    for (int it = 0; it < NIT; it++) {
        int stage = it & 1;
        if (it == NIT - 1) cp_wait<0>(); else cp_wait<1>();
        storeA(stage);
        __syncthreads();
        if (it + 1 < NIT) loadA(it + 1);
        compute(stage);
        __syncthreads();
        if (it + 2 < NIT) issueB(it + 2, stage);
    }

    // ---- LSTM epilogue ----
    float* zbuf = (float*)dsm;                       // [64][68]
#pragma unroll
    for (int i = 0; i < 2; i++) {
        int row = mbase + i * 16 + (lane >> 2);
#pragma unroll
        for (int j = 0; j < 4; j++) {
            int col = nbase + j * 8 + (lane & 3) * 2;
            zbuf[row * 68 + col]           = acc[i][j][0];
            zbuf[row * 68 + col + 1]       = acc[i][j][1];
            zbuf[(row + 8) * 68 + col]     = acc[i][j][2];
            zbuf[(row + 8) * 68 + col + 1] = acc[i][j][3];
        }
    }
    __syncthreads();
#pragma unroll
    for (int l = 0; l < 8; l++) {
        int idx = tid + l * 128;                     // 1024 = 64 b x 16 u
        int b = idx >> 4, ul = idx & 15;
        int u = (n0 >> 2) + ul;
        const float* ad = zpre_t + (size_t)b * 2048;
        float zi = zbuf[b * 68 + ul * 4 + 0] + ad[u];
        float zf = zbuf[b * 68 + ul * 4 + 1] + ad[512 + u];
        float zg = zbuf[b * 68 + ul * 4 + 2] + ad[1024 + u];
        float zo = zbuf[b * 68 + ul * 4 + 3] + ad[1536 + u];
        float si = fast_sigmoid(zi);
        float sf = fast_sigmoid(zf);
        float so = fast_sigmoid(zo);
        float tg = fast_tanh(zg);
        float c  = sf * cprev[(size_t)b * UNITS + u] + si * tg;
        float h  = so * fast_tanh(c);
        cnew[(size_t)b * UNITS + u] = c;
        hout[(size_t)b * hstride + u] = h;
    }
}

// ---------------------------------------------------------------------------
// Attention (q = h@WqT fused, fast tanh), 512 threads, one block per b.
// Reads h from hrow[b*HLD + 0:512]; writes ctx to hrow[b*HLD + 512:1024].
__global__ void __launch_bounds__(512)
attention_kernel(float* __restrict__ hrow,           // = g_hctx + t*1024
                 const float* __restrict__ wqT,      // [n][k]
                 const float* __restrict__ keys,
                 const float* __restrict__ memory,
                 const float* __restrict__ v_att)
{
    int b = blockIdx.x;
    __shared__ __align__(16) float sh[UNITS];
    __shared__ float sq[UNITS];
    __shared__ float sscore[64];
    int tid = threadIdx.x, warp = tid >> 5, lane = tid & 31;

    sh[tid] = hrow[(size_t)b * HLD + tid];
    __syncthreads();

    // q[n] = sum_k sh[k] * wqT[n][k]
    {
        float a = 0.f;
        const float* w = wqT + (size_t)tid * UNITS;
#pragma unroll 4
        for (int k = 0; k < UNITS; k += 4) {
            float4 hv = *(const float4*)&sh[k];
            float4 x  = *(const float4*)&w[k];
            a = fmaf(hv.x, x.x, fmaf(hv.y, x.y, fmaf(hv.z, x.z, fmaf(hv.w, x.w, a))));
        }
        sq[tid] = a;
    }
    __syncthreads();

    for (int t = warp; t < TIN; t += 16) {
        const float* krow = keys + ((size_t)b * TIN + t) * UNITS;
        float s = 0.f;
        for (int u = lane; u < UNITS; u += 32)
            s += fast_tanh(krow[u] + sq[u]) * v_att[u];
#pragma unroll
        for (int off = 16; off; off >>= 1) s += __shfl_xor_sync(~0u, s, off);
        if (lane == 0) sscore[t] = s;
    }
    __syncthreads();

    if (tid < 32) {
        float m = -1e30f;
        for (int t = lane; t < TIN; t += 32) m = fmaxf(m, sscore[t]);
#pragma unroll
        for (int off = 16; off; off >>= 1) m = fmaxf(m, __shfl_xor_sync(~0u, m, off));
        float ssum = 0.f;
        for (int t = lane; t < TIN; t += 32) {
            float e = __expf(sscore[t] - m);
            sscore[t] = e; ssum += e;
        }
#pragma unroll
        for (int off = 16; off; off >>= 1) ssum += __shfl_xor_sync(~0u, ssum, off);
        float inv = __fdividef(1.f, ssum);
        for (int t = lane; t < TIN; t += 32) sscore[t] *= inv;
    }
    __syncthreads();

    const float* mrow = memory + (size_t)b * TIN * UNITS;
    float acc = 0.f;
#pragma unroll 4
    for (int t = 0; t < TIN; t++)
        acc = fmaf(sscore[t], mrow[(size_t)t * UNITS + tid], acc);
    hrow[(size_t)b * HLD + 512 + tid] = acc;
}

// ---------------------------------------------------------------------------
// setup conversions
__global__ void convert_states_kernel(const float* __restrict__ s,
                                      __nv_bfloat16* __restrict__ hi,
                                      __nv_bfloat16* __restrict__ lo) {
    int i = blockIdx.x * 256 + threadIdx.x;
    float v = (i < ROWS * UNITS) ? s[i] : 0.f;
    __nv_bfloat16 h = __float2bfloat16(v);
    hi[i] = h;
    lo[i] = __float2bfloat16(v - __bfloat162float(h));
}

__global__ void convert_wfc_kernel(const float* __restrict__ W,
                                   __nv_bfloat16* __restrict__ hiT,
                                   __nv_bfloat16* __restrict__ loT) {
    __shared__ float tile[32][33];
    int n0 = blockIdx.x * 32, k0 = blockIdx.y * 32;
    int txx = threadIdx.x & 31, tyy = threadIdx.x >> 5;
    for (int j = tyy; j < 32; j += 8) {
        int n = n0 + txx;
        tile[j][txx] = (n < VOCAB) ? W[(size_t)(k0 + j) * VOCAB + n] : 0.f;
    }
    __syncthreads();
    for (int j = tyy; j < 32; j += 8) {
        int n = n0 + j, k = k0 + txx;
        float v = tile[txx][j];
        __nv_bfloat16 h = __float2bfloat16(v);
        hiT[(size_t)n * UNITS + k] = h;
        loT[(size_t)n * UNITS + k] = __float2bfloat16(v - __bfloat162float(h));
    }
}

// W [K][2048] -> gate-interleaved split-bf16 [n'=(n&511)*4+(n>>9)][K]
__global__ void convert_gatesW_kernel(const float* __restrict__ W, int K,
                                      __nv_bfloat16* __restrict__ hi,
                                      __nv_bfloat16* __restrict__ lo) {
    __shared__ float tile[32][33];
    int n0 = blockIdx.x * 32, k0 = blockIdx.y * 32;
    int txx = threadIdx.x & 31, tyy = threadIdx.x >> 5;
    for (int j = tyy; j < 32; j += 8)
        tile[j][txx] = W[(size_t)(k0 + j) * 2048 + n0 + txx];
    __syncthreads();
    for (int j = tyy; j < 32; j += 8) {
        int n = n0 + j, k = k0 + txx;
        int np = (n & 511) * 4 + (n >> 9);
        float v = tile[txx][j];
        __nv_bfloat16 h = __float2bfloat16(v);
        hi[(size_t)np * K + k] = h;
        lo[(size_t)np * K + k] = __float2bfloat16(v - __bfloat162float(h));
    }
}

__global__ void add_uk_kernel(float* __restrict__ wbig,
                              const float* __restrict__ Uk) {
    int i = blockIdx.x * 256 + threadIdx.x;      // over 512*2048
    if (i < 512 * 2048) wbig[i] += Uk[i];
}

__global__ void transpose_wq_kernel(const float* __restrict__ Wq,
                                    float* __restrict__ WqT) {
    __shared__ float tile[32][33];
    int n0 = blockIdx.x * 32, k0 = blockIdx.y * 32;
    int txx = threadIdx.x & 31, tyy = threadIdx.x >> 5;
    for (int j = tyy; j < 32; j += 8)
        tile[j][txx] = Wq[(size_t)(k0 + j) * UNITS + n0 + txx];
    __syncthreads();
    for (int j = tyy; j < 32; j += 8)
        WqT[(size_t)(n0 + j) * UNITS + k0 + txx] = tile[txx][j];
}

// ---------------------------------------------------------------------------
// Pipelined split-bf16 mma GEMM: out[1984,34004] = states @ WfcT^T + bias.
#define FTS     72
#define F_ARR   (128 * FTS * 2)        // 18432 B
#define F_STAGE (4 * F_ARR)            // 73728 B
#define F_SMEM  (2 * F_STAGE)          // 147456 B

__global__ void __launch_bounds__(256)
gemm_mma_pipe(const __nv_bfloat16* __restrict__ Ah,
              const __nv_bfloat16* __restrict__ Al,
              const __nv_bfloat16* __restrict__ Bh,
              const __nv_bfloat16* __restrict__ Bl,
              const float* __restrict__ bias,
              float* __restrict__ out)
{
    extern __shared__ char dsm[];
    const int m0 = blockIdx.x * 128;
    const int n0 = blockIdx.y * 128;
    const int tid  = threadIdx.x;
    const int wid  = tid >> 5, lane = tid & 31;
    const int wm   = wid & 1,  wn   = wid >> 1;
    const int mbase = wm * 64, nbase = wn * 32;
    const uint32_t sb = smem_u32(dsm);

    float acc[16][4];
#pragma unroll
    for (int i = 0; i < 16; i++)
#pragma unroll
        for (int j = 0; j < 4; j++) acc[i][j] = 0.f;

    auto issue = [&](int it, int stage) {
        int koff = it * 64;
#pragma unroll
        for (int arr = 0; arr < 4; arr++) {
            const __nv_bfloat16* src = (arr == 0) ? Ah : (arr == 1) ? Al
                                     : (arr == 2) ? Bh : Bl;
            const int rbase = (arr < 2) ? m0 : n0;
#pragma unroll
            for (int l = 0; l < 4; l++) {
                int q = tid + l * 256;
                int r = q >> 3, c8 = (q & 7) * 8;
                uint32_t dst = sb + stage * F_STAGE + arr * F_ARR
                             + (uint32_t)(r * FTS + c8) * 2;
                cp_async16(dst, src + (size_t)(rbase + r) * UNITS + koff + c8);
            }
        }
        cp_commit();
    };
    auto compute = [&](int stage) {
        uint32_t aHb = sb + stage * F_STAGE;
        uint32_t aLb = aHb + F_ARR;
        uint32_t bHb = aHb + 2 * F_ARR;
        uint32_t bLb = aHb + 3 * F_ARR;
#pragma unroll
        for (int ks = 0; ks < 4; ks++) {
            uint32_t a_off = (uint32_t)(((mbase + (lane & 15)) * FTS
                              + ks * 16 + (lane >> 4) * 8) * 2);
            uint32_t aH[4][4], aL[4][4];
#pragma unroll
            for (int i = 0; i < 4; i++) {
                uint32_t o = a_off + (uint32_t)(i * 16 * FTS * 2);
                ldm_x4(aH[i][0], aH[i][1], aH[i][2], aH[i][3], aHb + o);
                ldm_x4(aL[i][0], aL[i][1], aL[i][2], aL[i][3], aLb + o);
            }
            uint32_t b_off = (uint32_t)(((nbase + (lane & 7) + (lane >> 4) * 8) * FTS
                              + ks * 16 + ((lane >> 3) & 1) * 8) * 2);
            uint32_t bH[4][2], bL[4][2];
#pragma unroll
            for (int jp = 0; jp < 2; jp++) {
                uint32_t o = b_off + (uint32_t)(jp * 16 * FTS * 2);
                ldm_x4(bH[jp*2][0], bH[jp*2][1], bH[jp*2+1][0], bH[jp*2+1][1], bHb + o);
                ldm_x4(bL[jp*2][0], bL[jp*2][1], bL[jp*2+1][0], bL[jp*2+1][1], bLb + o);
            }
#pragma unroll
            for (int i = 0; i < 4; i++)
#pragma unroll
                for (int j = 0; j < 4; j++) {
                    mma_bf16(acc[i * 4 + j], aH[i], bH[j]);
                    mma_bf16(acc[i * 4 + j], aH[i], bL[j]);
                    mma_bf16(acc[i * 4 + j], aL[i], bH[j]);
                }
        }
    };

    issue(0, 0);
    issue(1, 1);
    for (int it = 0; it < 8; it++) {
        int stage = it & 1;
        if (it == 7) cp_wait<0>(); else cp_wait<1>();
        __syncthreads();
        compute(stage);
        __syncthreads();
        if (it + 2 < 8) issue(it + 2, stage);
    }

#pragma unroll
    for (int i = 0; i < 4; i++) {
        int row0 = m0 + mbase + i * 16 + (lane >> 2);
#pragma unroll
        for (int j = 0; j < 4; j++) {
            int col = n0 + nbase + j * 8 + (lane & 3) * 2;
            if (col >= VOCAB) continue;
            float b0 = bias[col], b1 = bias[col + 1];
            const float* c = acc[i * 4 + j];
            if (row0 < ROWS) {
                out[(size_t)row0 * VOCAB + col]     = c[0] + b0;
                out[(size_t)row0 * VOCAB + col + 1] = c[1] + b1;
            }
            if (row0 + 8 < ROWS) {
                out[(size_t)(row0 + 8) * VOCAB + col]     = c[2] + b0;
                out[(size_t)(row0 + 8) * VOCAB + col + 1] = c[3] + b1;
            }
        }
    }
}

// ---------------------------------------------------------------------------
static inline float* sym_addr(const void* sym) {
    void* p = nullptr;
    cudaGetSymbolAddress(&p, sym);
    return (float*)p;
}
static inline __nv_bfloat16* sym_addr_bf(const void* sym) {
    void* p = nullptr;
    cudaGetSymbolAddress(&p, sym);
    return (__nv_bfloat16*)p;
}
#define DIVUP(a, b) (((a) + (b) - 1) / (b))

extern "C" void kernel_launch(void* const* d_in, const int* in_sizes, int n_in,
                              void* d_out, int out_size)
{
    const int*   dec = (const int*)  d_in[0];
    const float* h0  = (const float*)d_in[1];
    const float* c0  = (const float*)d_in[2];
    const float* mem = (const float*)d_in[3];
    const float* emb = (const float*)d_in[4];
    const float* Wk  = (const float*)d_in[5];
    const float* Uk  = (const float*)d_in[6];
    const float* bk  = (const float*)d_in[7];
    const float* Wm  = (const float*)d_in[8];
    const float* Wq  = (const float*)d_in[9];
    const float* vat = (const float*)d_in[10];
    const float* Wa  = (const float*)d_in[11];
    const float* Wfc = (const float*)d_in[12];
    const float* bfc = (const float*)d_in[13];
    float* out = (float*)d_out;

    float* keys   = sym_addr(g_keys);
    float* embA   = sym_addr(g_embA);
    float* zpre   = sym_addr(g_zpre);
    float* cbuf   = sym_addr(g_cbuf);
    float* hctx   = sym_addr(g_hctx);
    float* states = sym_addr(g_states);
    float* wqT    = sym_addr(g_wqT);
    float* wbig   = sym_addr(g_wbig);
    __nv_bfloat16* sA_hi = sym_addr_bf(g_sA_hi);
    __nv_bfloat16* sA_lo = sym_addr_bf(g_sA_lo);
    __nv_bfloat16* wT_hi = sym_addr_bf(g_wT_hi);
    __nv_bfloat16* wT_lo = sym_addr_bf(g_wT_lo);
    __nv_bfloat16* wkuH  = sym_addr_bf(g_wkuH);
    __nv_bfloat16* wkuL  = sym_addr_bf(g_wkuL);
    __nv_bfloat16* uk0H  = sym_addr_bf(g_uk0H);
    __nv_bfloat16* uk0L  = sym_addr_bf(g_uk0L);

    static bool attr_done = false;
    if (!attr_done) {
        cudaFuncSetAttribute(gates_mma_kernel,
                             cudaFuncAttributeMaxDynamicSharedMemorySize, G_SMEM);
        cudaFuncSetAttribute(gemm_mma_pipe,
                             cudaFuncAttributeMaxDynamicSharedMemorySize, F_SMEM);
        attr_done = true;
    }

    // ---- setup ----
    gather_emb_kernel<<<ROWS, 128>>>(dec, emb, embA);
    // zpre = embA @ Wk[0:300] + bk
    sgemm128_kernel<<<dim3(16, 16), 256>>>(
        embA, EMB, Wk, 2048, bk, zpre, 2048, ROWS, 2048, EMB);
    // keys = memory @ Wm
    sgemm128_kernel<<<dim3(4, 30), 256>>>(
        mem, UNITS, Wm, UNITS, nullptr, keys, UNITS, B64 * TIN, UNITS, UNITS);
    convert_wfc_kernel<<<dim3(VPAD / 32, UNITS / 32), 256>>>(Wfc, wT_hi, wT_lo);
    transpose_wq_kernel<<<dim3(16, 16), 256>>>(Wq, wqT);
    // Wbig = Wa @ Wk[300:812] ; then += [Uk;0]
    sgemm128_kernel<<<dim3(16, 8), 256>>>(
        Wa, UNITS, Wk + (size_t)EMB * 2048, 2048, nullptr, wbig, 2048,
        1024, 2048, UNITS);
    add_uk_kernel<<<(512 * 2048) / 256, 256>>>(wbig, Uk);
    convert_gatesW_kernel<<<dim3(64, 32), 256>>>(wbig, 1024, wkuH, wkuL);
    convert_gatesW_kernel<<<dim3(64, 16), 256>>>(Uk, 512, uk0H, uk0L);

    // ---- recurrence: 2 kernels per step ----
    for (int t = 0; t < TOUT; t++) {
        const float* cp = t ? (cbuf + (size_t)((t - 1) & 1) * B64 * UNITS) : c0;
        float* cn = cbuf + (size_t)(t & 1) * B64 * UNITS;

        if (t == 0) {
            gates_mma_kernel<<<32, 128, G_SMEM>>>(
                h0, UNITS, 512, uk0H, uk0L, cp,
                zpre, hctx, HLD, cn);
        } else {
            gates_mma_kernel<<<32, 128, G_SMEM>>>(
                hctx + (size_t)(t - 1) * 1024, HLD, 1024, wkuH, wkuL, cp,
                zpre + (size_t)t * B64 * 2048, hctx + (size_t)t * 1024, HLD, cn);
        }
        attention_kernel<<<B64, 512>>>(hctx + (size_t)t * 1024, wqT, keys, mem, vat);
    }

    // ---- states = hctx @ Wa  (one batched GEMM) ----
    sgemm128_kernel<<<dim3(4, 16), 256>>>(
        hctx, 1024, Wa, UNITS, nullptr, states, UNITS, ROWS, UNITS, 1024);

    // ---- vocab projection ----
    convert_states_kernel<<<MPAD * UNITS / 256, 256>>>(states, sA_hi, sA_lo);
    gemm_mma_pipe<<<dim3(MPAD / 128, VPAD / 128), 256, F_SMEM>>>(
        sA_hi, sA_lo, wT_hi, wT_lo, bfc, out);
}

// round 7
// speedup vs baseline: 1.7461x; 1.0199x over previous
#include <cuda_runtime.h>
#include <cuda.h>
#include <cuda_bf16.h>
#include <math.h>
#include <stdint.h>

// ============================================================================
// Attention-LSTM decoder. B=64, T_out=31, T_in=60, U=512, EMB=300, VOCAB=34004.
// Weight folding: z_t = [h|ctx]_{t-1} @ Wbig,  Wbig = Wa@Wk' + [Uk;0].
// ONE persistent kernel (64 CTAs x 512 thr) runs all 31 steps with software
// grid barriers:  gates(split-bf16 mma + LSTM) -> barrier -> attention -> barrier.
// Post: states = hctx@Wa (fp32 GEMM, bf16 hi/lo epilogue);
//       out = states @ Wfc + bfc (pipelined split-bf16 mma GEMM).
// ============================================================================

#define B64   64
#define TOUT  31
#define TIN   60
#define UNITS 512
#define EMB   300
#define VOCAB 34004
#define ROWS  (B64 * TOUT)     // 1984
#define MPAD  2048
#define VPAD  34048            // 266 * 128
#define HLD   (TOUT * 1024)    // hctx batch stride = 31744

// ---------------- scratch ----------------------------------------------------
__device__ float g_keys  [B64 * TIN * UNITS];
__device__ float g_embA  [ROWS * EMB];
__device__ float g_zpre  [ROWS * 4 * UNITS];
__device__ float g_cbuf  [2][B64 * UNITS];
__device__ float g_hctx  [ROWS * 1024];            // (b*31+t)*1024 : [h|ctx]
__device__ float g_states[ROWS * UNITS];
__device__ float g_wqT   [UNITS * UNITS];          // [n][k]
__device__ float g_wbig  [1024 * 2048];            // Wa@Wk' + [Uk;0]
__device__ __align__(16) __nv_bfloat16 g_sA_hi[MPAD * UNITS];   // pad rows stay 0
__device__ __align__(16) __nv_bfloat16 g_sA_lo[MPAD * UNITS];
__device__ __align__(16) __nv_bfloat16 g_wT_hi[(size_t)VPAD * UNITS];  // [n][k]
__device__ __align__(16) __nv_bfloat16 g_wT_lo[(size_t)VPAD * UNITS];
__device__ __align__(16) __nv_bfloat16 g_wkuH[2048 * 1024];   // [n'=u*4+g][k]
__device__ __align__(16) __nv_bfloat16 g_wkuL[2048 * 1024];
__device__ __align__(16) __nv_bfloat16 g_uk0H[2048 * 512];
__device__ __align__(16) __nv_bfloat16 g_uk0L[2048 * 512];

// grid barrier state
__device__ int g_bar_cnt = 0;
__device__ volatile unsigned g_bar_gen = 0;

// ---------------- PTX helpers -------------------------------------------------
__device__ __forceinline__ uint32_t smem_u32(const void* p) {
    uint32_t a;
    asm("{ .reg .u64 t; cvta.to.shared.u64 t, %1; cvt.u32.u64 %0, t; }" : "=r"(a) : "l"(p));
    return a;
}
__device__ __forceinline__ void ldm_x4(uint32_t& r0, uint32_t& r1, uint32_t& r2,
                                       uint32_t& r3, uint32_t addr) {
    asm volatile("ldmatrix.sync.aligned.m8n8.x4.shared.b16 {%0,%1,%2,%3}, [%4];"
                 : "=r"(r0), "=r"(r1), "=r"(r2), "=r"(r3) : "r"(addr));
}
__device__ __forceinline__ void ldm_x2(uint32_t& r0, uint32_t& r1, uint32_t addr) {
    asm volatile("ldmatrix.sync.aligned.m8n8.x2.shared.b16 {%0,%1}, [%2];"
                 : "=r"(r0), "=r"(r1) : "r"(addr));
}
__device__ __forceinline__ void mma_bf16(float* c, const uint32_t* a, const uint32_t* b) {
    asm volatile("mma.sync.aligned.m16n8k16.row.col.f32.bf16.bf16.f32 "
                 "{%0,%1,%2,%3}, {%4,%5,%6,%7}, {%8,%9}, {%0,%1,%2,%3};"
                 : "+f"(c[0]), "+f"(c[1]), "+f"(c[2]), "+f"(c[3])
                 : "r"(a[0]), "r"(a[1]), "r"(a[2]), "r"(a[3]), "r"(b[0]), "r"(b[1]));
}
__device__ __forceinline__ void cp_async16(uint32_t dst, const void* src) {
    asm volatile("cp.async.cg.shared.global [%0], [%1], 16;" :: "r"(dst), "l"(src));
}
__device__ __forceinline__ void cp_commit() { asm volatile("cp.async.commit_group;"); }
template<int N> __device__ __forceinline__ void cp_wait() {
    asm volatile("cp.async.wait_group %0;" :: "n"(N));
}
__device__ __forceinline__ uint32_t pack_bf2(float a, float b) {
    __nv_bfloat162 t = __floats2bfloat162_rn(a, b);
    return *reinterpret_cast<uint32_t*>(&t);
}
__device__ __forceinline__ float bf_res(float a) {
    return a - __bfloat162float(__float2bfloat16(a));
}
__device__ __forceinline__ float fast_tanh(float x) {
    float e = __expf(2.f * x);
    return 1.f - __fdividef(2.f, e + 1.f);
}
__device__ __forceinline__ float fast_sigmoid(float x) {
    return __fdividef(1.f, 1.f + __expf(-x));
}
__device__ __forceinline__ void grid_barrier(int nCTA) {
    __syncthreads();
    if (threadIdx.x == 0) {
        unsigned gen = g_bar_gen;
        __threadfence();
        if (atomicAdd(&g_bar_cnt, 1) == nCTA - 1) {
            g_bar_cnt = 0;
            __threadfence();
            g_bar_gen = gen + 1;
        } else {
            while (g_bar_gen == gen) { }
        }
        __threadfence();
    }
    __syncthreads();
}

// ---------------------------------------------------------------------------
__global__ void gather_emb_kernel(const int* __restrict__ dec,
                                  const float* __restrict__ emb,
                                  float* __restrict__ out) {
    int r = blockIdx.x;          // r = t*64 + b
    int t = r >> 6, b = r & 63;
    int tok = dec[b * TOUT + t];
    const float* src = emb + (size_t)tok * EMB;
    float* dst = out + (size_t)r * EMB;
    for (int e = threadIdx.x; e < EMB; e += blockDim.x) dst[e] = src[e];
}

// ---------------------------------------------------------------------------
// fp32 SGEMM 128x128x16. BF16OUT: epilogue writes hi/lo split-bf16 instead.
template<bool BF16OUT>
__global__ void sgemm128_kernel(const float* __restrict__ A, int lda,
                                const float* __restrict__ B, int ldb,
                                const float* __restrict__ bias,
                                float* __restrict__ C, int ldc,
                                __nv_bfloat16* __restrict__ Chi,
                                __nv_bfloat16* __restrict__ Clo,
                                int M, int N, int K)
{
    __shared__ __align__(16) float As[16][128];
    __shared__ __align__(16) float Bs[16][128];
    const int bm = blockIdx.y * 128, bn = blockIdx.x * 128;
    const int tid = threadIdx.x;
    const int tx = tid & 15, ty = tid >> 4;

    float acc[8][8];
#pragma unroll
    for (int i = 0; i < 8; i++)
#pragma unroll
        for (int j = 0; j < 8; j++) acc[i][j] = 0.f;

    for (int k0 = 0; k0 < K; k0 += 16) {
#pragma unroll
        for (int l = 0; l < 2; l++) {
            int q = tid + l * 256;
            int r = q >> 2, kq = (q & 3) * 4;
            int gm = bm + r, gk = k0 + kq;
            float4 v = make_float4(0.f, 0.f, 0.f, 0.f);
            if (gm < M) {
                if (gk + 3 < K) v = *(const float4*)(A + (size_t)gm * lda + gk);
                else {
                    if (gk + 0 < K) v.x = A[(size_t)gm * lda + gk + 0];
                    if (gk + 1 < K) v.y = A[(size_t)gm * lda + gk + 1];
                    if (gk + 2 < K) v.z = A[(size_t)gm * lda + gk + 2];
                }
            }
            As[kq + 0][r] = v.x; As[kq + 1][r] = v.y;
            As[kq + 2][r] = v.z; As[kq + 3][r] = v.w;
        }
#pragma unroll
        for (int l = 0; l < 2; l++) {
            int q = tid + l * 256;
            int r = q >> 5, cq = (q & 31) * 4;
            int gk = k0 + r, gn = bn + cq;
            float4 v = make_float4(0.f, 0.f, 0.f, 0.f);
            if (gk < K) {
                if (gn + 3 < N) v = *(const float4*)(B + (size_t)gk * ldb + gn);
                else {
                    if (gn + 0 < N) v.x = B[(size_t)gk * ldb + gn + 0];
                    if (gn + 1 < N) v.y = B[(size_t)gk * ldb + gn + 1];
                    if (gn + 2 < N) v.z = B[(size_t)gk * ldb + gn + 2];
                }
            }
            *(float4*)&Bs[r][cq] = v;
        }
        __syncthreads();
#pragma unroll
        for (int kk = 0; kk < 16; kk++) {
            float a[8], b[8];
            *(float4*)&a[0] = *(const float4*)&As[kk][ty * 8];
            *(float4*)&a[4] = *(const float4*)&As[kk][ty * 8 + 4];
            *(float4*)&b[0] = *(const float4*)&Bs[kk][tx * 8];
            *(float4*)&b[4] = *(const float4*)&Bs[kk][tx * 8 + 4];
#pragma unroll
            for (int i = 0; i < 8; i++)
#pragma unroll
                for (int j = 0; j < 8; j++)
                    acc[i][j] = fmaf(a[i], b[j], acc[i][j]);
        }
        __syncthreads();
    }
#pragma unroll
    for (int i = 0; i < 8; i++) {
        int gm = bm + ty * 8 + i;
        if (gm >= M) continue;
#pragma unroll
        for (int j = 0; j < 8; j++) {
            int gn = bn + tx * 8 + j;
            if (gn >= N) continue;
            if (BF16OUT) {
                float v = acc[i][j];
                __nv_bfloat16 h = __float2bfloat16(v);
                Chi[(size_t)gm * ldc + gn] = h;
                Clo[(size_t)gm * ldc + gn] =
                    __float2bfloat16(v - __bfloat162float(h));
            } else {
                C[(size_t)gm * ldc + gn] = acc[i][j] + (bias ? bias[gn] : 0.f);
            }
        }
    }
}

// ---------------------------------------------------------------------------
// setup conversions
__global__ void convert_wfc_kernel(const float* __restrict__ W,
                                   __nv_bfloat16* __restrict__ hiT,
                                   __nv_bfloat16* __restrict__ loT) {
    __shared__ float tile[32][33];
    int n0 = blockIdx.x * 32, k0 = blockIdx.y * 32;
    int txx = threadIdx.x & 31, tyy = threadIdx.x >> 5;
    for (int j = tyy; j < 32; j += 8) {
        int n = n0 + txx;
        tile[j][txx] = (n < VOCAB) ? W[(size_t)(k0 + j) * VOCAB + n] : 0.f;
    }
    __syncthreads();
    for (int j = tyy; j < 32; j += 8) {
        int n = n0 + j, k = k0 + txx;
        float v = tile[txx][j];
        __nv_bfloat16 h = __float2bfloat16(v);
        hiT[(size_t)n * UNITS + k] = h;
        loT[(size_t)n * UNITS + k] = __float2bfloat16(v - __bfloat162float(h));
    }
}

// W [K][2048] -> gate-interleaved split-bf16 [n'=(n&511)*4+(n>>9)][K]
__global__ void convert_gatesW_kernel(const float* __restrict__ W, int K,
                                      __nv_bfloat16* __restrict__ hi,
                                      __nv_bfloat16* __restrict__ lo) {
    __shared__ float tile[32][33];
    int n0 = blockIdx.x * 32, k0 = blockIdx.y * 32;
    int txx = threadIdx.x & 31, tyy = threadIdx.x >> 5;
    for (int j = tyy; j < 32; j += 8)
        tile[j][txx] = W[(size_t)(k0 + j) * 2048 + n0 + txx];
    __syncthreads();
    for (int j = tyy; j < 32; j += 8) {
        int n = n0 + j, k = k0 + txx;
        int np = (n & 511) * 4 + (n >> 9);
        float v = tile[txx][j];
        __nv_bfloat16 h = __float2bfloat16(v);
        hi[(size_t)np * K + k] = h;
        lo[(size_t)np * K + k] = __float2bfloat16(v - __bfloat162float(h));
    }
}

__global__ void add_uk_kernel(float* __restrict__ wbig,
                              const float* __restrict__ Uk) {
    int i = blockIdx.x * 256 + threadIdx.x;
    if (i < 512 * 2048) wbig[i] += Uk[i];
}

__global__ void transpose_wq_kernel(const float* __restrict__ Wq,
                                    float* __restrict__ WqT) {
    __shared__ float tile[32][33];
    int n0 = blockIdx.x * 32, k0 = blockIdx.y * 32;
    int txx = threadIdx.x & 31, tyy = threadIdx.x >> 5;
    for (int j = tyy; j < 32; j += 8)
        tile[j][txx] = Wq[(size_t)(k0 + j) * UNITS + n0 + txx];
    __syncthreads();
    for (int j = tyy; j < 32; j += 8)
        WqT[(size_t)(n0 + j) * UNITS + k0 + txx] = tile[txx][j];
}

// ---------------------------------------------------------------------------
// PERSISTENT step loop: 64 CTAs x 512 threads, all co-resident.
// Gates phase: CTA cta handles n' = cta*32 .. +31 (tile 64m x 32n', BK=64,
// 2-stage cp.async, 16 mma warps of 16x8, split-bf16 3-term). LSTM epilogue.
// Attention phase: CTA b = cta (q fused, fast tanh).
#define PTS     72
#define P_AH    0
#define P_AL    9216
#define P_BH    18432
#define P_BL    23040
#define P_STAGE 27648
#define P_SMEM  (2 * P_STAGE)    // 55296 B

__global__ void __launch_bounds__(512, 1)
step_loop_kernel(const float* __restrict__ h0,
                 const float* __restrict__ c0,
                 const __nv_bfloat16* __restrict__ uk0H,
                 const __nv_bfloat16* __restrict__ uk0L,
                 const __nv_bfloat16* __restrict__ wkuH,
                 const __nv_bfloat16* __restrict__ wkuL,
                 const float* __restrict__ zpre,
                 float* __restrict__ cbuf,          // [2][64*512]
                 float* __restrict__ hctx,
                 const float* __restrict__ wqT,
                 const float* __restrict__ keys,
                 const float* __restrict__ memory,
                 const float* __restrict__ v_att)
{
    extern __shared__ char dsm[];
    const int cta  = blockIdx.x;        // 0..63
    const int tid  = threadIdx.x;
    const int wid  = tid >> 5, lane = tid & 31;
    const int wm   = wid & 3,  wn   = wid >> 2;    // 4x4 warp grid
    const int mbase = wm * 16, nbase = wn * 8;
    const int n0   = cta * 32;
    const uint32_t sb = smem_u32(dsm);
    const int nCTA = gridDim.x;

    for (int t = 0; t < TOUT; t++) {
        // ================= gates phase =================
        const float* Aptr; int astride, K;
        const __nv_bfloat16 *BH, *BL;
        if (t == 0) { Aptr = h0; astride = UNITS; K = 512; BH = uk0H; BL = uk0L; }
        else { Aptr = hctx + (size_t)(t - 1) * 1024; astride = HLD; K = 1024;
               BH = wkuH; BL = wkuL; }
        const float* cprev = t ? (cbuf + (size_t)((t - 1) & 1) * B64 * UNITS) : c0;
        float* cnew = cbuf + (size_t)(t & 1) * B64 * UNITS;
        const int NIT = K >> 6;

        float acc[4] = {0.f, 0.f, 0.f, 0.f};
        float4 Areg[2];

        auto issueB = [&](int it, int stage) {
            int koff = it * 64;
            int arr = tid >> 8;                   // 0: hi, 1: lo
            int r   = (tid >> 3) & 31;
            int c8  = (tid & 7) * 8;
            const __nv_bfloat16* src = arr ? BL : BH;
            uint32_t dst = sb + stage * P_STAGE + (arr ? P_BL : P_BH)
                         + (uint32_t)(r * PTS + c8) * 2;
            cp_async16(dst, src + (size_t)(n0 + r) * K + koff + c8);
            cp_commit();
        };
        auto loadA = [&](int it) {
            int koff = it * 64;
#pragma unroll
            for (int l = 0; l < 2; l++) {
                int q = tid + l * 512;
                int r = q >> 4, c4 = (q & 15) * 4;
                Areg[l] = *(const float4*)(Aptr + (size_t)r * astride + koff + c4);
            }
        };
        auto storeA = [&](int stage) {
#pragma unroll
            for (int l = 0; l < 2; l++) {
                int q = tid + l * 512;
                int r = q >> 4, c4 = (q & 15) * 4;
                float4 v = Areg[l];
                uint32_t off = (uint32_t)(r * PTS + c4) * 2;
                uint2 hi = make_uint2(pack_bf2(v.x, v.y), pack_bf2(v.z, v.w));
                uint2 lo = make_uint2(pack_bf2(bf_res(v.x), bf_res(v.y)),
                                      pack_bf2(bf_res(v.z), bf_res(v.w)));
                *(uint2*)(dsm + stage * P_STAGE + P_AH + off) = hi;
                *(uint2*)(dsm + stage * P_STAGE + P_AL + off) = lo;
            }
        };
        auto compute = [&](int stage) {
            uint32_t aHb = sb + stage * P_STAGE + P_AH;
            uint32_t aLb = sb + stage * P_STAGE + P_AL;
            uint32_t bHb = sb + stage * P_STAGE + P_BH;
            uint32_t bLb = sb + stage * P_STAGE + P_BL;
#pragma unroll
            for (int ks = 0; ks < 4; ks++) {
                uint32_t a_off = (uint32_t)(((mbase + (lane & 15)) * PTS
                                  + ks * 16 + (lane >> 4) * 8) * 2);
                uint32_t aH[4], aL[4];
                ldm_x4(aH[0], aH[1], aH[2], aH[3], aHb + a_off);
                ldm_x4(aL[0], aL[1], aL[2], aL[3], aLb + a_off);
                uint32_t b_off = (uint32_t)(((nbase + (lane & 7)) * PTS
                                  + ks * 16 + ((lane >> 3) & 1) * 8) * 2);
                uint32_t bH[2], bL[2];
                ldm_x2(bH[0], bH[1], bHb + b_off);
                ldm_x2(bL[0], bL[1], bLb + b_off);
                mma_bf16(acc, aH, bH);
                mma_bf16(acc, aH, bL);
                mma_bf16(acc, aL, bH);
            }
        };

        loadA(0);
        issueB(0, 0);
        issueB(1, 1);
        for (int it = 0; it < NIT; it++) {
            int stage = it & 1;
            if (it == NIT - 1) cp_wait<0>(); else cp_wait<1>();
            storeA(stage);
            __syncthreads();
            if (it + 1 < NIT) loadA(it + 1);
            compute(stage);
            __syncthreads();
            if (it + 2 < NIT) issueB(it + 2, stage);
        }

        // LSTM epilogue: z fragments -> smem -> pointwise
        float* zbuf = (float*)dsm;                   // [64][36]
        {
            int row = mbase + (lane >> 2);
            int col = nbase + (lane & 3) * 2;
            zbuf[row * 36 + col]           = acc[0];
            zbuf[row * 36 + col + 1]       = acc[1];
            zbuf[(row + 8) * 36 + col]     = acc[2];
            zbuf[(row + 8) * 36 + col + 1] = acc[3];
        }
        __syncthreads();
        {
            int b  = tid >> 3, ul = tid & 7;         // 64 b x 8 u
            int u  = cta * 8 + ul;
            const float* ad = zpre + (size_t)t * B64 * 2048 + (size_t)b * 2048;
            float zi = zbuf[b * 36 + ul * 4 + 0] + ad[u];
            float zf = zbuf[b * 36 + ul * 4 + 1] + ad[512 + u];
            float zg = zbuf[b * 36 + ul * 4 + 2] + ad[1024 + u];
            float zo = zbuf[b * 36 + ul * 4 + 3] + ad[1536 + u];
            float si = fast_sigmoid(zi);
            float sf = fast_sigmoid(zf);
            float so = fast_sigmoid(zo);
            float tg = fast_tanh(zg);
            float c  = sf * cprev[(size_t)b * UNITS + u] + si * tg;
            float h  = so * fast_tanh(c);
            cnew[(size_t)b * UNITS + u] = c;
            hctx[(size_t)b * HLD + (size_t)t * 1024 + u] = h;
        }

        grid_barrier(nCTA);

        // ================= attention phase =================
        {
            int b = cta;
            float* sh  = (float*)dsm;                // 512
            float* sq  = sh + 512;                   // 512
            float* ssc = sq + 512;                   // 64
            float* hrow = hctx + (size_t)b * HLD + (size_t)t * 1024;

            sh[tid] = hrow[tid];
            __syncthreads();

            {
                float a = 0.f;
                const float* w = wqT + (size_t)tid * UNITS;
#pragma unroll 4
                for (int k = 0; k < UNITS; k += 4) {
                    float4 hv = *(const float4*)&sh[k];
                    float4 x  = *(const float4*)&w[k];
                    a = fmaf(hv.x, x.x, fmaf(hv.y, x.y,
                        fmaf(hv.z, x.z, fmaf(hv.w, x.w, a))));
                }
                sq[tid] = a;
            }
            __syncthreads();

            for (int s = wid; s < TIN; s += 16) {
                const float* krow = keys + ((size_t)b * TIN + s) * UNITS;
                float sc = 0.f;
                for (int u = lane; u < UNITS; u += 32)
                    sc += fast_tanh(krow[u] + sq[u]) * v_att[u];
#pragma unroll
                for (int off = 16; off; off >>= 1)
                    sc += __shfl_xor_sync(~0u, sc, off);
                if (lane == 0) ssc[s] = sc;
            }
            __syncthreads();

            if (tid < 32) {
                float m = -1e30f;
                for (int s = lane; s < TIN; s += 32) m = fmaxf(m, ssc[s]);
#pragma unroll
                for (int off = 16; off; off >>= 1)
                    m = fmaxf(m, __shfl_xor_sync(~0u, m, off));
                float ssum = 0.f;
                for (int s = lane; s < TIN; s += 32) {
                    float e = __expf(ssc[s] - m);
                    ssc[s] = e; ssum += e;
                }
#pragma unroll
                for (int off = 16; off; off >>= 1)
                    ssum += __shfl_xor_sync(~0u, ssum, off);
                float inv = __fdividef(1.f, ssum);
                for (int s = lane; s < TIN; s += 32) ssc[s] *= inv;
            }
            __syncthreads();

            const float* mrow = memory + (size_t)b * TIN * UNITS;
            float accc = 0.f;
#pragma unroll 4
            for (int s = 0; s < TIN; s++)
                accc = fmaf(ssc[s], mrow[(size_t)s * UNITS + tid], accc);
            hrow[512 + tid] = accc;
        }

        grid_barrier(nCTA);
    }
}

// ---------------------------------------------------------------------------
// Pipelined split-bf16 mma GEMM: out[1984,34004] = states @ WfcT^T + bias.
#define FTS     72
#define F_ARR   (128 * FTS * 2)
#define F_STAGE (4 * F_ARR)
#define F_SMEM  (2 * F_STAGE)

__global__ void __launch_bounds__(256)
gemm_mma_pipe(const __nv_bfloat16* __restrict__ Ah,
              const __nv_bfloat16* __restrict__ Al,
              const __nv_bfloat16* __restrict__ Bh,
              const __nv_bfloat16* __restrict__ Bl,
              const float* __restrict__ bias,
              float* __restrict__ out)
{
    extern __shared__ char dsm[];
    const int m0 = blockIdx.x * 128;
    const int n0 = blockIdx.y * 128;
    const int tid  = threadIdx.x;
    const int wid  = tid >> 5, lane = tid & 31;
    const int wm   = wid & 1,  wn   = wid >> 1;
    const int mbase = wm * 64, nbase = wn * 32;
    const uint32_t sb = smem_u32(dsm);

    float acc[16][4];
#pragma unroll
    for (int i = 0; i < 16; i++)
#pragma unroll
        for (int j = 0; j < 4; j++) acc[i][j] = 0.f;

    auto issue = [&](int it, int stage) {
        int koff = it * 64;
#pragma unroll
        for (int arr = 0; arr < 4; arr++) {
            const __nv_bfloat16* src = (arr == 0) ? Ah : (arr == 1) ? Al
                                     : (arr == 2) ? Bh : Bl;
            const int rbase = (arr < 2) ? m0 : n0;
#pragma unroll
            for (int l = 0; l < 4; l++) {
                int q = tid + l * 256;
                int r = q >> 3, c8 = (q & 7) * 8;
                uint32_t dst = sb + stage * F_STAGE + arr * F_ARR
                             + (uint32_t)(r * FTS + c8) * 2;
                cp_async16(dst, src + (size_t)(rbase + r) * UNITS + koff + c8);
            }
        }
        cp_commit();
    };
    auto compute = [&](int stage) {
        uint32_t aHb = sb + stage * F_STAGE;
        uint32_t aLb = aHb + F_ARR;
        uint32_t bHb = aHb + 2 * F_ARR;
        uint32_t bLb = aHb + 3 * F_ARR;
#pragma unroll
        for (int ks = 0; ks < 4; ks++) {
            uint32_t a_off = (uint32_t)(((mbase + (lane & 15)) * FTS
                              + ks * 16 + (lane >> 4) * 8) * 2);
            uint32_t aH[4][4], aL[4][4];
#pragma unroll
            for (int i = 0; i < 4; i++) {
                uint32_t o = a_off + (uint32_t)(i * 16 * FTS * 2);
                ldm_x4(aH[i][0], aH[i][1], aH[i][2], aH[i][3], aHb + o);
                ldm_x4(aL[i][0], aL[i][1], aL[i][2], aL[i][3], aLb + o);
            }
            uint32_t b_off = (uint32_t)(((nbase + (lane & 7) + (lane >> 4) * 8) * FTS
                              + ks * 16 + ((lane >> 3) & 1) * 8) * 2);
            uint32_t bH[4][2], bL[4][2];
#pragma unroll
            for (int jp = 0; jp < 2; jp++) {
                uint32_t o = b_off + (uint32_t)(jp * 16 * FTS * 2);
                ldm_x4(bH[jp*2][0], bH[jp*2][1], bH[jp*2+1][0], bH[jp*2+1][1], bHb + o);
                ldm_x4(bL[jp*2][0], bL[jp*2][1], bL[jp*2+1][0], bL[jp*2+1][1], bLb + o);
            }
#pragma unroll
            for (int i = 0; i < 4; i++)
#pragma unroll
                for (int j = 0; j < 4; j++) {
                    mma_bf16(acc[i * 4 + j], aH[i], bH[j]);
                    mma_bf16(acc[i * 4 + j], aH[i], bL[j]);
                    mma_bf16(acc[i * 4 + j], aL[i], bH[j]);
                }
        }
    };

    issue(0, 0);
    issue(1, 1);
    for (int it = 0; it < 8; it++) {
        int stage = it & 1;
        if (it == 7) cp_wait<0>(); else cp_wait<1>();
        __syncthreads();
        compute(stage);
        __syncthreads();
        if (it + 2 < 8) issue(it + 2, stage);
    }

#pragma unroll
    for (int i = 0; i < 4; i++) {
        int row0 = m0 + mbase + i * 16 + (lane >> 2);
#pragma unroll
        for (int j = 0; j < 4; j++) {
            int col = n0 + nbase + j * 8 + (lane & 3) * 2;
            if (col >= VOCAB) continue;
            float b0 = bias[col], b1 = bias[col + 1];
            const float* c = acc[i * 4 + j];
            if (row0 < ROWS) {
                out[(size_t)row0 * VOCAB + col]     = c[0] + b0;
                out[(size_t)row0 * VOCAB + col + 1] = c[1] + b1;
            }
            if (row0 + 8 < ROWS) {
                out[(size_t)(row0 + 8) * VOCAB + col]     = c[2] + b0;
                out[(size_t)(row0 + 8) * VOCAB + col + 1] = c[3] + b1;
            }
        }
    }
}

// ---------------------------------------------------------------------------
static inline float* sym_addr(const void* sym) {
    void* p = nullptr;
    cudaGetSymbolAddress(&p, sym);
    return (float*)p;
}
static inline __nv_bfloat16* sym_addr_bf(const void* sym) {
    void* p = nullptr;
    cudaGetSymbolAddress(&p, sym);
    return (__nv_bfloat16*)p;
}
#define DIVUP(a, b) (((a) + (b) - 1) / (b))

extern "C" void kernel_launch(void* const* d_in, const int* in_sizes, int n_in,
                              void* d_out, int out_size)
{
    const int*   dec = (const int*)  d_in[0];
    const float* h0  = (const float*)d_in[1];
    const float* c0  = (const float*)d_in[2];
    const float* mem = (const float*)d_in[3];
    const float* emb = (const float*)d_in[4];
    const float* Wk  = (const float*)d_in[5];
    const float* Uk  = (const float*)d_in[6];
    const float* bk  = (const float*)d_in[7];
    const float* Wm  = (const float*)d_in[8];
    const float* Wq  = (const float*)d_in[9];
    const float* vat = (const float*)d_in[10];
    const float* Wa  = (const float*)d_in[11];
    const float* Wfc = (const float*)d_in[12];
    const float* bfc = (const float*)d_in[13];
    float* out = (float*)d_out;

    float* keys   = sym_addr(g_keys);
    float* embA   = sym_addr(g_embA);
    float* zpre   = sym_addr(g_zpre);
    float* cbuf   = sym_addr(g_cbuf);
    float* hctx   = sym_addr(g_hctx);
    float* states = sym_addr(g_states);
    float* wqT    = sym_addr(g_wqT);
    float* wbig   = sym_addr(g_wbig);
    __nv_bfloat16* sA_hi = sym_addr_bf(g_sA_hi);
    __nv_bfloat16* sA_lo = sym_addr_bf(g_sA_lo);
    __nv_bfloat16* wT_hi = sym_addr_bf(g_wT_hi);
    __nv_bfloat16* wT_lo = sym_addr_bf(g_wT_lo);
    __nv_bfloat16* wkuH  = sym_addr_bf(g_wkuH);
    __nv_bfloat16* wkuL  = sym_addr_bf(g_wkuL);
    __nv_bfloat16* uk0H  = sym_addr_bf(g_uk0H);
    __nv_bfloat16* uk0L  = sym_addr_bf(g_uk0L);

    cudaFuncSetAttribute(step_loop_kernel,
                         cudaFuncAttributeMaxDynamicSharedMemorySize, P_SMEM);
    cudaFuncSetAttribute(gemm_mma_pipe,
                         cudaFuncAttributeMaxDynamicSharedMemorySize, F_SMEM);

    // ---- setup (independent) ----
    gather_emb_kernel<<<ROWS, 128>>>(dec, emb, embA);
    sgemm128_kernel<false><<<dim3(16, 16), 256>>>(
        embA, EMB, Wk, 2048, bk, zpre, 2048, nullptr, nullptr, ROWS, 2048, EMB);
    sgemm128_kernel<false><<<dim3(4, 30), 256>>>(
        mem, UNITS, Wm, UNITS, nullptr, keys, UNITS, nullptr, nullptr,
        B64 * TIN, UNITS, UNITS);
    convert_wfc_kernel<<<dim3(VPAD / 32, UNITS / 32), 256>>>(Wfc, wT_hi, wT_lo);
    transpose_wq_kernel<<<dim3(16, 16), 256>>>(Wq, wqT);
    sgemm128_kernel<false><<<dim3(16, 8), 256>>>(
        Wa, UNITS, Wk + (size_t)EMB * 2048, 2048, nullptr, wbig, 2048,
        nullptr, nullptr, 1024, 2048, UNITS);
    add_uk_kernel<<<(512 * 2048) / 256, 256>>>(wbig, Uk);
    convert_gatesW_kernel<<<dim3(64, 32), 256>>>(wbig, 1024, wkuH, wkuL);
    convert_gatesW_kernel<<<dim3(64, 16), 256>>>(Uk, 512, uk0H, uk0L);

    // ---- all 31 steps in ONE persistent kernel ----
    step_loop_kernel<<<64, 512, P_SMEM>>>(
        h0, c0, uk0H, uk0L, wkuH, wkuL, zpre, cbuf, hctx,
        wqT, keys, mem, vat);

    // ---- states = hctx @ Wa with split-bf16 epilogue ----
    sgemm128_kernel<true><<<dim3(4, 16), 256>>>(
        hctx, 1024, Wa, UNITS, nullptr, nullptr, UNITS, sA_hi, sA_lo,
        ROWS, UNITS, 1024);

    // ---- vocab projection ----
    gemm_mma_pipe<<<dim3(MPAD / 128, VPAD / 128), 256, F_SMEM>>>(
        sA_hi, sA_lo, wT_hi, wT_lo, bfc, out);
}

// round 8
// speedup vs baseline: 2.1833x; 1.2504x over previous
#include <cuda_runtime.h>
#include <cuda.h>
#include <cuda_bf16.h>
#include <cuda_fp16.h>
#include <math.h>
#include <stdint.h>

// ============================================================================
// Attention-LSTM decoder. B=64, T_out=31, T_in=60, U=512, EMB=300, VOCAB=34004.
// - setup GEMMs (keys/zpre/wbig/states) on tensor cores: generic split-bf16
//   3-term mma GEMM with on-the-fly fp32 A conversion, pre-split B.
// - persistent step loop (64 CTA x 512 thr): gates split-bf16 mma + LSTM ->
//   barrier -> attention (fused q, fast tanh) -> barrier.
// - vocab projection: 2-term fp16 mma GEMM (A split exactly, B rounded once;
//   L2 rel err ~2.8e-4 << 1e-3).
// ============================================================================

#define B64   64
#define TOUT  31
#define TIN   60
#define UNITS 512
#define EMB   300
#define EMBP  320
#define VOCAB 34004
#define ROWS  (B64 * TOUT)     // 1984
#define MPAD  2048
#define VPAD  34048            // 266 * 128
#define HLD   (TOUT * 1024)

// ---------------- scratch ----------------------------------------------------
__device__ float g_keys  [B64 * TIN * UNITS];
__device__ float g_embA  [ROWS * EMBP];
__device__ float g_zpre  [ROWS * 4 * UNITS];
__device__ float g_cbuf  [2][B64 * UNITS];
__device__ float g_hctx  [ROWS * 1024];
__device__ float g_wqT   [UNITS * UNITS];
__device__ float g_wbig  [1024 * 2048];
__device__ __align__(16) __half g_sA_hi[MPAD * UNITS];   // pad rows stay 0
__device__ __align__(16) __half g_sA_lo[MPAD * UNITS];
__device__ __align__(16) __half g_wT_h [(size_t)VPAD * UNITS];  // fp16 [n][k]
__device__ __align__(16) __nv_bfloat16 g_wkuH[2048 * 1024];
__device__ __align__(16) __nv_bfloat16 g_wkuL[2048 * 1024];
__device__ __align__(16) __nv_bfloat16 g_uk0H[2048 * 512];
__device__ __align__(16) __nv_bfloat16 g_uk0L[2048 * 512];
// B splits for setup GEMMs  [n][k] bf16
__device__ __align__(16) __nv_bfloat16 g_wmT_h [512 * 512];
__device__ __align__(16) __nv_bfloat16 g_wmT_l [512 * 512];
__device__ __align__(16) __nv_bfloat16 g_wk0T_h[2048 * EMBP];
__device__ __align__(16) __nv_bfloat16 g_wk0T_l[2048 * EMBP];
__device__ __align__(16) __nv_bfloat16 g_wkpT_h[2048 * 512];
__device__ __align__(16) __nv_bfloat16 g_wkpT_l[2048 * 512];
__device__ __align__(16) __nv_bfloat16 g_waT_h [512 * 1024];
__device__ __align__(16) __nv_bfloat16 g_waT_l [512 * 1024];

__device__ int g_bar_cnt = 0;
__device__ volatile unsigned g_bar_gen = 0;

// ---------------- PTX helpers -------------------------------------------------
__device__ __forceinline__ uint32_t smem_u32(const void* p) {
    uint32_t a;
    asm("{ .reg .u64 t; cvta.to.shared.u64 t, %1; cvt.u32.u64 %0, t; }" : "=r"(a) : "l"(p));
    return a;
}
__device__ __forceinline__ void ldm_x4(uint32_t& r0, uint32_t& r1, uint32_t& r2,
                                       uint32_t& r3, uint32_t addr) {
    asm volatile("ldmatrix.sync.aligned.m8n8.x4.shared.b16 {%0,%1,%2,%3}, [%4];"
                 : "=r"(r0), "=r"(r1), "=r"(r2), "=r"(r3) : "r"(addr));
}
__device__ __forceinline__ void ldm_x2(uint32_t& r0, uint32_t& r1, uint32_t addr) {
    asm volatile("ldmatrix.sync.aligned.m8n8.x2.shared.b16 {%0,%1}, [%2];"
                 : "=r"(r0), "=r"(r1) : "r"(addr));
}
__device__ __forceinline__ void mma_bf16(float* c, const uint32_t* a, const uint32_t* b) {
    asm volatile("mma.sync.aligned.m16n8k16.row.col.f32.bf16.bf16.f32 "
                 "{%0,%1,%2,%3}, {%4,%5,%6,%7}, {%8,%9}, {%0,%1,%2,%3};"
                 : "+f"(c[0]), "+f"(c[1]), "+f"(c[2]), "+f"(c[3])
                 : "r"(a[0]), "r"(a[1]), "r"(a[2]), "r"(a[3]), "r"(b[0]), "r"(b[1]));
}
__device__ __forceinline__ void mma_f16(float* c, const uint32_t* a, const uint32_t* b) {
    asm volatile("mma.sync.aligned.m16n8k16.row.col.f32.f16.f16.f32 "
                 "{%0,%1,%2,%3}, {%4,%5,%6,%7}, {%8,%9}, {%0,%1,%2,%3};"
                 : "+f"(c[0]), "+f"(c[1]), "+f"(c[2]), "+f"(c[3])
                 : "r"(a[0]), "r"(a[1]), "r"(a[2]), "r"(a[3]), "r"(b[0]), "r"(b[1]));
}
__device__ __forceinline__ void cp_async16(uint32_t dst, const void* src) {
    asm volatile("cp.async.cg.shared.global [%0], [%1], 16;" :: "r"(dst), "l"(src));
}
__device__ __forceinline__ void cp_commit() { asm volatile("cp.async.commit_group;"); }
template<int N> __device__ __forceinline__ void cp_wait() {
    asm volatile("cp.async.wait_group %0;" :: "n"(N));
}
__device__ __forceinline__ uint32_t pack_bf2(float a, float b) {
    __nv_bfloat162 t = __floats2bfloat162_rn(a, b);
    return *reinterpret_cast<uint32_t*>(&t);
}
__device__ __forceinline__ float bf_res(float a) {
    return a - __bfloat162float(__float2bfloat16(a));
}
__device__ __forceinline__ float fast_tanh(float x) {
    float e = __expf(2.f * x);
    return 1.f - __fdividef(2.f, e + 1.f);
}
__device__ __forceinline__ float fast_sigmoid(float x) {
    return __fdividef(1.f, 1.f + __expf(-x));
}
__device__ __forceinline__ void grid_barrier(int nCTA) {
    __syncthreads();
    if (threadIdx.x == 0) {
        unsigned gen = g_bar_gen;
        __threadfence();
        if (atomicAdd(&g_bar_cnt, 1) == nCTA - 1) {
            g_bar_cnt = 0;
            __threadfence();
            g_bar_gen = gen + 1;
        } else {
            while (g_bar_gen == gen) { }
        }
        __threadfence();
    }
    __syncthreads();
}

// ---------------------------------------------------------------------------
__global__ void gather_emb_kernel(const int* __restrict__ dec,
                                  const float* __restrict__ emb,
                                  float* __restrict__ out) {
    int r = blockIdx.x;          // r = t*64 + b
    int t = r >> 6, b = r & 63;
    int tok = dec[b * TOUT + t];
    const float* src = emb + (size_t)tok * EMB;
    float* dst = out + (size_t)r * EMBP;
    for (int e = threadIdx.x; e < EMBP; e += blockDim.x)
        dst[e] = (e < EMB) ? src[e] : 0.f;
}

// ---------------------------------------------------------------------------
// Generic transpose + split-bf16: W [K][N] (ld=ldn) -> hiT/loT [Npad][Kpad]
__global__ void tsplit_bf16_kernel(const float* __restrict__ W,
                                   int K, int N, int ldn, int Kpad,
                                   __nv_bfloat16* __restrict__ hiT,
                                   __nv_bfloat16* __restrict__ loT) {
    __shared__ float tile[32][33];
    int n0 = blockIdx.x * 32, k0 = blockIdx.y * 32;
    int tx = threadIdx.x & 31, ty = threadIdx.x >> 5;
    for (int j = ty; j < 32; j += 8) {
        int k = k0 + j, n = n0 + tx;
        tile[j][tx] = (k < K && n < N) ? W[(size_t)k * ldn + n] : 0.f;
    }
    __syncthreads();
    for (int j = ty; j < 32; j += 8) {
        int n = n0 + j, k = k0 + tx;
        float v = tile[tx][j];
        __nv_bfloat16 h = __float2bfloat16(v);
        hiT[(size_t)n * Kpad + k] = h;
        loT[(size_t)n * Kpad + k] = __float2bfloat16(v - __bfloat162float(h));
    }
}

// Wfc [512][34004] -> single fp16 [VPAD][512]
__global__ void convert_wfc_h_kernel(const float* __restrict__ W,
                                     __half* __restrict__ hT) {
    __shared__ float tile[32][33];
    int n0 = blockIdx.x * 32, k0 = blockIdx.y * 32;
    int tx = threadIdx.x & 31, ty = threadIdx.x >> 5;
    for (int j = ty; j < 32; j += 8) {
        int n = n0 + tx;
        tile[j][tx] = (n < VOCAB) ? W[(size_t)(k0 + j) * VOCAB + n] : 0.f;
    }
    __syncthreads();
    for (int j = ty; j < 32; j += 8) {
        int n = n0 + j, k = k0 + tx;
        hT[(size_t)n * UNITS + k] = __float2half_rn(tile[tx][j]);
    }
}

// W [K][2048] -> gate-interleaved split-bf16 [n'=(n&511)*4+(n>>9)][K]
__global__ void convert_gatesW_kernel(const float* __restrict__ W, int K,
                                      __nv_bfloat16* __restrict__ hi,
                                      __nv_bfloat16* __restrict__ lo) {
    __shared__ float tile[32][33];
    int n0 = blockIdx.x * 32, k0 = blockIdx.y * 32;
    int tx = threadIdx.x & 31, ty = threadIdx.x >> 5;
    for (int j = ty; j < 32; j += 8)
        tile[j][tx] = W[(size_t)(k0 + j) * 2048 + n0 + tx];
    __syncthreads();
    for (int j = ty; j < 32; j += 8) {
        int n = n0 + j, k = k0 + tx;
        int np = (n & 511) * 4 + (n >> 9);
        float v = tile[tx][j];
        __nv_bfloat16 h = __float2bfloat16(v);
        hi[(size_t)np * K + k] = h;
        lo[(size_t)np * K + k] = __float2bfloat16(v - __bfloat162float(h));
    }
}

__global__ void add_uk_kernel(float* __restrict__ wbig,
                              const float* __restrict__ Uk) {
    int i = blockIdx.x * 256 + threadIdx.x;
    if (i < 512 * 2048) wbig[i] += Uk[i];
}

__global__ void transpose_wq_kernel(const float* __restrict__ Wq,
                                    float* __restrict__ WqT) {
    __shared__ float tile[32][33];
    int n0 = blockIdx.x * 32, k0 = blockIdx.y * 32;
    int tx = threadIdx.x & 31, ty = threadIdx.x >> 5;
    for (int j = ty; j < 32; j += 8)
        tile[j][tx] = Wq[(size_t)(k0 + j) * UNITS + n0 + tx];
    __syncthreads();
    for (int j = ty; j < 32; j += 8)
        WqT[(size_t)(n0 + j) * UNITS + k0 + tx] = tile[tx][j];
}

// ---------------------------------------------------------------------------
// Generic split-bf16 3-term mma GEMM with fp32 A (converted on the fly).
// C[M x N] = A[M x K] @ Bsplit^T (+ bias).  Tile 128x128, BK=64, 2-stage.
// MODE 0: fp32 C (+bias).  MODE 1: fp16 hi/lo outputs (exact split).
#define FTS     72
#define F_ARR   (128 * FTS * 2)        // 18432 B
#define F_STAGE (4 * F_ARR)            // 73728 B
#define F_SMEM  (2 * F_STAGE)          // 147456 B

template<int MODE>
__global__ void __launch_bounds__(256)
gemm_mma_AF(const float* __restrict__ A, int lda, int M, int N, int K,
            const __nv_bfloat16* __restrict__ BhT,
            const __nv_bfloat16* __restrict__ BlT,
            const float* __restrict__ bias,
            float* __restrict__ C, int ldc,
            __half* __restrict__ Chi, __half* __restrict__ Clo)
{
    extern __shared__ char dsm[];
    const int m0 = blockIdx.x * 128;
    const int n0 = blockIdx.y * 128;
    const int tid  = threadIdx.x;
    const int wid  = tid >> 5, lane = tid & 31;
    const int wm   = wid & 1,  wn   = wid >> 1;
    const int mbase = wm * 64, nbase = wn * 32;
    const uint32_t sb = smem_u32(dsm);
    const int NIT = K >> 6;

    float acc[16][4];
#pragma unroll
    for (int i = 0; i < 16; i++)
#pragma unroll
        for (int j = 0; j < 4; j++) acc[i][j] = 0.f;

    float4 Areg[8];
    auto loadA = [&](int it) {
        int koff = it * 64;
#pragma unroll
        for (int l = 0; l < 8; l++) {
            int q = tid + l * 256;                 // 2048 float4
            int r = q >> 4, c4 = (q & 15) * 4;
            int gm = m0 + r;
            Areg[l] = (gm < M) ? *(const float4*)(A + (size_t)gm * lda + koff + c4)
                               : make_float4(0.f, 0.f, 0.f, 0.f);
        }
    };
    auto storeA = [&](int stage) {
#pragma unroll
        for (int l = 0; l < 8; l++) {
            int q = tid + l * 256;
            int r = q >> 4, c4 = (q & 15) * 4;
            float4 v = Areg[l];
            uint32_t off = (uint32_t)(r * FTS + c4) * 2;
            uint2 hi = make_uint2(pack_bf2(v.x, v.y), pack_bf2(v.z, v.w));
            uint2 lo = make_uint2(pack_bf2(bf_res(v.x), bf_res(v.y)),
                                  pack_bf2(bf_res(v.z), bf_res(v.w)));
            *(uint2*)(dsm + stage * F_STAGE + 0 * F_ARR + off) = hi;
            *(uint2*)(dsm + stage * F_STAGE + 1 * F_ARR + off) = lo;
        }
    };
    auto issueB = [&](int it, int stage) {
        int koff = it * 64;
#pragma unroll
        for (int arr = 0; arr < 2; arr++) {
            const __nv_bfloat16* src = arr ? BlT : BhT;
#pragma unroll
            for (int l = 0; l < 4; l++) {
                int q = tid + l * 256;             // 1024 chunks per array
                int r = q >> 3, c8 = (q & 7) * 8;
                uint32_t dst = sb + stage * F_STAGE + (2 + arr) * F_ARR
                             + (uint32_t)(r * FTS + c8) * 2;
                cp_async16(dst, src + (size_t)(n0 + r) * K + koff + c8);
            }
        }
        cp_commit();
    };
    auto compute = [&](int stage) {
        uint32_t aHb = sb + stage * F_STAGE;
        uint32_t aLb = aHb + F_ARR;
        uint32_t bHb = aHb + 2 * F_ARR;
        uint32_t bLb = aHb + 3 * F_ARR;
#pragma unroll
        for (int ks = 0; ks < 4; ks++) {
            uint32_t a_off = (uint32_t)(((mbase + (lane & 15)) * FTS
                              + ks * 16 + (lane >> 4) * 8) * 2);
            uint32_t aH[4][4], aL[4][4];
#pragma unroll
            for (int i = 0; i < 4; i++) {
                uint32_t o = a_off + (uint32_t)(i * 16 * FTS * 2);
                ldm_x4(aH[i][0], aH[i][1], aH[i][2], aH[i][3], aHb + o);
                ldm_x4(aL[i][0], aL[i][1], aL[i][2], aL[i][3], aLb + o);
            }
            uint32_t b_off = (uint32_t)(((nbase + (lane & 7) + (lane >> 4) * 8) * FTS
                              + ks * 16 + ((lane >> 3) & 1) * 8) * 2);
            uint32_t bH[4][2], bL[4][2];
#pragma unroll
            for (int jp = 0; jp < 2; jp++) {
                uint32_t o = b_off + (uint32_t)(jp * 16 * FTS * 2);
                ldm_x4(bH[jp*2][0], bH[jp*2][1], bH[jp*2+1][0], bH[jp*2+1][1], bHb + o);
                ldm_x4(bL[jp*2][0], bL[jp*2][1], bL[jp*2+1][0], bL[jp*2+1][1], bLb + o);
            }
#pragma unroll
            for (int i = 0; i < 4; i++)
#pragma unroll
                for (int j = 0; j < 4; j++) {
                    mma_bf16(acc[i * 4 + j], aH[i], bH[j]);
                    mma_bf16(acc[i * 4 + j], aH[i], bL[j]);
                    mma_bf16(acc[i * 4 + j], aL[i], bH[j]);
                }
        }
    };

    loadA(0);
    issueB(0, 0);
    if (NIT > 1) issueB(1, 1);
    for (int it = 0; it < NIT; it++) {
        int stage = it & 1;
        if (it >= NIT - 2) cp_wait<0>(); else cp_wait<1>();
        storeA(stage);
        __syncthreads();
        if (it + 1 < NIT) loadA(it + 1);
        compute(stage);
        __syncthreads();
        if (it + 2 < NIT) issueB(it + 2, stage);
    }

#pragma unroll
    for (int i = 0; i < 4; i++) {
        int row0 = m0 + mbase + i * 16 + (lane >> 2);
#pragma unroll
        for (int j = 0; j < 4; j++) {
            int col = n0 + nbase + j * 8 + (lane & 3) * 2;
            if (col >= N) continue;
            const float* c = acc[i * 4 + j];
#pragma unroll
            for (int hrow = 0; hrow < 2; hrow++) {
                int gm = row0 + hrow * 8;
                if (gm >= M) continue;
                float v0 = c[hrow * 2 + 0], v1 = c[hrow * 2 + 1];
                if (MODE == 0) {
                    float b0 = bias ? bias[col] : 0.f;
                    float b1 = bias ? bias[col + 1] : 0.f;
                    C[(size_t)gm * ldc + col]     = v0 + b0;
                    C[(size_t)gm * ldc + col + 1] = v1 + b1;
                } else {
                    __half h0 = __float2half_rn(v0), h1 = __float2half_rn(v1);
                    Chi[(size_t)gm * ldc + col]     = h0;
                    Chi[(size_t)gm * ldc + col + 1] = h1;
                    Clo[(size_t)gm * ldc + col]     =
                        __float2half_rn(v0 - __half2float(h0));
                    Clo[(size_t)gm * ldc + col + 1] =
                        __float2half_rn(v1 - __half2float(h1));
                }
            }
        }
    }
}

// ---------------------------------------------------------------------------
// PERSISTENT step loop (unchanged from R7).
#define PTS     72
#define P_AH    0
#define P_AL    9216
#define P_BH    18432
#define P_BL    23040
#define P_STAGE 27648
#define P_SMEM  (2 * P_STAGE)

__global__ void __launch_bounds__(512, 1)
step_loop_kernel(const float* __restrict__ h0,
                 const float* __restrict__ c0,
                 const __nv_bfloat16* __restrict__ uk0H,
                 const __nv_bfloat16* __restrict__ uk0L,
                 const __nv_bfloat16* __restrict__ wkuH,
                 const __nv_bfloat16* __restrict__ wkuL,
                 const float* __restrict__ zpre,
                 float* __restrict__ cbuf,
                 float* __restrict__ hctx,
                 const float* __restrict__ wqT,
                 const float* __restrict__ keys,
                 const float* __restrict__ memory,
                 const float* __restrict__ v_att)
{
    extern __shared__ char dsm[];
    const int cta  = blockIdx.x;
    const int tid  = threadIdx.x;
    const int wid  = tid >> 5, lane = tid & 31;
    const int wm   = wid & 3,  wn   = wid >> 2;
    const int mbase = wm * 16, nbase = wn * 8;
    const int n0   = cta * 32;
    const uint32_t sb = smem_u32(dsm);
    const int nCTA = gridDim.x;

    for (int t = 0; t < TOUT; t++) {
        const float* Aptr; int astride, K;
        const __nv_bfloat16 *BH, *BL;
        if (t == 0) { Aptr = h0; astride = UNITS; K = 512; BH = uk0H; BL = uk0L; }
        else { Aptr = hctx + (size_t)(t - 1) * 1024; astride = HLD; K = 1024;
               BH = wkuH; BL = wkuL; }
        const float* cprev = t ? (cbuf + (size_t)((t - 1) & 1) * B64 * UNITS) : c0;
        float* cnew = cbuf + (size_t)(t & 1) * B64 * UNITS;
        const int NIT = K >> 6;

        float acc[4] = {0.f, 0.f, 0.f, 0.f};
        float4 Areg[2];

        auto issueB = [&](int it, int stage) {
            int koff = it * 64;
            int arr = tid >> 8;
            int r   = (tid >> 3) & 31;
            int c8  = (tid & 7) * 8;
            const __nv_bfloat16* src = arr ? BL : BH;
            uint32_t dst = sb + stage * P_STAGE + (arr ? P_BL : P_BH)
                         + (uint32_t)(r * PTS + c8) * 2;
            cp_async16(dst, src + (size_t)(n0 + r) * K + koff + c8);
            cp_commit();
        };
        auto loadA = [&](int it) {
            int koff = it * 64;
#pragma unroll
            for (int l = 0; l < 2; l++) {
                int q = tid + l * 512;
                int r = q >> 4, c4 = (q & 15) * 4;
                Areg[l] = *(const float4*)(Aptr + (size_t)r * astride + koff + c4);
            }
        };
        auto storeA = [&](int stage) {
#pragma unroll
            for (int l = 0; l < 2; l++) {
                int q = tid + l * 512;
                int r = q >> 4, c4 = (q & 15) * 4;
                float4 v = Areg[l];
                uint32_t off = (uint32_t)(r * PTS + c4) * 2;
                uint2 hi = make_uint2(pack_bf2(v.x, v.y), pack_bf2(v.z, v.w));
                uint2 lo = make_uint2(pack_bf2(bf_res(v.x), bf_res(v.y)),
                                      pack_bf2(bf_res(v.z), bf_res(v.w)));
                *(uint2*)(dsm + stage * P_STAGE + P_AH + off) = hi;
                *(uint2*)(dsm + stage * P_STAGE + P_AL + off) = lo;
            }
        };
        auto compute = [&](int stage) {
            uint32_t aHb = sb + stage * P_STAGE + P_AH;
            uint32_t aLb = sb + stage * P_STAGE + P_AL;
            uint32_t bHb = sb + stage * P_STAGE + P_BH;
            uint32_t bLb = sb + stage * P_STAGE + P_BL;
#pragma unroll
            for (int ks = 0; ks < 4; ks++) {
                uint32_t a_off = (uint32_t)(((mbase + (lane & 15)) * PTS
                                  + ks * 16 + (lane >> 4) * 8) * 2);
                uint32_t aH[4], aL[4];
                ldm_x4(aH[0], aH[1], aH[2], aH[3], aHb + a_off);
                ldm_x4(aL[0], aL[1], aL[2], aL[3], aLb + a_off);
                uint32_t b_off = (uint32_t)(((nbase + (lane & 7)) * PTS
                                  + ks * 16 + ((lane >> 3) & 1) * 8) * 2);
                uint32_t bH[2], bL[2];
                ldm_x2(bH[0], bH[1], bHb + b_off);
                ldm_x2(bL[0], bL[1], bLb + b_off);
                mma_bf16(acc, aH, bH);
                mma_bf16(acc, aH, bL);
                mma_bf16(acc, aL, bH);
            }
        };

        loadA(0);
        issueB(0, 0);
        issueB(1, 1);
        for (int it = 0; it < NIT; it++) {
            int stage = it & 1;
            if (it >= NIT - 2) cp_wait<0>(); else cp_wait<1>();
            storeA(stage);
            __syncthreads();
            if (it + 1 < NIT) loadA(it + 1);
            compute(stage);
            __syncthreads();
            if (it + 2 < NIT) issueB(it + 2, stage);
        }

        float* zbuf = (float*)dsm;
        {
            int row = mbase + (lane >> 2);
            int col = nbase + (lane & 3) * 2;
            zbuf[row * 36 + col]           = acc[0];
            zbuf[row * 36 + col + 1]       = acc[1];
            zbuf[(row + 8) * 36 + col]     = acc[2];
            zbuf[(row + 8) * 36 + col + 1] = acc[3];
        }
        __syncthreads();
        {
            int b  = tid >> 3, ul = tid & 7;
            int u  = cta * 8 + ul;
            const float* ad = zpre + (size_t)t * B64 * 2048 + (size_t)b * 2048;
            float zi = zbuf[b * 36 + ul * 4 + 0] + ad[u];
            float zf = zbuf[b * 36 + ul * 4 + 1] + ad[512 + u];
            float zg = zbuf[b * 36 + ul * 4 + 2] + ad[1024 + u];
            float zo = zbuf[b * 36 + ul * 4 + 3] + ad[1536 + u];
            float si = fast_sigmoid(zi);
            float sf = fast_sigmoid(zf);
            float so = fast_sigmoid(zo);
            float tg = fast_tanh(zg);
            float c  = sf * cprev[(size_t)b * UNITS + u] + si * tg;
            float h  = so * fast_tanh(c);
            cnew[(size_t)b * UNITS + u] = c;
            hctx[(size_t)b * HLD + (size_t)t * 1024 + u] = h;
        }

        grid_barrier(nCTA);

        {
            int b = cta;
            float* sh  = (float*)dsm;
            float* sq  = sh + 512;
            float* ssc = sq + 512;
            float* hrow = hctx + (size_t)b * HLD + (size_t)t * 1024;

            sh[tid] = hrow[tid];
            __syncthreads();
            {
                float a = 0.f;
                const float* w = wqT + (size_t)tid * UNITS;
#pragma unroll 4
                for (int k = 0; k < UNITS; k += 4) {
                    float4 hv = *(const float4*)&sh[k];
                    float4 x  = *(const float4*)&w[k];
                    a = fmaf(hv.x, x.x, fmaf(hv.y, x.y,
                        fmaf(hv.z, x.z, fmaf(hv.w, x.w, a))));
                }
                sq[tid] = a;
            }
            __syncthreads();

            for (int s = wid; s < TIN; s += 16) {
                const float* krow = keys + ((size_t)b * TIN + s) * UNITS;
                float sc = 0.f;
                for (int u = lane; u < UNITS; u += 32)
                    sc += fast_tanh(krow[u] + sq[u]) * v_att[u];
#pragma unroll
                for (int off = 16; off; off >>= 1)
                    sc += __shfl_xor_sync(~0u, sc, off);
                if (lane == 0) ssc[s] = sc;
            }
            __syncthreads();

            if (tid < 32) {
                float m = -1e30f;
                for (int s = lane; s < TIN; s += 32) m = fmaxf(m, ssc[s]);
#pragma unroll
                for (int off = 16; off; off >>= 1)
                    m = fmaxf(m, __shfl_xor_sync(~0u, m, off));
                float ssum = 0.f;
                for (int s = lane; s < TIN; s += 32) {
                    float e = __expf(ssc[s] - m);
                    ssc[s] = e; ssum += e;
                }
#pragma unroll
                for (int off = 16; off; off >>= 1)
                    ssum += __shfl_xor_sync(~0u, ssum, off);
                float inv = __fdividef(1.f, ssum);
                for (int s = lane; s < TIN; s += 32) ssc[s] *= inv;
            }
            __syncthreads();

            const float* mrow = memory + (size_t)b * TIN * UNITS;
            float accc = 0.f;
#pragma unroll 4
            for (int s = 0; s < TIN; s++)
                accc = fmaf(ssc[s], mrow[(size_t)s * UNITS + tid], accc);
            hrow[512 + tid] = accc;
        }

        grid_barrier(nCTA);
    }
}

// ---------------------------------------------------------------------------
// Vocab GEMM: 2-term fp16. out[1984,34004] = (Ah+Al) @ Bh^T + bias.
#define V_ARR   (128 * FTS * 2)         // 18432 B
#define V_STAGE (3 * V_ARR)             // 55296 B
#define V_SMEM  (2 * V_STAGE)           // 110592 B

__global__ void __launch_bounds__(256)
gemm_vocab_f16(const __half* __restrict__ Ah,
               const __half* __restrict__ Al,
               const __half* __restrict__ Bh,
               const float* __restrict__ bias,
               float* __restrict__ out)
{
    extern __shared__ char dsm[];
    const int m0 = blockIdx.x * 128;
    const int n0 = blockIdx.y * 128;
    const int tid  = threadIdx.x;
    const int wid  = tid >> 5, lane = tid & 31;
    const int wm   = wid & 1,  wn   = wid >> 1;
    const int mbase = wm * 64, nbase = wn * 32;
    const uint32_t sb = smem_u32(dsm);

    float acc[16][4];
#pragma unroll
    for (int i = 0; i < 16; i++)
#pragma unroll
        for (int j = 0; j < 4; j++) acc[i][j] = 0.f;

    auto issue = [&](int it, int stage) {
        int koff = it * 64;
#pragma unroll
        for (int arr = 0; arr < 3; arr++) {
            const __half* src = (arr == 0) ? Ah : (arr == 1) ? Al : Bh;
            const int rbase = (arr < 2) ? m0 : n0;
#pragma unroll
            for (int l = 0; l < 4; l++) {
                int q = tid + l * 256;
                int r = q >> 3, c8 = (q & 7) * 8;
                uint32_t dst = sb + stage * V_STAGE + arr * V_ARR
                             + (uint32_t)(r * FTS + c8) * 2;
                cp_async16(dst, src + (size_t)(rbase + r) * UNITS + koff + c8);
            }
        }
        cp_commit();
    };
    auto compute = [&](int stage) {
        uint32_t aHb = sb + stage * V_STAGE;
        uint32_t aLb = aHb + V_ARR;
        uint32_t bHb = aHb + 2 * V_ARR;
#pragma unroll
        for (int ks = 0; ks < 4; ks++) {
            uint32_t a_off = (uint32_t)(((mbase + (lane & 15)) * FTS
                              + ks * 16 + (lane >> 4) * 8) * 2);
            uint32_t aH[4][4], aL[4][4];
#pragma unroll
            for (int i = 0; i < 4; i++) {
                uint32_t o = a_off + (uint32_t)(i * 16 * FTS * 2);
                ldm_x4(aH[i][0], aH[i][1], aH[i][2], aH[i][3], aHb + o);
                ldm_x4(aL[i][0], aL[i][1], aL[i][2], aL[i][3], aLb + o);
            }
            uint32_t b_off = (uint32_t)(((nbase + (lane & 7) + (lane >> 4) * 8) * FTS
                              + ks * 16 + ((lane >> 3) & 1) * 8) * 2);
            uint32_t bH[4][2];
#pragma unroll
            for (int jp = 0; jp < 2; jp++) {
                uint32_t o = b_off + (uint32_t)(jp * 16 * FTS * 2);
                ldm_x4(bH[jp*2][0], bH[jp*2][1], bH[jp*2+1][0], bH[jp*2+1][1], bHb + o);
            }
#pragma unroll
            for (int i = 0; i < 4; i++)
#pragma unroll
                for (int j = 0; j < 4; j++) {
                    mma_f16(acc[i * 4 + j], aH[i], bH[j]);
                    mma_f16(acc[i * 4 + j], aL[i], bH[j]);
                }
        }
    };

    issue(0, 0);
    issue(1, 1);
    for (int it = 0; it < 8; it++) {
        int stage = it & 1;
        if (it >= 6) cp_wait<0>(); else cp_wait<1>();
        __syncthreads();
        compute(stage);
        __syncthreads();
        if (it + 2 < 8) issue(it + 2, stage);
    }

#pragma unroll
    for (int i = 0; i < 4; i++) {
        int row0 = m0 + mbase + i * 16 + (lane >> 2);
#pragma unroll
        for (int j = 0; j < 4; j++) {
            int col = n0 + nbase + j * 8 + (lane & 3) * 2;
            if (col >= VOCAB) continue;
            float b0 = bias[col], b1 = bias[col + 1];
            const float* c = acc[i * 4 + j];
            if (row0 < ROWS) {
                out[(size_t)row0 * VOCAB + col]     = c[0] + b0;
                out[(size_t)row0 * VOCAB + col + 1] = c[1] + b1;
            }
            if (row0 + 8 < ROWS) {
                out[(size_t)(row0 + 8) * VOCAB + col]     = c[2] + b0;
                out[(size_t)(row0 + 8) * VOCAB + col + 1] = c[3] + b1;
            }
        }
    }
}

// ---------------------------------------------------------------------------
static inline float* sym_addr(const void* sym) {
    void* p = nullptr;
    cudaGetSymbolAddress(&p, sym);
    return (float*)p;
}
static inline __nv_bfloat16* sym_addr_bf(const void* sym) {
    void* p = nullptr;
    cudaGetSymbolAddress(&p, sym);
    return (__nv_bfloat16*)p;
}
static inline __half* sym_addr_h(const void* sym) {
    void* p = nullptr;
    cudaGetSymbolAddress(&p, sym);
    return (__half*)p;
}
#define DIVUP(a, b) (((a) + (b) - 1) / (b))

extern "C" void kernel_launch(void* const* d_in, const int* in_sizes, int n_in,
                              void* d_out, int out_size)
{
    const int*   dec = (const int*)  d_in[0];
    const float* h0  = (const float*)d_in[1];
    const float* c0  = (const float*)d_in[2];
    const float* mem = (const float*)d_in[3];
    const float* emb = (const float*)d_in[4];
    const float* Wk  = (const float*)d_in[5];
    const float* Uk  = (const float*)d_in[6];
    const float* bk  = (const float*)d_in[7];
    const float* Wm  = (const float*)d_in[8];
    const float* Wq  = (const float*)d_in[9];
    const float* vat = (const float*)d_in[10];
    const float* Wa  = (const float*)d_in[11];
    const float* Wfc = (const float*)d_in[12];
    const float* bfc = (const float*)d_in[13];
    float* out = (float*)d_out;

    float* keys   = sym_addr(g_keys);
    float* embA   = sym_addr(g_embA);
    float* zpre   = sym_addr(g_zpre);
    float* cbuf   = sym_addr(g_cbuf);
    float* hctx   = sym_addr(g_hctx);
    float* wqT    = sym_addr(g_wqT);
    float* wbig   = sym_addr(g_wbig);
    __half* sA_hi = sym_addr_h(g_sA_hi);
    __half* sA_lo = sym_addr_h(g_sA_lo);
    __half* wT_h  = sym_addr_h(g_wT_h);
    __nv_bfloat16* wkuH = sym_addr_bf(g_wkuH);
    __nv_bfloat16* wkuL = sym_addr_bf(g_wkuL);
    __nv_bfloat16* uk0H = sym_addr_bf(g_uk0H);
    __nv_bfloat16* uk0L = sym_addr_bf(g_uk0L);
    __nv_bfloat16* wmT_h  = sym_addr_bf(g_wmT_h);
    __nv_bfloat16* wmT_l  = sym_addr_bf(g_wmT_l);
    __nv_bfloat16* wk0T_h = sym_addr_bf(g_wk0T_h);
    __nv_bfloat16* wk0T_l = sym_addr_bf(g_wk0T_l);
    __nv_bfloat16* wkpT_h = sym_addr_bf(g_wkpT_h);
    __nv_bfloat16* wkpT_l = sym_addr_bf(g_wkpT_l);
    __nv_bfloat16* waT_h  = sym_addr_bf(g_waT_h);
    __nv_bfloat16* waT_l  = sym_addr_bf(g_waT_l);

    cudaFuncSetAttribute(gemm_mma_AF<0>,
                         cudaFuncAttributeMaxDynamicSharedMemorySize, F_SMEM);
    cudaFuncSetAttribute(gemm_mma_AF<1>,
                         cudaFuncAttributeMaxDynamicSharedMemorySize, F_SMEM);
    cudaFuncSetAttribute(step_loop_kernel,
                         cudaFuncAttributeMaxDynamicSharedMemorySize, P_SMEM);
    cudaFuncSetAttribute(gemm_vocab_f16,
                         cudaFuncAttributeMaxDynamicSharedMemorySize, V_SMEM);

    // ---- setup: converts ----
    gather_emb_kernel<<<ROWS, 128>>>(dec, emb, embA);
    tsplit_bf16_kernel<<<dim3(512 / 32, 512 / 32), 256>>>(
        Wm, 512, 512, 512, 512, wmT_h, wmT_l);
    tsplit_bf16_kernel<<<dim3(2048 / 32, EMBP / 32), 256>>>(
        Wk, EMB, 2048, 2048, EMBP, wk0T_h, wk0T_l);
    tsplit_bf16_kernel<<<dim3(2048 / 32, 512 / 32), 256>>>(
        Wk + (size_t)EMB * 2048, 512, 2048, 2048, 512, wkpT_h, wkpT_l);
    tsplit_bf16_kernel<<<dim3(512 / 32, 1024 / 32), 256>>>(
        Wa, 1024, 512, 512, 1024, waT_h, waT_l);
    convert_wfc_h_kernel<<<dim3(VPAD / 32, UNITS / 32), 256>>>(Wfc, wT_h);
    transpose_wq_kernel<<<dim3(16, 16), 256>>>(Wq, wqT);

    // ---- setup GEMMs on tensor cores ----
    // keys = memory @ Wm       [3840 x 512 x 512]
    gemm_mma_AF<0><<<dim3(30, 4), 256, F_SMEM>>>(
        mem, UNITS, B64 * TIN, UNITS, UNITS, wmT_h, wmT_l,
        nullptr, keys, UNITS, nullptr, nullptr);
    // zpre = embA @ Wk[0:300] + bk   [1984 x 2048 x 320]
    gemm_mma_AF<0><<<dim3(16, 16), 256, F_SMEM>>>(
        embA, EMBP, ROWS, 2048, EMBP, wk0T_h, wk0T_l,
        bk, zpre, 2048, nullptr, nullptr);
    // wbig = Wa @ Wk[300:812]  [1024 x 2048 x 512], then += [Uk;0]
    gemm_mma_AF<0><<<dim3(8, 16), 256, F_SMEM>>>(
        Wa, UNITS, 1024, 2048, UNITS, wkpT_h, wkpT_l,
        nullptr, wbig, 2048, nullptr, nullptr);
    add_uk_kernel<<<(512 * 2048) / 256, 256>>>(wbig, Uk);
    convert_gatesW_kernel<<<dim3(64, 32), 256>>>(wbig, 1024, wkuH, wkuL);
    convert_gatesW_kernel<<<dim3(64, 16), 256>>>(Uk, 512, uk0H, uk0L);

    // ---- persistent step loop ----
    step_loop_kernel<<<64, 512, P_SMEM>>>(
        h0, c0, uk0H, uk0L, wkuH, wkuL, zpre, cbuf, hctx,
        wqT, keys, mem, vat);

    // ---- states = hctx @ Wa -> fp16 hi/lo   [1984 x 512 x 1024]
    gemm_mma_AF<1><<<dim3(16, 4), 256, F_SMEM>>>(
        hctx, 1024, ROWS, UNITS, 1024, waT_h, waT_l,
        nullptr, nullptr, UNITS, sA_hi, sA_lo);

    // ---- vocab projection (2-term fp16) ----
    gemm_vocab_f16<<<dim3(MPAD / 128, VPAD / 128), 256, V_SMEM>>>(
        sA_hi, sA_lo, wT_h, bfc, out);
}

// round 9
// speedup vs baseline: 2.4297x; 1.1128x over previous
#include <cuda_runtime.h>
#include <cuda.h>
#include <cuda_bf16.h>
#include <cuda_fp16.h>
#include <math.h>
#include <stdint.h>

// ============================================================================
// Attention-LSTM decoder. B=64, T_out=31, T_in=60, U=512, EMB=300, VOCAB=34004.
// - setup GEMMs on tensor cores (split-bf16 3-term, fp32 A on the fly).
// - persistent step loop (128 CTA x 512 thr): gates split-bf16 mma
//   (tile 64x16, 3-stage cp.async) + LSTM -> barrier -> attention (CTAs 0..63)
//   -> barrier.
// - vocab projection: 1-term fp16 mma GEMM (A and B each rounded once;
//   predicted rel err ~3e-4 << 1e-3).
// ============================================================================

#define B64   64
#define TOUT  31
#define TIN   60
#define UNITS 512
#define EMB   300
#define EMBP  320
#define VOCAB 34004
#define ROWS  (B64 * TOUT)     // 1984
#define MPAD  2048
#define VPAD  34048            // 266 * 128
#define HLD   (TOUT * 1024)

// ---------------- scratch ----------------------------------------------------
__device__ float g_keys  [B64 * TIN * UNITS];
__device__ float g_embA  [ROWS * EMBP];
__device__ float g_zpre  [ROWS * 4 * UNITS];
__device__ float g_cbuf  [2][B64 * UNITS];
__device__ float g_hctx  [ROWS * 1024];
__device__ float g_wqT   [UNITS * UNITS];
__device__ float g_wbig  [1024 * 2048];
__device__ __align__(16) __half g_sA_h[MPAD * UNITS];            // pad rows stay 0
__device__ __align__(16) __half g_wT_h [(size_t)VPAD * UNITS];   // fp16 [n][k]
__device__ __align__(16) __nv_bfloat16 g_wkuH[2048 * 1024];
__device__ __align__(16) __nv_bfloat16 g_wkuL[2048 * 1024];
__device__ __align__(16) __nv_bfloat16 g_uk0H[2048 * 512];
__device__ __align__(16) __nv_bfloat16 g_uk0L[2048 * 512];
__device__ __align__(16) __nv_bfloat16 g_wmT_h [512 * 512];
__device__ __align__(16) __nv_bfloat16 g_wmT_l [512 * 512];
__device__ __align__(16) __nv_bfloat16 g_wk0T_h[2048 * EMBP];
__device__ __align__(16) __nv_bfloat16 g_wk0T_l[2048 * EMBP];
__device__ __align__(16) __nv_bfloat16 g_wkpT_h[2048 * 512];
__device__ __align__(16) __nv_bfloat16 g_wkpT_l[2048 * 512];
__device__ __align__(16) __nv_bfloat16 g_waT_h [512 * 1024];
__device__ __align__(16) __nv_bfloat16 g_waT_l [512 * 1024];

__device__ int g_bar_cnt = 0;
__device__ volatile unsigned g_bar_gen = 0;

// ---------------- PTX helpers -------------------------------------------------
__device__ __forceinline__ uint32_t smem_u32(const void* p) {
    uint32_t a;
    asm("{ .reg .u64 t; cvta.to.shared.u64 t, %1; cvt.u32.u64 %0, t; }" : "=r"(a) : "l"(p));
    return a;
}
__device__ __forceinline__ void ldm_x4(uint32_t& r0, uint32_t& r1, uint32_t& r2,
                                       uint32_t& r3, uint32_t addr) {
    asm volatile("ldmatrix.sync.aligned.m8n8.x4.shared.b16 {%0,%1,%2,%3}, [%4];"
                 : "=r"(r0), "=r"(r1), "=r"(r2), "=r"(r3) : "r"(addr));
}
__device__ __forceinline__ void ldm_x2(uint32_t& r0, uint32_t& r1, uint32_t addr) {
    asm volatile("ldmatrix.sync.aligned.m8n8.x2.shared.b16 {%0,%1}, [%2];"
                 : "=r"(r0), "=r"(r1) : "r"(addr));
}
__device__ __forceinline__ void mma_bf16(float* c, const uint32_t* a, const uint32_t* b) {
    asm volatile("mma.sync.aligned.m16n8k16.row.col.f32.bf16.bf16.f32 "
                 "{%0,%1,%2,%3}, {%4,%5,%6,%7}, {%8,%9}, {%0,%1,%2,%3};"
                 : "+f"(c[0]), "+f"(c[1]), "+f"(c[2]), "+f"(c[3])
                 : "r"(a[0]), "r"(a[1]), "r"(a[2]), "r"(a[3]), "r"(b[0]), "r"(b[1]));
}
__device__ __forceinline__ void mma_f16(float* c, const uint32_t* a, const uint32_t* b) {
    asm volatile("mma.sync.aligned.m16n8k16.row.col.f32.f16.f16.f32 "
                 "{%0,%1,%2,%3}, {%4,%5,%6,%7}, {%8,%9}, {%0,%1,%2,%3};"
                 : "+f"(c[0]), "+f"(c[1]), "+f"(c[2]), "+f"(c[3])
                 : "r"(a[0]), "r"(a[1]), "r"(a[2]), "r"(a[3]), "r"(b[0]), "r"(b[1]));
}
__device__ __forceinline__ void cp_async16(uint32_t dst, const void* src) {
    asm volatile("cp.async.cg.shared.global [%0], [%1], 16;" :: "r"(dst), "l"(src));
}
__device__ __forceinline__ void cp_commit() { asm volatile("cp.async.commit_group;"); }
template<int N> __device__ __forceinline__ void cp_wait() {
    asm volatile("cp.async.wait_group %0;" :: "n"(N));
}
__device__ __forceinline__ uint32_t pack_bf2(float a, float b) {
    __nv_bfloat162 t = __floats2bfloat162_rn(a, b);
    return *reinterpret_cast<uint32_t*>(&t);
}
__device__ __forceinline__ float bf_res(float a) {
    return a - __bfloat162float(__float2bfloat16(a));
}
__device__ __forceinline__ float fast_tanh(float x) {
    float e = __expf(2.f * x);
    return 1.f - __fdividef(2.f, e + 1.f);
}
__device__ __forceinline__ float fast_sigmoid(float x) {
    return __fdividef(1.f, 1.f + __expf(-x));
}
__device__ __forceinline__ void grid_barrier(int nCTA) {
    __syncthreads();
    if (threadIdx.x == 0) {
        unsigned gen = g_bar_gen;
        __threadfence();
        if (atomicAdd(&g_bar_cnt, 1) == nCTA - 1) {
            g_bar_cnt = 0;
            __threadfence();
            g_bar_gen = gen + 1;
        } else {
            while (g_bar_gen == gen) { }
        }
        __threadfence();
    }
    __syncthreads();
}

// ---------------------------------------------------------------------------
__global__ void gather_emb_kernel(const int* __restrict__ dec,
                                  const float* __restrict__ emb,
                                  float* __restrict__ out) {
    int r = blockIdx.x;          // r = t*64 + b
    int t = r >> 6, b = r & 63;
    int tok = dec[b * TOUT + t];
    const float* src = emb + (size_t)tok * EMB;
    float* dst = out + (size_t)r * EMBP;
    for (int e = threadIdx.x; e < EMBP; e += blockDim.x)
        dst[e] = (e < EMB) ? src[e] : 0.f;
}

// Generic transpose + split-bf16: W [K][N] (ld=ldn) -> hiT/loT [Npad][Kpad]
__global__ void tsplit_bf16_kernel(const float* __restrict__ W,
                                   int K, int N, int ldn, int Kpad,
                                   __nv_bfloat16* __restrict__ hiT,
                                   __nv_bfloat16* __restrict__ loT) {
    __shared__ float tile[32][33];
    int n0 = blockIdx.x * 32, k0 = blockIdx.y * 32;
    int tx = threadIdx.x & 31, ty = threadIdx.x >> 5;
    for (int j = ty; j < 32; j += 8) {
        int k = k0 + j, n = n0 + tx;
        tile[j][tx] = (k < K && n < N) ? W[(size_t)k * ldn + n] : 0.f;
    }
    __syncthreads();
    for (int j = ty; j < 32; j += 8) {
        int n = n0 + j, k = k0 + tx;
        float v = tile[tx][j];
        __nv_bfloat16 h = __float2bfloat16(v);
        hiT[(size_t)n * Kpad + k] = h;
        loT[(size_t)n * Kpad + k] = __float2bfloat16(v - __bfloat162float(h));
    }
}

// Wfc [512][34004] -> single fp16 [VPAD][512]
__global__ void convert_wfc_h_kernel(const float* __restrict__ W,
                                     __half* __restrict__ hT) {
    __shared__ float tile[32][33];
    int n0 = blockIdx.x * 32, k0 = blockIdx.y * 32;
    int tx = threadIdx.x & 31, ty = threadIdx.x >> 5;
    for (int j = ty; j < 32; j += 8) {
        int n = n0 + tx;
        tile[j][tx] = (n < VOCAB) ? W[(size_t)(k0 + j) * VOCAB + n] : 0.f;
    }
    __syncthreads();
    for (int j = ty; j < 32; j += 8) {
        int n = n0 + j, k = k0 + tx;
        hT[(size_t)n * UNITS + k] = __float2half_rn(tile[tx][j]);
    }
}

// W [K][2048] -> gate-interleaved split-bf16 [n'=(n&511)*4+(n>>9)][K]
__global__ void convert_gatesW_kernel(const float* __restrict__ W, int K,
                                      __nv_bfloat16* __restrict__ hi,
                                      __nv_bfloat16* __restrict__ lo) {
    __shared__ float tile[32][33];
    int n0 = blockIdx.x * 32, k0 = blockIdx.y * 32;
    int tx = threadIdx.x & 31, ty = threadIdx.x >> 5;
    for (int j = ty; j < 32; j += 8)
        tile[j][tx] = W[(size_t)(k0 + j) * 2048 + n0 + tx];
    __syncthreads();
    for (int j = ty; j < 32; j += 8) {
        int n = n0 + j, k = k0 + tx;
        int np = (n & 511) * 4 + (n >> 9);
        float v = tile[tx][j];
        __nv_bfloat16 h = __float2bfloat16(v);
        hi[(size_t)np * K + k] = h;
        lo[(size_t)np * K + k] = __float2bfloat16(v - __bfloat162float(h));
    }
}

__global__ void add_uk_kernel(float* __restrict__ wbig,
                              const float* __restrict__ Uk) {
    int i = blockIdx.x * 256 + threadIdx.x;
    if (i < 512 * 2048) wbig[i] += Uk[i];
}

__global__ void transpose_wq_kernel(const float* __restrict__ Wq,
                                    float* __restrict__ WqT) {
    __shared__ float tile[32][33];
    int n0 = blockIdx.x * 32, k0 = blockIdx.y * 32;
    int tx = threadIdx.x & 31, ty = threadIdx.x >> 5;
    for (int j = ty; j < 32; j += 8)
        tile[j][tx] = Wq[(size_t)(k0 + j) * UNITS + n0 + tx];
    __syncthreads();
    for (int j = ty; j < 32; j += 8)
        WqT[(size_t)(n0 + j) * UNITS + k0 + tx] = tile[tx][j];
}

// ---------------------------------------------------------------------------
// Generic split-bf16 3-term mma GEMM with fp32 A (converted on the fly).
// MODE 0: fp32 C (+bias).  MODE 1: fp16 (single rounding) output.
#define FTS     72
#define F_ARR   (128 * FTS * 2)        // 18432 B
#define F_STAGE (4 * F_ARR)            // 73728 B
#define F_SMEM  (2 * F_STAGE)          // 147456 B

template<int MODE>
__global__ void __launch_bounds__(256)
gemm_mma_AF(const float* __restrict__ A, int lda, int M, int N, int K,
            const __nv_bfloat16* __restrict__ BhT,
            const __nv_bfloat16* __restrict__ BlT,
            const float* __restrict__ bias,
            float* __restrict__ C, int ldc,
            __half* __restrict__ Ch)
{
    extern __shared__ char dsm[];
    const int m0 = blockIdx.x * 128;
    const int n0 = blockIdx.y * 128;
    const int tid  = threadIdx.x;
    const int wid  = tid >> 5, lane = tid & 31;
    const int wm   = wid & 1,  wn   = wid >> 1;
    const int mbase = wm * 64, nbase = wn * 32;
    const uint32_t sb = smem_u32(dsm);
    const int NIT = K >> 6;

    float acc[16][4];
#pragma unroll
    for (int i = 0; i < 16; i++)
#pragma unroll
        for (int j = 0; j < 4; j++) acc[i][j] = 0.f;

    float4 Areg[8];
    auto loadA = [&](int it) {
        int koff = it * 64;
#pragma unroll
        for (int l = 0; l < 8; l++) {
            int q = tid + l * 256;
            int r = q >> 4, c4 = (q & 15) * 4;
            int gm = m0 + r;
            Areg[l] = (gm < M) ? *(const float4*)(A + (size_t)gm * lda + koff + c4)
                               : make_float4(0.f, 0.f, 0.f, 0.f);
        }
    };
    auto storeA = [&](int stage) {
#pragma unroll
        for (int l = 0; l < 8; l++) {
            int q = tid + l * 256;
            int r = q >> 4, c4 = (q & 15) * 4;
            float4 v = Areg[l];
            uint32_t off = (uint32_t)(r * FTS + c4) * 2;
            uint2 hi = make_uint2(pack_bf2(v.x, v.y), pack_bf2(v.z, v.w));
            uint2 lo = make_uint2(pack_bf2(bf_res(v.x), bf_res(v.y)),
                                  pack_bf2(bf_res(v.z), bf_res(v.w)));
            *(uint2*)(dsm + stage * F_STAGE + 0 * F_ARR + off) = hi;
            *(uint2*)(dsm + stage * F_STAGE + 1 * F_ARR + off) = lo;
        }
    };
    auto issueB = [&](int it, int stage) {
        int koff = it * 64;
#pragma unroll
        for (int arr = 0; arr < 2; arr++) {
            const __nv_bfloat16* src = arr ? BlT : BhT;
#pragma unroll
            for (int l = 0; l < 4; l++) {
                int q = tid + l * 256;
                int r = q >> 3, c8 = (q & 7) * 8;
                uint32_t dst = sb + stage * F_STAGE + (2 + arr) * F_ARR
                             + (uint32_t)(r * FTS + c8) * 2;
                cp_async16(dst, src + (size_t)(n0 + r) * K + koff + c8);
            }
        }
        cp_commit();
    };
    auto compute = [&](int stage) {
        uint32_t aHb = sb + stage * F_STAGE;
        uint32_t aLb = aHb + F_ARR;
        uint32_t bHb = aHb + 2 * F_ARR;
        uint32_t bLb = aHb + 3 * F_ARR;
#pragma unroll
        for (int ks = 0; ks < 4; ks++) {
            uint32_t a_off = (uint32_t)(((mbase + (lane & 15)) * FTS
                              + ks * 16 + (lane >> 4) * 8) * 2);
            uint32_t aH[4][4], aL[4][4];
#pragma unroll
            for (int i = 0; i < 4; i++) {
                uint32_t o = a_off + (uint32_t)(i * 16 * FTS * 2);
                ldm_x4(aH[i][0], aH[i][1], aH[i][2], aH[i][3], aHb + o);
                ldm_x4(aL[i][0], aL[i][1], aL[i][2], aL[i][3], aLb + o);
            }
            uint32_t b_off = (uint32_t)(((nbase + (lane & 7) + (lane >> 4) * 8) * FTS
                              + ks * 16 + ((lane >> 3) & 1) * 8) * 2);
            uint32_t bH[4][2], bL[4][2];
#pragma unroll
            for (int jp = 0; jp < 2; jp++) {
                uint32_t o = b_off + (uint32_t)(jp * 16 * FTS * 2);
                ldm_x4(bH[jp*2][0], bH[jp*2][1], bH[jp*2+1][0], bH[jp*2+1][1], bHb + o);
                ldm_x4(bL[jp*2][0], bL[jp*2][1], bL[jp*2+1][0], bL[jp*2+1][1], bLb + o);
            }
#pragma unroll
            for (int i = 0; i < 4; i++)
#pragma unroll
                for (int j = 0; j < 4; j++) {
                    mma_bf16(acc[i * 4 + j], aH[i], bH[j]);
                    mma_bf16(acc[i * 4 + j], aH[i], bL[j]);
                    mma_bf16(acc[i * 4 + j], aL[i], bH[j]);
                }
        }
    };

    loadA(0);
    issueB(0, 0);
    if (NIT > 1) issueB(1, 1);
    for (int it = 0; it < NIT; it++) {
        int stage = it & 1;
        if (it >= NIT - 2) cp_wait<0>(); else cp_wait<1>();
        storeA(stage);
        __syncthreads();
        if (it + 1 < NIT) loadA(it + 1);
        compute(stage);
        __syncthreads();
        if (it + 2 < NIT) issueB(it + 2, stage);
    }

#pragma unroll
    for (int i = 0; i < 4; i++) {
        int row0 = m0 + mbase + i * 16 + (lane >> 2);
#pragma unroll
        for (int j = 0; j < 4; j++) {
            int col = n0 + nbase + j * 8 + (lane & 3) * 2;
            if (col >= N) continue;
            const float* c = acc[i * 4 + j];
#pragma unroll
            for (int hrow = 0; hrow < 2; hrow++) {
                int gm = row0 + hrow * 8;
                if (gm >= M) continue;
                float v0 = c[hrow * 2 + 0], v1 = c[hrow * 2 + 1];
                if (MODE == 0) {
                    float b0 = bias ? bias[col] : 0.f;
                    float b1 = bias ? bias[col + 1] : 0.f;
                    C[(size_t)gm * ldc + col]     = v0 + b0;
                    C[(size_t)gm * ldc + col + 1] = v1 + b1;
                } else {
                    Ch[(size_t)gm * ldc + col]     = __float2half_rn(v0);
                    Ch[(size_t)gm * ldc + col + 1] = __float2half_rn(v1);
                }
            }
        }
    }
}

// ---------------------------------------------------------------------------
// PERSISTENT step loop: 128 CTAs x 512 threads.
// Gates: CTA cta -> n' = cta*16..+15 (tile 64m x 16n', BK=64, 3-stage
// cp.async, 8 mma warps of 16x8, split-bf16 3-term). Fused LSTM.
// Attention: CTAs 0..63, one per batch.
#define PTS     72
#define P_AH    0
#define P_AL    9216
#define P_BH    18432
#define P_BL    20736
#define P_STAGE 23040
#define P_SMEM  (3 * P_STAGE)    // 69120 B

__global__ void __launch_bounds__(512, 1)
step_loop_kernel(const float* __restrict__ h0,
                 const float* __restrict__ c0,
                 const __nv_bfloat16* __restrict__ uk0H,
                 const __nv_bfloat16* __restrict__ uk0L,
                 const __nv_bfloat16* __restrict__ wkuH,
                 const __nv_bfloat16* __restrict__ wkuL,
                 const float* __restrict__ zpre,
                 float* __restrict__ cbuf,
                 float* __restrict__ hctx,
                 const float* __restrict__ wqT,
                 const float* __restrict__ keys,
                 const float* __restrict__ memory,
                 const float* __restrict__ v_att)
{
    extern __shared__ char dsm[];
    const int cta  = blockIdx.x;              // 0..127
    const int tid  = threadIdx.x;
    const int wid  = tid >> 5, lane = tid & 31;
    const int mbase = (wid & 3) * 16;          // mma warps: wid < 8
    const int nbase = (wid >> 2) * 8;          // 0 or 8 (valid for wid<8)
    const int n0   = cta * 16;
    const uint32_t sb = smem_u32(dsm);
    const int nCTA = gridDim.x;

    for (int t = 0; t < TOUT; t++) {
        // ================= gates phase =================
        const float* Aptr; int astride, K;
        const __nv_bfloat16 *BH, *BL;
        if (t == 0) { Aptr = h0; astride = UNITS; K = 512; BH = uk0H; BL = uk0L; }
        else { Aptr = hctx + (size_t)(t - 1) * 1024; astride = HLD; K = 1024;
               BH = wkuH; BL = wkuL; }
        const float* cprev = t ? (cbuf + (size_t)((t - 1) & 1) * B64 * UNITS) : c0;
        float* cnew = cbuf + (size_t)(t & 1) * B64 * UNITS;
        const int NIT = K >> 6;

        float acc[4] = {0.f, 0.f, 0.f, 0.f};
        float4 Areg[2];

        auto issueB = [&](int it, int stage) {
            int koff = it * 64;
            if (tid < 256) {       // 256 x 16B = 4KB (hi 2KB + lo 2KB)
                int arr = tid >> 7;
                int rem = tid & 127;
                int r   = rem >> 3;
                int c8  = (rem & 7) * 8;
                const __nv_bfloat16* src = arr ? BL : BH;
                uint32_t dst = sb + stage * P_STAGE + (arr ? P_BL : P_BH)
                             + (uint32_t)(r * PTS + c8) * 2;
                cp_async16(dst, src + (size_t)(n0 + r) * K + koff + c8);
            }
            cp_commit();
        };
        auto loadA = [&](int it) {
            int koff = it * 64;
#pragma unroll
            for (int l = 0; l < 2; l++) {
                int q = tid + l * 512;
                int r = q >> 4, c4 = (q & 15) * 4;
                Areg[l] = *(const float4*)(Aptr + (size_t)r * astride + koff + c4);
            }
        };
        auto storeA = [&](int stage) {
#pragma unroll
            for (int l = 0; l < 2; l++) {
                int q = tid + l * 512;
                int r = q >> 4, c4 = (q & 15) * 4;
                float4 v = Areg[l];
                uint32_t off = (uint32_t)(r * PTS + c4) * 2;
                uint2 hi = make_uint2(pack_bf2(v.x, v.y), pack_bf2(v.z, v.w));
                uint2 lo = make_uint2(pack_bf2(bf_res(v.x), bf_res(v.y)),
                                      pack_bf2(bf_res(v.z), bf_res(v.w)));
                *(uint2*)(dsm + stage * P_STAGE + P_AH + off) = hi;
                *(uint2*)(dsm + stage * P_STAGE + P_AL + off) = lo;
            }
        };
        auto compute = [&](int stage) {
            uint32_t aHb = sb + stage * P_STAGE + P_AH;
            uint32_t aLb = sb + stage * P_STAGE + P_AL;
            uint32_t bHb = sb + stage * P_STAGE + P_BH;
            uint32_t bLb = sb + stage * P_STAGE + P_BL;
#pragma unroll
            for (int ks = 0; ks < 4; ks++) {
                uint32_t a_off = (uint32_t)(((mbase + (lane & 15)) * PTS
                                  + ks * 16 + (lane >> 4) * 8) * 2);
                uint32_t aH[4], aL[4];
                ldm_x4(aH[0], aH[1], aH[2], aH[3], aHb + a_off);
                ldm_x4(aL[0], aL[1], aL[2], aL[3], aLb + a_off);
                uint32_t b_off = (uint32_t)(((nbase + (lane & 7)) * PTS
                                  + ks * 16 + ((lane >> 3) & 1) * 8) * 2);
                uint32_t bH[2], bL[2];
                ldm_x2(bH[0], bH[1], bHb + b_off);
                ldm_x2(bL[0], bL[1], bLb + b_off);
                mma_bf16(acc, aH, bH);
                mma_bf16(acc, aH, bL);
                mma_bf16(acc, aL, bH);
            }
        };

        loadA(0);
        issueB(0, 0);
        issueB(1, 1);
        issueB(2, 2);
        for (int it = 0; it < NIT; it++) {
            int stage = it % 3;
            if (it + 3 <= NIT)      cp_wait<2>();
            else if (it + 2 == NIT) cp_wait<1>();
            else                    cp_wait<0>();
            storeA(stage);
            __syncthreads();
            if (it + 1 < NIT) loadA(it + 1);
            if (wid < 8) compute(stage);
            __syncthreads();
            if (it + 3 < NIT) issueB(it + 3, stage);
        }

        // ---- LSTM epilogue ----
        float* zbuf = (float*)dsm;               // [64][20]
        if (wid < 8) {
            int row = mbase + (lane >> 2);
            int col = nbase + (lane & 3) * 2;
            zbuf[row * 20 + col]           = acc[0];
            zbuf[row * 20 + col + 1]       = acc[1];
            zbuf[(row + 8) * 20 + col]     = acc[2];
            zbuf[(row + 8) * 20 + col + 1] = acc[3];
        }
        __syncthreads();
        if (tid < 256) {
            int b  = tid >> 2, ul = tid & 3;      // 64 b x 4 u
            int u  = cta * 4 + ul;
            const float* ad = zpre + (size_t)t * B64 * 2048 + (size_t)b * 2048;
            float zi = zbuf[b * 20 + ul * 4 + 0] + ad[u];
            float zf = zbuf[b * 20 + ul * 4 + 1] + ad[512 + u];
            float zg = zbuf[b * 20 + ul * 4 + 2] + ad[1024 + u];
            float zo = zbuf[b * 20 + ul * 4 + 3] + ad[1536 + u];
            float si = fast_sigmoid(zi);
            float sf = fast_sigmoid(zf);
            float so = fast_sigmoid(zo);
            float tg = fast_tanh(zg);
            float c  = sf * cprev[(size_t)b * UNITS + u] + si * tg;
            float h  = so * fast_tanh(c);
            cnew[(size_t)b * UNITS + u] = c;
            hctx[(size_t)b * HLD + (size_t)t * 1024 + u] = h;
        }

        grid_barrier(nCTA);

        // ================= attention phase (CTAs 0..63) =================
        if (cta < B64) {
            int b = cta;
            float* sh  = (float*)dsm;
            float* sq  = sh + 512;
            float* ssc = sq + 512;
            float* hrow = hctx + (size_t)b * HLD + (size_t)t * 1024;

            sh[tid] = hrow[tid];
            __syncthreads();
            {
                float a = 0.f;
                const float* w = wqT + (size_t)tid * UNITS;
#pragma unroll 4
                for (int k = 0; k < UNITS; k += 4) {
                    float4 hv = *(const float4*)&sh[k];
                    float4 x  = *(const float4*)&w[k];
                    a = fmaf(hv.x, x.x, fmaf(hv.y, x.y,
                        fmaf(hv.z, x.z, fmaf(hv.w, x.w, a))));
                }
                sq[tid] = a;
            }
            __syncthreads();

            for (int s = wid; s < TIN; s += 16) {
                const float* krow = keys + ((size_t)b * TIN + s) * UNITS;
                float sc = 0.f;
                for (int u = lane; u < UNITS; u += 32)
                    sc += fast_tanh(krow[u] + sq[u]) * v_att[u];
#pragma unroll
                for (int off = 16; off; off >>= 1)
                    sc += __shfl_xor_sync(~0u, sc, off);
                if (lane == 0) ssc[s] = sc;
            }
            __syncthreads();

            if (tid < 32) {
                float m = -1e30f;
                for (int s = lane; s < TIN; s += 32) m = fmaxf(m, ssc[s]);
#pragma unroll
                for (int off = 16; off; off >>= 1)
                    m = fmaxf(m, __shfl_xor_sync(~0u, m, off));
                float ssum = 0.f;
                for (int s = lane; s < TIN; s += 32) {
                    float e = __expf(ssc[s] - m);
                    ssc[s] = e; ssum += e;
                }
#pragma unroll
                for (int off = 16; off; off >>= 1)
                    ssum += __shfl_xor_sync(~0u, ssum, off);
                float inv = __fdividef(1.f, ssum);
                for (int s = lane; s < TIN; s += 32) ssc[s] *= inv;
            }
            __syncthreads();

            const float* mrow = memory + (size_t)b * TIN * UNITS;
            float accc = 0.f;
#pragma unroll 4
            for (int s = 0; s < TIN; s++)
                accc = fmaf(ssc[s], mrow[(size_t)s * UNITS + tid], accc);
            hrow[512 + tid] = accc;
        }

        grid_barrier(nCTA);
    }
}

// ---------------------------------------------------------------------------
// Vocab GEMM: 1-term fp16. out[1984,34004] = Ah @ Bh^T + bias.
#define V_ARR   (128 * FTS * 2)         // 18432 B
#define V_STAGE (2 * V_ARR)             // 36864 B
#define V_SMEM  (2 * V_STAGE)           // 73728 B

__global__ void __launch_bounds__(256)
gemm_vocab_f16(const __half* __restrict__ Ah,
               const __half* __restrict__ Bh,
               const float* __restrict__ bias,
               float* __restrict__ out)
{
    extern __shared__ char dsm[];
    const int m0 = blockIdx.x * 128;
    const int n0 = blockIdx.y * 128;
    const int tid  = threadIdx.x;
    const int wid  = tid >> 5, lane = tid & 31;
    const int wm   = wid & 1,  wn   = wid >> 1;
    const int mbase = wm * 64, nbase = wn * 32;
    const uint32_t sb = smem_u32(dsm);

    float acc[16][4];
#pragma unroll
    for (int i = 0; i < 16; i++)
#pragma unroll
        for (int j = 0; j < 4; j++) acc[i][j] = 0.f;

    auto issue = [&](int it, int stage) {
        int koff = it * 64;
#pragma unroll
        for (int arr = 0; arr < 2; arr++) {
            const __half* src = arr ? Bh : Ah;
            const int rbase = arr ? n0 : m0;
#pragma unroll
            for (int l = 0; l < 4; l++) {
                int q = tid + l * 256;
                int r = q >> 3, c8 = (q & 7) * 8;
                uint32_t dst = sb + stage * V_STAGE + arr * V_ARR
                             + (uint32_t)(r * FTS + c8) * 2;
                cp_async16(dst, src + (size_t)(rbase + r) * UNITS + koff + c8);
            }
        }
        cp_commit();
    };
    auto compute = [&](int stage) {
        uint32_t aHb = sb + stage * V_STAGE;
        uint32_t bHb = aHb + V_ARR;
#pragma unroll
        for (int ks = 0; ks < 4; ks++) {
            uint32_t a_off = (uint32_t)(((mbase + (lane & 15)) * FTS
                              + ks * 16 + (lane >> 4) * 8) * 2);
            uint32_t aH[4][4];
#pragma unroll
            for (int i = 0; i < 4; i++) {
                uint32_t o = a_off + (uint32_t)(i * 16 * FTS * 2);
                ldm_x4(aH[i][0], aH[i][1], aH[i][2], aH[i][3], aHb + o);
            }
            uint32_t b_off = (uint32_t)(((nbase + (lane & 7) + (lane >> 4) * 8) * FTS
                              + ks * 16 + ((lane >> 3) & 1) * 8) * 2);
            uint32_t bH[4][2];
#pragma unroll
            for (int jp = 0; jp < 2; jp++) {
                uint32_t o = b_off + (uint32_t)(jp * 16 * FTS * 2);
                ldm_x4(bH[jp*2][0], bH[jp*2][1], bH[jp*2+1][0], bH[jp*2+1][1], bHb + o);
            }
#pragma unroll
            for (int i = 0; i < 4; i++)
#pragma unroll
                for (int j = 0; j < 4; j++)
                    mma_f16(acc[i * 4 + j], aH[i], bH[j]);
        }
    };

    issue(0, 0);
    issue(1, 1);
    for (int it = 0; it < 8; it++) {
        int stage = it & 1;
        if (it >= 6) cp_wait<0>(); else cp_wait<1>();
        __syncthreads();
        compute(stage);
        __syncthreads();
        if (it + 2 < 8) issue(it + 2, stage);
    }

#pragma unroll
    for (int i = 0; i < 4; i++) {
        int row0 = m0 + mbase + i * 16 + (lane >> 2);
#pragma unroll
        for (int j = 0; j < 4; j++) {
            int col = n0 + nbase + j * 8 + (lane & 3) * 2;
            if (col >= VOCAB) continue;
            float b0 = bias[col], b1 = bias[col + 1];
            const float* c = acc[i * 4 + j];
            if (row0 < ROWS) {
                out[(size_t)row0 * VOCAB + col]     = c[0] + b0;
                out[(size_t)row0 * VOCAB + col + 1] = c[1] + b1;
            }
            if (row0 + 8 < ROWS) {
                out[(size_t)(row0 + 8) * VOCAB + col]     = c[2] + b0;
                out[(size_t)(row0 + 8) * VOCAB + col + 1] = c[3] + b1;
            }
        }
    }
}

// ---------------------------------------------------------------------------
static inline float* sym_addr(const void* sym) {
    void* p = nullptr;
    cudaGetSymbolAddress(&p, sym);
    return (float*)p;
}
static inline __nv_bfloat16* sym_addr_bf(const void* sym) {
    void* p = nullptr;
    cudaGetSymbolAddress(&p, sym);
    return (__nv_bfloat16*)p;
}
static inline __half* sym_addr_h(const void* sym) {
    void* p = nullptr;
    cudaGetSymbolAddress(&p, sym);
    return (__half*)p;
}
#define DIVUP(a, b) (((a) + (b) - 1) / (b))

extern "C" void kernel_launch(void* const* d_in, const int* in_sizes, int n_in,
                              void* d_out, int out_size)
{
    const int*   dec = (const int*)  d_in[0];
    const float* h0  = (const float*)d_in[1];
    const float* c0  = (const float*)d_in[2];
    const float* mem = (const float*)d_in[3];
    const float* emb = (const float*)d_in[4];
    const float* Wk  = (const float*)d_in[5];
    const float* Uk  = (const float*)d_in[6];
    const float* bk  = (const float*)d_in[7];
    const float* Wm  = (const float*)d_in[8];
    const float* Wq  = (const float*)d_in[9];
    const float* vat = (const float*)d_in[10];
    const float* Wa  = (const float*)d_in[11];
    const float* Wfc = (const float*)d_in[12];
    const float* bfc = (const float*)d_in[13];
    float* out = (float*)d_out;

    float* keys   = sym_addr(g_keys);
    float* embA   = sym_addr(g_embA);
    float* zpre   = sym_addr(g_zpre);
    float* cbuf   = sym_addr(g_cbuf);
    float* hctx   = sym_addr(g_hctx);
    float* wqT    = sym_addr(g_wqT);
    float* wbig   = sym_addr(g_wbig);
    __half* sA_h  = sym_addr_h(g_sA_h);
    __half* wT_h  = sym_addr_h(g_wT_h);
    __nv_bfloat16* wkuH = sym_addr_bf(g_wkuH);
    __nv_bfloat16* wkuL = sym_addr_bf(g_wkuL);
    __nv_bfloat16* uk0H = sym_addr_bf(g_uk0H);
    __nv_bfloat16* uk0L = sym_addr_bf(g_uk0L);
    __nv_bfloat16* wmT_h  = sym_addr_bf(g_wmT_h);
    __nv_bfloat16* wmT_l  = sym_addr_bf(g_wmT_l);
    __nv_bfloat16* wk0T_h = sym_addr_bf(g_wk0T_h);
    __nv_bfloat16* wk0T_l = sym_addr_bf(g_wk0T_l);
    __nv_bfloat16* wkpT_h = sym_addr_bf(g_wkpT_h);
    __nv_bfloat16* wkpT_l = sym_addr_bf(g_wkpT_l);
    __nv_bfloat16* waT_h  = sym_addr_bf(g_waT_h);
    __nv_bfloat16* waT_l  = sym_addr_bf(g_waT_l);

    cudaFuncSetAttribute(gemm_mma_AF<0>,
                         cudaFuncAttributeMaxDynamicSharedMemorySize, F_SMEM);
    cudaFuncSetAttribute(gemm_mma_AF<1>,
                         cudaFuncAttributeMaxDynamicSharedMemorySize, F_SMEM);
    cudaFuncSetAttribute(step_loop_kernel,
                         cudaFuncAttributeMaxDynamicSharedMemorySize, P_SMEM);
    cudaFuncSetAttribute(gemm_vocab_f16,
                         cudaFuncAttributeMaxDynamicSharedMemorySize, V_SMEM);

    // ---- setup: converts ----
    gather_emb_kernel<<<ROWS, 128>>>(dec, emb, embA);
    tsplit_bf16_kernel<<<dim3(512 / 32, 512 / 32), 256>>>(
        Wm, 512, 512, 512, 512, wmT_h, wmT_l);
    tsplit_bf16_kernel<<<dim3(2048 / 32, EMBP / 32), 256>>>(
        Wk, EMB, 2048, 2048, EMBP, wk0T_h, wk0T_l);
    tsplit_bf16_kernel<<<dim3(2048 / 32, 512 / 32), 256>>>(
        Wk + (size_t)EMB * 2048, 512, 2048, 2048, 512, wkpT_h, wkpT_l);
    tsplit_bf16_kernel<<<dim3(512 / 32, 1024 / 32), 256>>>(
        Wa, 1024, 512, 512, 1024, waT_h, waT_l);
    convert_wfc_h_kernel<<<dim3(VPAD / 32, UNITS / 32), 256>>>(Wfc, wT_h);
    transpose_wq_kernel<<<dim3(16, 16), 256>>>(Wq, wqT);

    // ---- setup GEMMs on tensor cores ----
    gemm_mma_AF<0><<<dim3(30, 4), 256, F_SMEM>>>(
        mem, UNITS, B64 * TIN, UNITS, UNITS, wmT_h, wmT_l,
        nullptr, keys, UNITS, nullptr);
    gemm_mma_AF<0><<<dim3(16, 16), 256, F_SMEM>>>(
        embA, EMBP, ROWS, 2048, EMBP, wk0T_h, wk0T_l,
        bk, zpre, 2048, nullptr);
    gemm_mma_AF<0><<<dim3(8, 16), 256, F_SMEM>>>(
        Wa, UNITS, 1024, 2048, UNITS, wkpT_h, wkpT_l,
        nullptr, wbig, 2048, nullptr);
    add_uk_kernel<<<(512 * 2048) / 256, 256>>>(wbig, Uk);
    convert_gatesW_kernel<<<dim3(64, 32), 256>>>(wbig, 1024, wkuH, wkuL);
    convert_gatesW_kernel<<<dim3(64, 16), 256>>>(Uk, 512, uk0H, uk0L);

    // ---- persistent step loop (128 CTAs) ----
    step_loop_kernel<<<128, 512, P_SMEM>>>(
        h0, c0, uk0H, uk0L, wkuH, wkuL, zpre, cbuf, hctx,
        wqT, keys, mem, vat);

    // ---- states = hctx @ Wa -> fp16   [1984 x 512 x 1024]
    gemm_mma_AF<1><<<dim3(16, 4), 256, F_SMEM>>>(
        hctx, 1024, ROWS, UNITS, 1024, waT_h, waT_l,
        nullptr, nullptr, UNITS, sA_h);

    // ---- vocab projection (1-term fp16) ----
    gemm_vocab_f16<<<dim3(MPAD / 128, VPAD / 128), 256, V_SMEM>>>(
        sA_h, wT_h, bfc, out);
}

// round 10
// speedup vs baseline: 3.1638x; 1.3022x over previous
#include <cuda_runtime.h>
#include <cuda.h>
#include <cuda_bf16.h>
#include <cuda_fp16.h>
#include <math.h>
#include <stdint.h>

// ============================================================================
// Attention-LSTM decoder. B=64, T_out=31, T_in=60, U=512, EMB=300, VOCAB=34004.
// Launch order (ncu captures app launch #4):
//   1 gather_emb   2 mega_convert (all pre-loop transposes/splits)
//   3 gemm3 (keys + zpre + wbig[fused +Uk + gate-interleave epilogue])
//   4 step_loop (PERSISTENT, 128 CTAs: gates mma + LSTM | attention)  <- ncu
//   5 post_convert (Wa split + Wfc fp16)   6 states GEMM   7 vocab GEMM
// ============================================================================

#define B64   64
#define TOUT  31
#define TIN   60
#define UNITS 512
#define EMB   300
#define EMBP  320
#define VOCAB 34004
#define ROWS  (B64 * TOUT)     // 1984
#define MPAD  2048
#define VPAD  34048            // 266 * 128
#define HLD   (TOUT * 1024)

// ---------------- scratch ----------------------------------------------------
__device__ float g_keys  [B64 * TIN * UNITS];
__device__ float g_embA  [ROWS * EMBP];
__device__ float g_zpre  [ROWS * 4 * UNITS];
__device__ float g_cbuf  [2][B64 * UNITS];
__device__ float g_hctx  [ROWS * 1024];
__device__ __align__(16) __half g_wqTh [UNITS * UNITS];          // fp16 [n][k]
__device__ __align__(16) __half g_sA_h[MPAD * UNITS];            // pad rows stay 0
__device__ __align__(16) __half g_wT_h [(size_t)VPAD * UNITS];   // fp16 [n][k]
__device__ __align__(16) __nv_bfloat16 g_wkuH[2048 * 1024];      // [n'][k]
__device__ __align__(16) __nv_bfloat16 g_wkuL[2048 * 1024];
__device__ __align__(16) __nv_bfloat16 g_uk0H[2048 * 512];
__device__ __align__(16) __nv_bfloat16 g_uk0L[2048 * 512];
__device__ __align__(16) __nv_bfloat16 g_wmT_h [512 * 512];
__device__ __align__(16) __nv_bfloat16 g_wmT_l [512 * 512];
__device__ __align__(16) __nv_bfloat16 g_wk0T_h[2048 * EMBP];
__device__ __align__(16) __nv_bfloat16 g_wk0T_l[2048 * EMBP];
__device__ __align__(16) __nv_bfloat16 g_wkpT_h[2048 * 512];
__device__ __align__(16) __nv_bfloat16 g_wkpT_l[2048 * 512];
__device__ __align__(16) __nv_bfloat16 g_waT_h [512 * 1024];
__device__ __align__(16) __nv_bfloat16 g_waT_l [512 * 1024];

__device__ int g_bar_cnt = 0;
__device__ volatile unsigned g_bar_gen = 0;

// ---------------- PTX helpers -------------------------------------------------
__device__ __forceinline__ uint32_t smem_u32(const void* p) {
    uint32_t a;
    asm("{ .reg .u64 t; cvta.to.shared.u64 t, %1; cvt.u32.u64 %0, t; }" : "=r"(a) : "l"(p));
    return a;
}
__device__ __forceinline__ void ldm_x4(uint32_t& r0, uint32_t& r1, uint32_t& r2,
                                       uint32_t& r3, uint32_t addr) {
    asm volatile("ldmatrix.sync.aligned.m8n8.x4.shared.b16 {%0,%1,%2,%3}, [%4];"
                 : "=r"(r0), "=r"(r1), "=r"(r2), "=r"(r3) : "r"(addr));
}
__device__ __forceinline__ void ldm_x2(uint32_t& r0, uint32_t& r1, uint32_t addr) {
    asm volatile("ldmatrix.sync.aligned.m8n8.x2.shared.b16 {%0,%1}, [%2];"
                 : "=r"(r0), "=r"(r1) : "r"(addr));
}
__device__ __forceinline__ void mma_bf16(float* c, const uint32_t* a, const uint32_t* b) {
    asm volatile("mma.sync.aligned.m16n8k16.row.col.f32.bf16.bf16.f32 "
                 "{%0,%1,%2,%3}, {%4,%5,%6,%7}, {%8,%9}, {%0,%1,%2,%3};"
                 : "+f"(c[0]), "+f"(c[1]), "+f"(c[2]), "+f"(c[3])
                 : "r"(a[0]), "r"(a[1]), "r"(a[2]), "r"(a[3]), "r"(b[0]), "r"(b[1]));
}
__device__ __forceinline__ void mma_f16(float* c, const uint32_t* a, const uint32_t* b) {
    asm volatile("mma.sync.aligned.m16n8k16.row.col.f32.f16.f16.f32 "
                 "{%0,%1,%2,%3}, {%4,%5,%6,%7}, {%8,%9}, {%0,%1,%2,%3};"
                 : "+f"(c[0]), "+f"(c[1]), "+f"(c[2]), "+f"(c[3])
                 : "r"(a[0]), "r"(a[1]), "r"(a[2]), "r"(a[3]), "r"(b[0]), "r"(b[1]));
}
__device__ __forceinline__ void cp_async16(uint32_t dst, const void* src) {
    asm volatile("cp.async.cg.shared.global [%0], [%1], 16;" :: "r"(dst), "l"(src));
}
__device__ __forceinline__ void cp_commit() { asm volatile("cp.async.commit_group;"); }
template<int N> __device__ __forceinline__ void cp_wait() {
    asm volatile("cp.async.wait_group %0;" :: "n"(N));
}
__device__ __forceinline__ uint32_t pack_bf2(float a, float b) {
    __nv_bfloat162 t = __floats2bfloat162_rn(a, b);
    return *reinterpret_cast<uint32_t*>(&t);
}
__device__ __forceinline__ float bf_res(float a) {
    return a - __bfloat162float(__float2bfloat16(a));
}
__device__ __forceinline__ float fast_tanh(float x) {
    float e = __expf(2.f * x);
    return 1.f - __fdividef(2.f, e + 1.f);
}
__device__ __forceinline__ float fast_sigmoid(float x) {
    return __fdividef(1.f, 1.f + __expf(-x));
}
__device__ __forceinline__ void grid_barrier(int nCTA) {
    __syncthreads();
    if (threadIdx.x == 0) {
        unsigned gen = g_bar_gen;
        __threadfence();
        if (atomicAdd(&g_bar_cnt, 1) == nCTA - 1) {
            g_bar_cnt = 0;
            __threadfence();
            g_bar_gen = gen + 1;
        } else {
            while (g_bar_gen == gen) { }
        }
        __threadfence();
    }
    __syncthreads();
}

// ---------------------------------------------------------------------------
__global__ void gather_emb_kernel(const int* __restrict__ dec,
                                  const float* __restrict__ emb,
                                  float* __restrict__ out) {
    int r = blockIdx.x;          // r = t*64 + b
    int t = r >> 6, b = r & 63;
    int tok = dec[b * TOUT + t];
    const float* src = emb + (size_t)tok * EMB;
    float* dst = out + (size_t)r * EMBP;
    for (int e = threadIdx.x; e < EMBP; e += blockDim.x)
        dst[e] = (e < EMB) ? src[e] : 0.f;
}

// ---------------------------------------------------------------------------
// mega_convert: all pre-loop transposes in one launch (dispatch by blockIdx).
//  P0 [0,256)     : Wm -> wmT hi/lo           (K=512,  N=512,  Kpad=512)
//  P1 [256,896)   : Wk[0:300] -> wk0T hi/lo   (K=300,  N=2048, Kpad=320)
//  P2 [896,1920)  : Wk[300:812] -> wkpT hi/lo (K=512,  N=2048, Kpad=512)
//  P3 [1920,2176) : Wq -> wqTh fp16           (K=512,  N=512)
//  P4 [2176,3200) : Uk -> uk0 gate-interleaved hi/lo (K=512, N=2048, Kpad=512)
__global__ void mega_convert_kernel(const float* __restrict__ Wm,
                                    const float* __restrict__ Wk,
                                    const float* __restrict__ Uk,
                                    const float* __restrict__ Wq,
                                    __nv_bfloat16* __restrict__ wmT_h,
                                    __nv_bfloat16* __restrict__ wmT_l,
                                    __nv_bfloat16* __restrict__ wk0T_h,
                                    __nv_bfloat16* __restrict__ wk0T_l,
                                    __nv_bfloat16* __restrict__ wkpT_h,
                                    __nv_bfloat16* __restrict__ wkpT_l,
                                    __half* __restrict__ wqTh,
                                    __nv_bfloat16* __restrict__ uk0H,
                                    __nv_bfloat16* __restrict__ uk0L)
{
    __shared__ float tile[32][33];
    int bid = blockIdx.x;
    const float* W; int K, N, ldn, Kpad, mode, n0, k0;
    __nv_bfloat16 *hi = nullptr, *lo = nullptr;

    if (bid < 256) {                 // P0
        int i = bid; W = Wm; K = 512; N = 512; ldn = 512; Kpad = 512; mode = 0;
        hi = wmT_h; lo = wmT_l; n0 = (i % 16) * 32; k0 = (i / 16) * 32;
    } else if (bid < 896) {          // P1
        int i = bid - 256; W = Wk; K = EMB; N = 2048; ldn = 2048; Kpad = EMBP; mode = 0;
        hi = wk0T_h; lo = wk0T_l; n0 = (i % 64) * 32; k0 = (i / 64) * 32;
    } else if (bid < 1920) {         // P2
        int i = bid - 896; W = Wk + (size_t)EMB * 2048; K = 512; N = 2048;
        ldn = 2048; Kpad = 512; mode = 0;
        hi = wkpT_h; lo = wkpT_l; n0 = (i % 64) * 32; k0 = (i / 64) * 32;
    } else if (bid < 2176) {         // P3
        int i = bid - 1920; W = Wq; K = 512; N = 512; ldn = 512; Kpad = 512; mode = 1;
        n0 = (i % 16) * 32; k0 = (i / 16) * 32;
    } else {                         // P4
        int i = bid - 2176; W = Uk; K = 512; N = 2048; ldn = 2048; Kpad = 512; mode = 2;
        hi = uk0H; lo = uk0L; n0 = (i % 64) * 32; k0 = (i / 64) * 32;
    }

    int tx = threadIdx.x & 31, ty = threadIdx.x >> 5;
    for (int j = ty; j < 32; j += 8) {
        int k = k0 + j, n = n0 + tx;
        tile[j][tx] = (k < K && n < N) ? W[(size_t)k * ldn + n] : 0.f;
    }
    __syncthreads();
    for (int j = ty; j < 32; j += 8) {
        int n = n0 + j, k = k0 + tx;
        float v = tile[tx][j];
        if (mode == 1) {
            wqTh[(size_t)n * 512 + k] = __float2half_rn(v);
        } else {
            int nn = (mode == 2) ? ((n & 511) * 4 + (n >> 9)) : n;
            __nv_bfloat16 h = __float2bfloat16(v);
            hi[(size_t)nn * Kpad + k] = h;
            lo[(size_t)nn * Kpad + k] = __float2bfloat16(v - __bfloat162float(h));
        }
    }
}

// post_convert: Wa split (pre-states) + Wfc fp16 (pre-vocab)
__global__ void post_convert_kernel(const float* __restrict__ Wa,
                                    const float* __restrict__ Wfc,
                                    __nv_bfloat16* __restrict__ waT_h,
                                    __nv_bfloat16* __restrict__ waT_l,
                                    __half* __restrict__ wT_h)
{
    __shared__ float tile[32][33];
    int bid = blockIdx.x;
    int tx = threadIdx.x & 31, ty = threadIdx.x >> 5;
    if (bid < 512) {                 // Wa: K=1024, N=512
        int n0 = (bid % 16) * 32, k0 = (bid / 16) * 32;
        for (int j = ty; j < 32; j += 8)
            tile[j][tx] = Wa[(size_t)(k0 + j) * 512 + n0 + tx];
        __syncthreads();
        for (int j = ty; j < 32; j += 8) {
            int n = n0 + j, k = k0 + tx;
            float v = tile[tx][j];
            __nv_bfloat16 h = __float2bfloat16(v);
            waT_h[(size_t)n * 1024 + k] = h;
            waT_l[(size_t)n * 1024 + k] = __float2bfloat16(v - __bfloat162float(h));
        }
    } else {                         // Wfc: K=512, N=34004 -> fp16 [VPAD][512]
        int i = bid - 512;
        int n0 = (i % 1064) * 32, k0 = (i / 1064) * 32;
        for (int j = ty; j < 32; j += 8) {
            int n = n0 + tx;
            tile[j][tx] = (n < VOCAB) ? Wfc[(size_t)(k0 + j) * VOCAB + n] : 0.f;
        }
        __syncthreads();
        for (int j = ty; j < 32; j += 8)
            wT_h[(size_t)(n0 + j) * UNITS + k0 + tx] = __float2half_rn(tile[tx][j]);
    }
}

// ---------------------------------------------------------------------------
// Core split-bf16 3-term mma GEMM (fp32 A on the fly, pre-split B).
// MODE 0: fp32 C (+bias[n]).  MODE 1: fp16 out.
// MODE 3: wbig special — add Uk (rows<512), write gate-interleaved split-bf16.
#define FTS     72
#define F_ARR   (128 * FTS * 2)        // 18432 B
#define F_STAGE (4 * F_ARR)            // 73728 B
#define F_SMEM  (2 * F_STAGE)          // 147456 B

template<int MODE>
__device__ __forceinline__ void gemm_core(
    char* dsm, int m0, int n0,
    const float* __restrict__ A, int lda, int M, int N, int K,
    const __nv_bfloat16* __restrict__ BhT,
    const __nv_bfloat16* __restrict__ BlT,
    const float* __restrict__ bias,         // MODE0: bias[n]; MODE3: Uk
    float* __restrict__ C, int ldc,
    __half* __restrict__ Ch,
    __nv_bfloat16* __restrict__ OH, __nv_bfloat16* __restrict__ OL)
{
    const int tid  = threadIdx.x;
    const int wid  = tid >> 5, lane = tid & 31;
    const int wm   = wid & 1,  wn   = wid >> 1;
    const int mbase = wm * 64, nbase = wn * 32;
    const uint32_t sb = smem_u32(dsm);
    const int NIT = K >> 6;

    float acc[16][4];
#pragma unroll
    for (int i = 0; i < 16; i++)
#pragma unroll
        for (int j = 0; j < 4; j++) acc[i][j] = 0.f;

    float4 Areg[8];
    auto loadA = [&](int it) {
        int koff = it * 64;
#pragma unroll
        for (int l = 0; l < 8; l++) {
            int q = tid + l * 256;
            int r = q >> 4, c4 = (q & 15) * 4;
            int gm = m0 + r;
            Areg[l] = (gm < M) ? *(const float4*)(A + (size_t)gm * lda + koff + c4)
                               : make_float4(0.f, 0.f, 0.f, 0.f);
        }
    };
    auto storeA = [&](int stage) {
#pragma unroll
        for (int l = 0; l < 8; l++) {
            int q = tid + l * 256;
            int r = q >> 4, c4 = (q & 15) * 4;
            float4 v = Areg[l];
            uint32_t off = (uint32_t)(r * FTS + c4) * 2;
            uint2 hi = make_uint2(pack_bf2(v.x, v.y), pack_bf2(v.z, v.w));
            uint2 lo = make_uint2(pack_bf2(bf_res(v.x), bf_res(v.y)),
                                  pack_bf2(bf_res(v.z), bf_res(v.w)));
            *(uint2*)(dsm + stage * F_STAGE + 0 * F_ARR + off) = hi;
            *(uint2*)(dsm + stage * F_STAGE + 1 * F_ARR + off) = lo;
        }
    };
    auto issueB = [&](int it, int stage) {
        int koff = it * 64;
#pragma unroll
        for (int arr = 0; arr < 2; arr++) {
            const __nv_bfloat16* src = arr ? BlT : BhT;
#pragma unroll
            for (int l = 0; l < 4; l++) {
                int q = tid + l * 256;
                int r = q >> 3, c8 = (q & 7) * 8;
                uint32_t dst = sb + stage * F_STAGE + (2 + arr) * F_ARR
                             + (uint32_t)(r * FTS + c8) * 2;
                cp_async16(dst, src + (size_t)(n0 + r) * K + koff + c8);
            }
        }
        cp_commit();
    };
    auto compute = [&](int stage) {
        uint32_t aHb = sb + stage * F_STAGE;
        uint32_t aLb = aHb + F_ARR;
        uint32_t bHb = aHb + 2 * F_ARR;
        uint32_t bLb = aHb + 3 * F_ARR;
#pragma unroll
        for (int ks = 0; ks < 4; ks++) {
            uint32_t a_off = (uint32_t)(((mbase + (lane & 15)) * FTS
                              + ks * 16 + (lane >> 4) * 8) * 2);
            uint32_t aH[4][4], aL[4][4];
#pragma unroll
            for (int i = 0; i < 4; i++) {
                uint32_t o = a_off + (uint32_t)(i * 16 * FTS * 2);
                ldm_x4(aH[i][0], aH[i][1], aH[i][2], aH[i][3], aHb + o);
                ldm_x4(aL[i][0], aL[i][1], aL[i][2], aL[i][3], aLb + o);
            }
            uint32_t b_off = (uint32_t)(((nbase + (lane & 7) + (lane >> 4) * 8) * FTS
                              + ks * 16 + ((lane >> 3) & 1) * 8) * 2);
            uint32_t bH[4][2], bL[4][2];
#pragma unroll
            for (int jp = 0; jp < 2; jp++) {
                uint32_t o = b_off + (uint32_t)(jp * 16 * FTS * 2);
                ldm_x4(bH[jp*2][0], bH[jp*2][1], bH[jp*2+1][0], bH[jp*2+1][1], bHb + o);
                ldm_x4(bL[jp*2][0], bL[jp*2][1], bL[jp*2+1][0], bL[jp*2+1][1], bLb + o);
            }
#pragma unroll
            for (int i = 0; i < 4; i++)
#pragma unroll
                for (int j = 0; j < 4; j++) {
                    mma_bf16(acc[i * 4 + j], aH[i], bH[j]);
                    mma_bf16(acc[i * 4 + j], aH[i], bL[j]);
                    mma_bf16(acc[i * 4 + j], aL[i], bH[j]);
                }
        }
    };

    loadA(0);
    issueB(0, 0);
    if (NIT > 1) issueB(1, 1);
    for (int it = 0; it < NIT; it++) {
        int stage = it & 1;
        if (it >= NIT - 2) cp_wait<0>(); else cp_wait<1>();
        storeA(stage);
        __syncthreads();
        if (it + 1 < NIT) loadA(it + 1);
        compute(stage);
        __syncthreads();
        if (it + 2 < NIT) issueB(it + 2, stage);
    }

#pragma unroll
    for (int i = 0; i < 4; i++) {
        int row0 = m0 + mbase + i * 16 + (lane >> 2);
#pragma unroll
        for (int j = 0; j < 4; j++) {
            int col = n0 + nbase + j * 8 + (lane & 3) * 2;
            if (col >= N) continue;
            const float* c = acc[i * 4 + j];
#pragma unroll
            for (int hrow = 0; hrow < 2; hrow++) {
                int gm = row0 + hrow * 8;
                if (gm >= M) continue;
                float v0 = c[hrow * 2 + 0], v1 = c[hrow * 2 + 1];
                if (MODE == 0) {
                    float b0 = bias ? bias[col] : 0.f;
                    float b1 = bias ? bias[col + 1] : 0.f;
                    C[(size_t)gm * ldc + col]     = v0 + b0;
                    C[(size_t)gm * ldc + col + 1] = v1 + b1;
                } else if (MODE == 1) {
                    Ch[(size_t)gm * ldc + col]     = __float2half_rn(v0);
                    Ch[(size_t)gm * ldc + col + 1] = __float2half_rn(v1);
                } else {   // MODE 3: +Uk (rows<512), gate-interleave split-bf16
                    if (gm < 512) {
                        v0 += bias[(size_t)gm * 2048 + col];
                        v1 += bias[(size_t)gm * 2048 + col + 1];
                    }
                    int np0 = (col & 511) * 4 + (col >> 9);
                    int np1 = ((col + 1) & 511) * 4 + ((col + 1) >> 9);
                    __nv_bfloat16 h0 = __float2bfloat16(v0);
                    __nv_bfloat16 h1 = __float2bfloat16(v1);
                    OH[(size_t)np0 * 1024 + gm] = h0;
                    OL[(size_t)np0 * 1024 + gm] =
                        __float2bfloat16(v0 - __bfloat162float(h0));
                    OH[(size_t)np1 * 1024 + gm] = h1;
                    OL[(size_t)np1 * 1024 + gm] =
                        __float2bfloat16(v1 - __bfloat162float(h1));
                }
            }
        }
    }
}

// gemm3: keys (120 blocks) + zpre (256) + wbig (128) in one launch.
__global__ void __launch_bounds__(256)
gemm3_kernel(const float* __restrict__ mem,
             const __nv_bfloat16* __restrict__ wmT_h,
             const __nv_bfloat16* __restrict__ wmT_l,
             float* __restrict__ keys,
             const float* __restrict__ embA,
             const __nv_bfloat16* __restrict__ wk0T_h,
             const __nv_bfloat16* __restrict__ wk0T_l,
             const float* __restrict__ bk,
             float* __restrict__ zpre,
             const float* __restrict__ Wa,
             const __nv_bfloat16* __restrict__ wkpT_h,
             const __nv_bfloat16* __restrict__ wkpT_l,
             const float* __restrict__ Uk,
             __nv_bfloat16* __restrict__ wkuH,
             __nv_bfloat16* __restrict__ wkuL)
{
    extern __shared__ char dsm[];
    int bid = blockIdx.x;
    if (bid < 120) {            // keys = memory @ Wm  [3840 x 512 x 512]
        int m0 = (bid % 30) * 128, n0 = (bid / 30) * 128;
        gemm_core<0>(dsm, m0, n0, mem, UNITS, B64 * TIN, UNITS, UNITS,
                     wmT_h, wmT_l, nullptr, keys, UNITS, nullptr,
                     nullptr, nullptr);
    } else if (bid < 376) {     // zpre = embA @ Wk0 + bk  [1984 x 2048 x 320]
        int p = bid - 120;
        int m0 = (p % 16) * 128, n0 = (p / 16) * 128;
        gemm_core<0>(dsm, m0, n0, embA, EMBP, ROWS, 2048, EMBP,
                     wk0T_h, wk0T_l, bk, zpre, 2048, nullptr,
                     nullptr, nullptr);
    } else {                    // wbig = Wa@Wk' (+Uk) -> wku interleaved
        int p = bid - 376;
        int m0 = (p % 8) * 128, n0 = (p / 8) * 128;
        gemm_core<3>(dsm, m0, n0, Wa, UNITS, 1024, 2048, UNITS,
                     wkpT_h, wkpT_l, Uk, nullptr, 0, nullptr,
                     wkuH, wkuL);
    }
}

// states GEMM wrapper (MODE 1 fp16 out)
__global__ void __launch_bounds__(256)
gemm_states_kernel(const float* __restrict__ hctx,
                   const __nv_bfloat16* __restrict__ waT_h,
                   const __nv_bfloat16* __restrict__ waT_l,
                   __half* __restrict__ sA_h)
{
    extern __shared__ char dsm[];
    int m0 = blockIdx.x * 128, n0 = blockIdx.y * 128;
    gemm_core<1>(dsm, m0, n0, hctx, 1024, ROWS, UNITS, 1024,
                 waT_h, waT_l, nullptr, nullptr, UNITS, sA_h,
                 nullptr, nullptr);
}

// ---------------------------------------------------------------------------
// PERSISTENT step loop: 128 CTAs x 512 threads (unchanged structure from R9;
// Wq now fp16).
#define PTS     72
#define P_AH    0
#define P_AL    9216
#define P_BH    18432
#define P_BL    20736
#define P_STAGE 23040
#define P_SMEM  (3 * P_STAGE)    // 69120 B

__global__ void __launch_bounds__(512, 1)
step_loop_kernel(const float* __restrict__ h0,
                 const float* __restrict__ c0,
                 const __nv_bfloat16* __restrict__ uk0H,
                 const __nv_bfloat16* __restrict__ uk0L,
                 const __nv_bfloat16* __restrict__ wkuH,
                 const __nv_bfloat16* __restrict__ wkuL,
                 const float* __restrict__ zpre,
                 float* __restrict__ cbuf,
                 float* __restrict__ hctx,
                 const __half* __restrict__ wqTh,
                 const float* __restrict__ keys,
                 const float* __restrict__ memory,
                 const float* __restrict__ v_att)
{
    extern __shared__ char dsm[];
    const int cta  = blockIdx.x;              // 0..127
    const int tid  = threadIdx.x;
    const int wid  = tid >> 5, lane = tid & 31;
    const int mbase = (wid & 3) * 16;
    const int nbase = (wid >> 2) * 8;
    const int n0   = cta * 16;
    const uint32_t sb = smem_u32(dsm);
    const int nCTA = gridDim.x;

    for (int t = 0; t < TOUT; t++) {
        // ================= gates phase =================
        const float* Aptr; int astride, K;
        const __nv_bfloat16 *BH, *BL;
        if (t == 0) { Aptr = h0; astride = UNITS; K = 512; BH = uk0H; BL = uk0L; }
        else { Aptr = hctx + (size_t)(t - 1) * 1024; astride = HLD; K = 1024;
               BH = wkuH; BL = wkuL; }
        const float* cprev = t ? (cbuf + (size_t)((t - 1) & 1) * B64 * UNITS) : c0;
        float* cnew = cbuf + (size_t)(t & 1) * B64 * UNITS;
        const int NIT = K >> 6;

        float acc[4] = {0.f, 0.f, 0.f, 0.f};
        float4 Areg[2];

        auto issueB = [&](int it, int stage) {
            int koff = it * 64;
            if (tid < 256) {
                int arr = tid >> 7;
                int rem = tid & 127;
                int r   = rem >> 3;
                int c8  = (rem & 7) * 8;
                const __nv_bfloat16* src = arr ? BL : BH;
                uint32_t dst = sb + stage * P_STAGE + (arr ? P_BL : P_BH)
                             + (uint32_t)(r * PTS + c8) * 2;
                cp_async16(dst, src + (size_t)(n0 + r) * K + koff + c8);
            }
            cp_commit();
        };
        auto loadA = [&](int it) {
            int koff = it * 64;
#pragma unroll
            for (int l = 0; l < 2; l++) {
                int q = tid + l * 512;
                int r = q >> 4, c4 = (q & 15) * 4;
                Areg[l] = *(const float4*)(Aptr + (size_t)r * astride + koff + c4);
            }
        };
        auto storeA = [&](int stage) {
#pragma unroll
            for (int l = 0; l < 2; l++) {
                int q = tid + l * 512;
                int r = q >> 4, c4 = (q & 15) * 4;
                float4 v = Areg[l];
                uint32_t off = (uint32_t)(r * PTS + c4) * 2;
                uint2 hi = make_uint2(pack_bf2(v.x, v.y), pack_bf2(v.z, v.w));
                uint2 lo = make_uint2(pack_bf2(bf_res(v.x), bf_res(v.y)),
                                      pack_bf2(bf_res(v.z), bf_res(v.w)));
                *(uint2*)(dsm + stage * P_STAGE + P_AH + off) = hi;
                *(uint2*)(dsm + stage * P_STAGE + P_AL + off) = lo;
            }
        };
        auto compute = [&](int stage) {
            uint32_t aHb = sb + stage * P_STAGE + P_AH;
            uint32_t aLb = sb + stage * P_STAGE + P_AL;
            uint32_t bHb = sb + stage * P_STAGE + P_BH;
            uint32_t bLb = sb + stage * P_STAGE + P_BL;
#pragma unroll
            for (int ks = 0; ks < 4; ks++) {
                uint32_t a_off = (uint32_t)(((mbase + (lane & 15)) * PTS
                                  + ks * 16 + (lane >> 4) * 8) * 2);
                uint32_t aH[4], aL[4];
                ldm_x4(aH[0], aH[1], aH[2], aH[3], aHb + a_off);
                ldm_x4(aL[0], aL[1], aL[2], aL[3], aLb + a_off);
                uint32_t b_off = (uint32_t)(((nbase + (lane & 7)) * PTS
                                  + ks * 16 + ((lane >> 3) & 1) * 8) * 2);
                uint32_t bH[2], bL[2];
                ldm_x2(bH[0], bH[1], bHb + b_off);
                ldm_x2(bL[0], bL[1], bLb + b_off);
                mma_bf16(acc, aH, bH);
                mma_bf16(acc, aH, bL);
                mma_bf16(acc, aL, bH);
            }
        };

        loadA(0);
        issueB(0, 0);
        issueB(1, 1);
        issueB(2, 2);
        for (int it = 0; it < NIT; it++) {
            int stage = it % 3;
            if (it + 3 <= NIT)      cp_wait<2>();
            else if (it + 2 == NIT) cp_wait<1>();
            else                    cp_wait<0>();
            storeA(stage);
            __syncthreads();
            if (it + 1 < NIT) loadA(it + 1);
            if (wid < 8) compute(stage);
            __syncthreads();
            if (it + 3 < NIT) issueB(it + 3, stage);
        }

        // ---- LSTM epilogue ----
        float* zbuf = (float*)dsm;               // [64][20]
        if (wid < 8) {
            int row = mbase + (lane >> 2);
            int col = nbase + (lane & 3) * 2;
            zbuf[row * 20 + col]           = acc[0];
            zbuf[row * 20 + col + 1]       = acc[1];
            zbuf[(row + 8) * 20 + col]     = acc[2];
            zbuf[(row + 8) * 20 + col + 1] = acc[3];
        }
        __syncthreads();
        if (tid < 256) {
            int b  = tid >> 2, ul = tid & 3;      // 64 b x 4 u
            int u  = cta * 4 + ul;
            const float* ad = zpre + (size_t)t * B64 * 2048 + (size_t)b * 2048;
            float zi = zbuf[b * 20 + ul * 4 + 0] + ad[u];
            float zf = zbuf[b * 20 + ul * 4 + 1] + ad[512 + u];
            float zg = zbuf[b * 20 + ul * 4 + 2] + ad[1024 + u];
            float zo = zbuf[b * 20 + ul * 4 + 3] + ad[1536 + u];
            float si = fast_sigmoid(zi);
            float sf = fast_sigmoid(zf);
            float so = fast_sigmoid(zo);
            float tg = fast_tanh(zg);
            float c  = sf * cprev[(size_t)b * UNITS + u] + si * tg;
            float h  = so * fast_tanh(c);
            cnew[(size_t)b * UNITS + u] = c;
            hctx[(size_t)b * HLD + (size_t)t * 1024 + u] = h;
        }

        grid_barrier(nCTA);

        // ================= attention phase (CTAs 0..63) =================
        if (cta < B64) {
            int b = cta;
            float* sh  = (float*)dsm;
            float* sq  = sh + 512;
            float* ssc = sq + 512;
            float* hrow = hctx + (size_t)b * HLD + (size_t)t * 1024;

            sh[tid] = hrow[tid];
            __syncthreads();
            {   // q[n] = sum_k h[k] * Wq[k][n]  (fp16 weights, fp32 accum)
                float a = 0.f;
                const __half* w = wqTh + (size_t)tid * UNITS;
#pragma unroll 4
                for (int k = 0; k < UNITS; k += 8) {
                    float4 hv0 = *(const float4*)&sh[k];
                    float4 hv1 = *(const float4*)&sh[k + 4];
                    uint4 raw = *(const uint4*)&w[k];
                    __half2 p0 = *(__half2*)&raw.x, p1 = *(__half2*)&raw.y;
                    __half2 p2 = *(__half2*)&raw.z, p3 = *(__half2*)&raw.w;
                    float2 f0 = __half22float2(p0), f1 = __half22float2(p1);
                    float2 f2 = __half22float2(p2), f3 = __half22float2(p3);
                    a = fmaf(hv0.x, f0.x, fmaf(hv0.y, f0.y,
                        fmaf(hv0.z, f1.x, fmaf(hv0.w, f1.y, a))));
                    a = fmaf(hv1.x, f2.x, fmaf(hv1.y, f2.y,
                        fmaf(hv1.z, f3.x, fmaf(hv1.w, f3.y, a))));
                }
                sq[tid] = a;
            }
            __syncthreads();

            for (int s = wid; s < TIN; s += 16) {
                const float* krow = keys + ((size_t)b * TIN + s) * UNITS;
                float sc = 0.f;
                for (int u = lane; u < UNITS; u += 32)
                    sc += fast_tanh(krow[u] + sq[u]) * v_att[u];
#pragma unroll
                for (int off = 16; off; off >>= 1)
                    sc += __shfl_xor_sync(~0u, sc, off);
                if (lane == 0) ssc[s] = sc;
            }
            __syncthreads();

            if (tid < 32) {
                float m = -1e30f;
                for (int s = lane; s < TIN; s += 32) m = fmaxf(m, ssc[s]);
#pragma unroll
                for (int off = 16; off; off >>= 1)
                    m = fmaxf(m, __shfl_xor_sync(~0u, m, off));
                float ssum = 0.f;
                for (int s = lane; s < TIN; s += 32) {
                    float e = __expf(ssc[s] - m);
                    ssc[s] = e; ssum += e;
                }
#pragma unroll
                for (int off = 16; off; off >>= 1)
                    ssum += __shfl_xor_sync(~0u, ssum, off);
                float inv = __fdividef(1.f, ssum);
                for (int s = lane; s < TIN; s += 32) ssc[s] *= inv;
            }
            __syncthreads();

            const float* mrow = memory + (size_t)b * TIN * UNITS;
            float accc = 0.f;
#pragma unroll 4
            for (int s = 0; s < TIN; s++)
                accc = fmaf(ssc[s], mrow[(size_t)s * UNITS + tid], accc);
            hrow[512 + tid] = accc;
        }

        grid_barrier(nCTA);
    }
}

// ---------------------------------------------------------------------------
// Vocab GEMM: 1-term fp16. out[1984,34004] = Ah @ Bh^T + bias.
#define V_ARR   (128 * FTS * 2)
#define V_STAGE (2 * V_ARR)
#define V_SMEM  (2 * V_STAGE)

__global__ void __launch_bounds__(256)
gemm_vocab_f16(const __half* __restrict__ Ah,
               const __half* __restrict__ Bh,
               const float* __restrict__ bias,
               float* __restrict__ out)
{
    extern __shared__ char dsm[];
    const int m0 = blockIdx.x * 128;
    const int n0 = blockIdx.y * 128;
    const int tid  = threadIdx.x;
    const int wid  = tid >> 5, lane = tid & 31;
    const int wm   = wid & 1,  wn   = wid >> 1;
    const int mbase = wm * 64, nbase = wn * 32;
    const uint32_t sb = smem_u32(dsm);

    float acc[16][4];
#pragma unroll
    for (int i = 0; i < 16; i++)
#pragma unroll
        for (int j = 0; j < 4; j++) acc[i][j] = 0.f;

    auto issue = [&](int it, int stage) {
        int koff = it * 64;
#pragma unroll
        for (int arr = 0; arr < 2; arr++) {
            const __half* src = arr ? Bh : Ah;
            const int rbase = arr ? n0 : m0;
#pragma unroll
            for (int l = 0; l < 4; l++) {
                int q = tid + l * 256;
                int r = q >> 3, c8 = (q & 7) * 8;
                uint32_t dst = sb + stage * V_STAGE + arr * V_ARR
                             + (uint32_t)(r * FTS + c8) * 2;
                cp_async16(dst, src + (size_t)(rbase + r) * UNITS + koff + c8);
            }
        }
        cp_commit();
    };
    auto compute = [&](int stage) {
        uint32_t aHb = sb + stage * V_STAGE;
        uint32_t bHb = aHb + V_ARR;
#pragma unroll
        for (int ks = 0; ks < 4; ks++) {
            uint32_t a_off = (uint32_t)(((mbase + (lane & 15)) * FTS
                              + ks * 16 + (lane >> 4) * 8) * 2);
            uint32_t aH[4][4];
#pragma unroll
            for (int i = 0; i < 4; i++) {
                uint32_t o = a_off + (uint32_t)(i * 16 * FTS * 2);
                ldm_x4(aH[i][0], aH[i][1], aH[i][2], aH[i][3], aHb + o);
            }
            uint32_t b_off = (uint32_t)(((nbase + (lane & 7) + (lane >> 4) * 8) * FTS
                              + ks * 16 + ((lane >> 3) & 1) * 8) * 2);
            uint32_t bH[4][2];
#pragma unroll
            for (int jp = 0; jp < 2; jp++) {
                uint32_t o = b_off + (uint32_t)(jp * 16 * FTS * 2);
                ldm_x4(bH[jp*2][0], bH[jp*2][1], bH[jp*2+1][0], bH[jp*2+1][1], bHb + o);
            }
#pragma unroll
            for (int i = 0; i < 4; i++)
#pragma unroll
                for (int j = 0; j < 4; j++)
                    mma_f16(acc[i * 4 + j], aH[i], bH[j]);
        }
    };

    issue(0, 0);
    issue(1, 1);
    for (int it = 0; it < 8; it++) {
        int stage = it & 1;
        if (it >= 6) cp_wait<0>(); else cp_wait<1>();
        __syncthreads();
        compute(stage);
        __syncthreads();
        if (it + 2 < 8) issue(it + 2, stage);
    }

#pragma unroll
    for (int i = 0; i < 4; i++) {
        int row0 = m0 + mbase + i * 16 + (lane >> 2);
#pragma unroll
        for (int j = 0; j < 4; j++) {
            int col = n0 + nbase + j * 8 + (lane & 3) * 2;
            if (col >= VOCAB) continue;
            float b0 = bias[col], b1 = bias[col + 1];
            const float* c = acc[i * 4 + j];
            if (row0 < ROWS) {
                out[(size_t)row0 * VOCAB + col]     = c[0] + b0;
                out[(size_t)row0 * VOCAB + col + 1] = c[1] + b1;
            }
            if (row0 + 8 < ROWS) {
                out[(size_t)(row0 + 8) * VOCAB + col]     = c[2] + b0;
                out[(size_t)(row0 + 8) * VOCAB + col + 1] = c[3] + b1;
            }
        }
    }
}

// ---------------------------------------------------------------------------
static inline float* sym_addr(const void* sym) {
    void* p = nullptr;
    cudaGetSymbolAddress(&p, sym);
    return (float*)p;
}
static inline __nv_bfloat16* sym_addr_bf(const void* sym) {
    void* p = nullptr;
    cudaGetSymbolAddress(&p, sym);
    return (__nv_bfloat16*)p;
}
static inline __half* sym_addr_h(const void* sym) {
    void* p = nullptr;
    cudaGetSymbolAddress(&p, sym);
    return (__half*)p;
}

extern "C" void kernel_launch(void* const* d_in, const int* in_sizes, int n_in,
                              void* d_out, int out_size)
{
    const int*   dec = (const int*)  d_in[0];
    const float* h0  = (const float*)d_in[1];
    const float* c0  = (const float*)d_in[2];
    const float* mem = (const float*)d_in[3];
    const float* emb = (const float*)d_in[4];
    const float* Wk  = (const float*)d_in[5];
    const float* Uk  = (const float*)d_in[6];
    const float* bk  = (const float*)d_in[7];
    const float* Wm  = (const float*)d_in[8];
    const float* Wq  = (const float*)d_in[9];
    const float* vat = (const float*)d_in[10];
    const float* Wa  = (const float*)d_in[11];
    const float* Wfc = (const float*)d_in[12];
    const float* bfc = (const float*)d_in[13];
    float* out = (float*)d_out;

    float* keys   = sym_addr(g_keys);
    float* embA   = sym_addr(g_embA);
    float* zpre   = sym_addr(g_zpre);
    float* cbuf   = sym_addr(g_cbuf);
    float* hctx   = sym_addr(g_hctx);
    __half* wqTh  = sym_addr_h(g_wqTh);
    __half* sA_h  = sym_addr_h(g_sA_h);
    __half* wT_h  = sym_addr_h(g_wT_h);
    __nv_bfloat16* wkuH = sym_addr_bf(g_wkuH);
    __nv_bfloat16* wkuL = sym_addr_bf(g_wkuL);
    __nv_bfloat16* uk0H = sym_addr_bf(g_uk0H);
    __nv_bfloat16* uk0L = sym_addr_bf(g_uk0L);
    __nv_bfloat16* wmT_h  = sym_addr_bf(g_wmT_h);
    __nv_bfloat16* wmT_l  = sym_addr_bf(g_wmT_l);
    __nv_bfloat16* wk0T_h = sym_addr_bf(g_wk0T_h);
    __nv_bfloat16* wk0T_l = sym_addr_bf(g_wk0T_l);
    __nv_bfloat16* wkpT_h = sym_addr_bf(g_wkpT_h);
    __nv_bfloat16* wkpT_l = sym_addr_bf(g_wkpT_l);
    __nv_bfloat16* waT_h  = sym_addr_bf(g_waT_h);
    __nv_bfloat16* waT_l  = sym_addr_bf(g_waT_l);

    cudaFuncSetAttribute(gemm3_kernel,
                         cudaFuncAttributeMaxDynamicSharedMemorySize, F_SMEM);
    cudaFuncSetAttribute(gemm_states_kernel,
                         cudaFuncAttributeMaxDynamicSharedMemorySize, F_SMEM);
    cudaFuncSetAttribute(step_loop_kernel,
                         cudaFuncAttributeMaxDynamicSharedMemorySize, P_SMEM);
    cudaFuncSetAttribute(gemm_vocab_f16,
                         cudaFuncAttributeMaxDynamicSharedMemorySize, V_SMEM);

    // 1: gather
    gather_emb_kernel<<<ROWS, 128>>>(dec, emb, embA);
    // 2: all pre-loop converts
    mega_convert_kernel<<<3200, 256>>>(Wm, Wk, Uk, Wq,
                                       wmT_h, wmT_l, wk0T_h, wk0T_l,
                                       wkpT_h, wkpT_l, wqTh, uk0H, uk0L);
    // 3: keys + zpre + wbig (fused +Uk + gate-interleave epilogue)
    gemm3_kernel<<<504, 256, F_SMEM>>>(mem, wmT_h, wmT_l, keys,
                                       embA, wk0T_h, wk0T_l, bk, zpre,
                                       Wa, wkpT_h, wkpT_l, Uk, wkuH, wkuL);
    // 4: persistent step loop  <-- ncu capture target
    step_loop_kernel<<<128, 512, P_SMEM>>>(
        h0, c0, uk0H, uk0L, wkuH, wkuL, zpre, cbuf, hctx,
        wqTh, keys, mem, vat);
    // 5: post-loop converts (Wa split + Wfc fp16)
    post_convert_kernel<<<512 + 17024, 256>>>(Wa, Wfc, waT_h, waT_l, wT_h);
    // 6: states = hctx @ Wa -> fp16
    gemm_states_kernel<<<dim3(16, 4), 256, F_SMEM>>>(hctx, waT_h, waT_l, sA_h);
    // 7: vocab projection
    gemm_vocab_f16<<<dim3(MPAD / 128, VPAD / 128), 256, V_SMEM>>>(
        sA_h, wT_h, bfc, out);
}

// round 11
// speedup vs baseline: 3.6877x; 1.1656x over previous
#include <cuda_runtime.h>
#include <cuda.h>
#include <cuda_bf16.h>
#include <cuda_fp16.h>
#include <math.h>
#include <stdint.h>

// ============================================================================
// Attention-LSTM decoder. B=64, T_out=31, T_in=60, U=512, EMB=300, VOCAB=34004.
// Launch order (ncu captures app launch #4):
//   1 gather_emb   2 mega_convert (ALL weight transposes/splits incl Wa/Wfc)
//   3 gemm3 (keys[fp16 out] + zpre + wbig[fused +Uk + gate-interleave])
//   4 step_loop (PERSISTENT, 128 CTAs)   5 states GEMM   6 vocab GEMM
// Key fix this round: attention q-GEMV uses Wq in ORIGINAL [k][n] layout
// (fp16) -> coalesced; previous transposed row-per-thread layout caused 8x
// L2 sector inflation (~128 MB/step).
// ============================================================================

#define B64   64
#define TOUT  31
#define TIN   60
#define UNITS 512
#define EMB   300
#define EMBP  320
#define VOCAB 34004
#define ROWS  (B64 * TOUT)     // 1984
#define MPAD  2048
#define VPAD  34048            // 266 * 128
#define HLD   (TOUT * 1024)

// ---------------- scratch ----------------------------------------------------
__device__ float g_embA  [ROWS * EMBP];
__device__ float g_zpre  [ROWS * 4 * UNITS];
__device__ float g_cbuf  [2][B64 * UNITS];
__device__ float g_hctx  [ROWS * 1024];
__device__ __align__(16) __half g_keysh[B64 * TIN * UNITS];      // fp16 keys
__device__ __align__(16) __half g_wqKh [UNITS * UNITS];          // Wq [k][n] fp16
__device__ __align__(16) __half g_sA_h[MPAD * UNITS];            // pad rows stay 0
__device__ __align__(16) __half g_wT_h [(size_t)VPAD * UNITS];   // fp16 [n][k]
__device__ __align__(16) __nv_bfloat16 g_wkuH[2048 * 1024];      // [n'][k]
__device__ __align__(16) __nv_bfloat16 g_wkuL[2048 * 1024];
__device__ __align__(16) __nv_bfloat16 g_uk0H[2048 * 512];
__device__ __align__(16) __nv_bfloat16 g_uk0L[2048 * 512];
__device__ __align__(16) __nv_bfloat16 g_wmT_h [512 * 512];
__device__ __align__(16) __nv_bfloat16 g_wmT_l [512 * 512];
__device__ __align__(16) __nv_bfloat16 g_wk0T_h[2048 * EMBP];
__device__ __align__(16) __nv_bfloat16 g_wk0T_l[2048 * EMBP];
__device__ __align__(16) __nv_bfloat16 g_wkpT_h[2048 * 512];
__device__ __align__(16) __nv_bfloat16 g_wkpT_l[2048 * 512];
__device__ __align__(16) __nv_bfloat16 g_waT_h [512 * 1024];
__device__ __align__(16) __nv_bfloat16 g_waT_l [512 * 1024];

__device__ int g_bar_cnt = 0;
__device__ volatile unsigned g_bar_gen = 0;

// ---------------- PTX helpers -------------------------------------------------
__device__ __forceinline__ uint32_t smem_u32(const void* p) {
    uint32_t a;
    asm("{ .reg .u64 t; cvta.to.shared.u64 t, %1; cvt.u32.u64 %0, t; }" : "=r"(a) : "l"(p));
    return a;
}
__device__ __forceinline__ void ldm_x4(uint32_t& r0, uint32_t& r1, uint32_t& r2,
                                       uint32_t& r3, uint32_t addr) {
    asm volatile("ldmatrix.sync.aligned.m8n8.x4.shared.b16 {%0,%1,%2,%3}, [%4];"
                 : "=r"(r0), "=r"(r1), "=r"(r2), "=r"(r3) : "r"(addr));
}
__device__ __forceinline__ void ldm_x2(uint32_t& r0, uint32_t& r1, uint32_t addr) {
    asm volatile("ldmatrix.sync.aligned.m8n8.x2.shared.b16 {%0,%1}, [%2];"
                 : "=r"(r0), "=r"(r1) : "r"(addr));
}
__device__ __forceinline__ void mma_bf16(float* c, const uint32_t* a, const uint32_t* b) {
    asm volatile("mma.sync.aligned.m16n8k16.row.col.f32.bf16.bf16.f32 "
                 "{%0,%1,%2,%3}, {%4,%5,%6,%7}, {%8,%9}, {%0,%1,%2,%3};"
                 : "+f"(c[0]), "+f"(c[1]), "+f"(c[2]), "+f"(c[3])
                 : "r"(a[0]), "r"(a[1]), "r"(a[2]), "r"(a[3]), "r"(b[0]), "r"(b[1]));
}
__device__ __forceinline__ void mma_f16(float* c, const uint32_t* a, const uint32_t* b) {
    asm volatile("mma.sync.aligned.m16n8k16.row.col.f32.f16.f16.f32 "
                 "{%0,%1,%2,%3}, {%4,%5,%6,%7}, {%8,%9}, {%0,%1,%2,%3};"
                 : "+f"(c[0]), "+f"(c[1]), "+f"(c[2]), "+f"(c[3])
                 : "r"(a[0]), "r"(a[1]), "r"(a[2]), "r"(a[3]), "r"(b[0]), "r"(b[1]));
}
__device__ __forceinline__ void cp_async16(uint32_t dst, const void* src) {
    asm volatile("cp.async.cg.shared.global [%0], [%1], 16;" :: "r"(dst), "l"(src));
}
__device__ __forceinline__ void cp_commit() { asm volatile("cp.async.commit_group;"); }
template<int N> __device__ __forceinline__ void cp_wait() {
    asm volatile("cp.async.wait_group %0;" :: "n"(N));
}
__device__ __forceinline__ uint32_t pack_bf2(float a, float b) {
    __nv_bfloat162 t = __floats2bfloat162_rn(a, b);
    return *reinterpret_cast<uint32_t*>(&t);
}
__device__ __forceinline__ float bf_res(float a) {
    return a - __bfloat162float(__float2bfloat16(a));
}
__device__ __forceinline__ float fast_tanh(float x) {
    float e = __expf(2.f * x);
    return 1.f - __fdividef(2.f, e + 1.f);
}
__device__ __forceinline__ float fast_sigmoid(float x) {
    return __fdividef(1.f, 1.f + __expf(-x));
}
__device__ __forceinline__ void grid_barrier(int nCTA) {
    __syncthreads();
    if (threadIdx.x == 0) {
        unsigned gen = g_bar_gen;
        __threadfence();
        if (atomicAdd(&g_bar_cnt, 1) == nCTA - 1) {
            g_bar_cnt = 0;
            __threadfence();
            g_bar_gen = gen + 1;
        } else {
            while (g_bar_gen == gen) { }
        }
        __threadfence();
    }
    __syncthreads();
}

// ---------------------------------------------------------------------------
__global__ void gather_emb_kernel(const int* __restrict__ dec,
                                  const float* __restrict__ emb,
                                  float* __restrict__ out) {
    int r = blockIdx.x;          // r = t*64 + b
    int t = r >> 6, b = r & 63;
    int tok = dec[b * TOUT + t];
    const float* src = emb + (size_t)tok * EMB;
    float* dst = out + (size_t)r * EMBP;
    for (int e = threadIdx.x; e < EMBP; e += blockDim.x)
        dst[e] = (e < EMB) ? src[e] : 0.f;
}

// ---------------------------------------------------------------------------
// mega_convert: ALL weight conversions in one launch (dispatch by blockIdx).
//  P0 [0,256)       : Wm -> wmT hi/lo            (K=512, N=512,  Kpad=512)
//  P1 [256,896)     : Wk[0:300] -> wk0T hi/lo    (K=300, N=2048, Kpad=320)
//  P2 [896,1920)    : Wk[300:812] -> wkpT hi/lo  (K=512, N=2048, Kpad=512)
//  P3 [1920,2176)   : Wq -> wqKh fp16 COPY (no transpose, [k][n])
//  P4 [2176,3200)   : Uk -> uk0 gate-interleaved hi/lo
//  P5 [3200,3712)   : Wa -> waT hi/lo            (K=1024, N=512, Kpad=1024)
//  P6 [3712,20736)  : Wfc -> wT_h fp16 [n][k]
__global__ void mega_convert_kernel(const float* __restrict__ Wm,
                                    const float* __restrict__ Wk,
                                    const float* __restrict__ Uk,
                                    const float* __restrict__ Wq,
                                    const float* __restrict__ Wa,
                                    const float* __restrict__ Wfc,
                                    __nv_bfloat16* __restrict__ wmT_h,
                                    __nv_bfloat16* __restrict__ wmT_l,
                                    __nv_bfloat16* __restrict__ wk0T_h,
                                    __nv_bfloat16* __restrict__ wk0T_l,
                                    __nv_bfloat16* __restrict__ wkpT_h,
                                    __nv_bfloat16* __restrict__ wkpT_l,
                                    __half* __restrict__ wqKh,
                                    __nv_bfloat16* __restrict__ uk0H,
                                    __nv_bfloat16* __restrict__ uk0L,
                                    __nv_bfloat16* __restrict__ waT_h,
                                    __nv_bfloat16* __restrict__ waT_l,
                                    __half* __restrict__ wT_h)
{
    __shared__ float tile[32][33];
    int bid = blockIdx.x;
    int tx = threadIdx.x & 31, ty = threadIdx.x >> 5;

    if (bid >= 1920 && bid < 2176) {     // P3: Wq straight fp16 copy
        int i = bid - 1920;
        int base = i * 1024;             // 256 blocks x 1024 elems = 256K
        for (int e = threadIdx.x; e < 1024; e += 256)
            wqKh[base + e] = __float2half_rn(Wq[base + e]);
        return;
    }
    if (bid >= 3712) {                   // P6: Wfc fp16 transpose
        int i = bid - 3712;
        int n0 = (i % 1064) * 32, k0 = (i / 1064) * 32;
        for (int j = ty; j < 32; j += 8) {
            int n = n0 + tx;
            tile[j][tx] = (n < VOCAB) ? Wfc[(size_t)(k0 + j) * VOCAB + n] : 0.f;
        }
        __syncthreads();
        for (int j = ty; j < 32; j += 8)
            wT_h[(size_t)(n0 + j) * UNITS + k0 + tx] = __float2half_rn(tile[tx][j]);
        return;
    }

    const float* W; int K, N, ldn, Kpad, mode, n0, k0;
    __nv_bfloat16 *hi, *lo;
    if (bid < 256) {                     // P0
        int i = bid; W = Wm; K = 512; N = 512; ldn = 512; Kpad = 512; mode = 0;
        hi = wmT_h; lo = wmT_l; n0 = (i % 16) * 32; k0 = (i / 16) * 32;
    } else if (bid < 896) {              // P1
        int i = bid - 256; W = Wk; K = EMB; N = 2048; ldn = 2048; Kpad = EMBP; mode = 0;
        hi = wk0T_h; lo = wk0T_l; n0 = (i % 64) * 32; k0 = (i / 64) * 32;
    } else if (bid < 1920) {             // P2
        int i = bid - 896; W = Wk + (size_t)EMB * 2048; K = 512; N = 2048;
        ldn = 2048; Kpad = 512; mode = 0;
        hi = wkpT_h; lo = wkpT_l; n0 = (i % 64) * 32; k0 = (i / 64) * 32;
    } else if (bid < 3200) {             // P4
        int i = bid - 2176; W = Uk; K = 512; N = 2048; ldn = 2048; Kpad = 512; mode = 2;
        hi = uk0H; lo = uk0L; n0 = (i % 64) * 32; k0 = (i / 64) * 32;
    } else {                             // P5
        int i = bid - 3200; W = Wa; K = 1024; N = 512; ldn = 512; Kpad = 1024; mode = 0;
        hi = waT_h; lo = waT_l; n0 = (i % 16) * 32; k0 = (i / 16) * 32;
    }

    for (int j = ty; j < 32; j += 8) {
        int k = k0 + j, n = n0 + tx;
        tile[j][tx] = (k < K && n < N) ? W[(size_t)k * ldn + n] : 0.f;
    }
    __syncthreads();
    for (int j = ty; j < 32; j += 8) {
        int n = n0 + j, k = k0 + tx;
        float v = tile[tx][j];
        int nn = (mode == 2) ? ((n & 511) * 4 + (n >> 9)) : n;
        __nv_bfloat16 h = __float2bfloat16(v);
        hi[(size_t)nn * Kpad + k] = h;
        lo[(size_t)nn * Kpad + k] = __float2bfloat16(v - __bfloat162float(h));
    }
}

// ---------------------------------------------------------------------------
// Core split-bf16 3-term mma GEMM (fp32 A on the fly, pre-split B).
// MODE 0: fp32 C (+bias[n]).  MODE 1: fp16 out.
// MODE 3: wbig special — add Uk (rows<512), write gate-interleaved split-bf16.
#define FTS     72
#define F_ARR   (128 * FTS * 2)        // 18432 B
#define F_STAGE (4 * F_ARR)            // 73728 B
#define F_SMEM  (2 * F_STAGE)          // 147456 B

template<int MODE>
__device__ __forceinline__ void gemm_core(
    char* dsm, int m0, int n0,
    const float* __restrict__ A, int lda, int M, int N, int K,
    const __nv_bfloat16* __restrict__ BhT,
    const __nv_bfloat16* __restrict__ BlT,
    const float* __restrict__ bias,
    float* __restrict__ C, int ldc,
    __half* __restrict__ Ch,
    __nv_bfloat16* __restrict__ OH, __nv_bfloat16* __restrict__ OL)
{
    const int tid  = threadIdx.x;
    const int wid  = tid >> 5, lane = tid & 31;
    const int wm   = wid & 1,  wn   = wid >> 1;
    const int mbase = wm * 64, nbase = wn * 32;
    const uint32_t sb = smem_u32(dsm);
    const int NIT = K >> 6;

    float acc[16][4];
#pragma unroll
    for (int i = 0; i < 16; i++)
#pragma unroll
        for (int j = 0; j < 4; j++) acc[i][j] = 0.f;

    float4 Areg[8];
    auto loadA = [&](int it) {
        int koff = it * 64;
#pragma unroll
        for (int l = 0; l < 8; l++) {
            int q = tid + l * 256;
            int r = q >> 4, c4 = (q & 15) * 4;
            int gm = m0 + r;
            Areg[l] = (gm < M) ? *(const float4*)(A + (size_t)gm * lda + koff + c4)
                               : make_float4(0.f, 0.f, 0.f, 0.f);
        }
    };
    auto storeA = [&](int stage) {
#pragma unroll
        for (int l = 0; l < 8; l++) {
            int q = tid + l * 256;
            int r = q >> 4, c4 = (q & 15) * 4;
            float4 v = Areg[l];
            uint32_t off = (uint32_t)(r * FTS + c4) * 2;
            uint2 hi = make_uint2(pack_bf2(v.x, v.y), pack_bf2(v.z, v.w));
            uint2 lo = make_uint2(pack_bf2(bf_res(v.x), bf_res(v.y)),
                                  pack_bf2(bf_res(v.z), bf_res(v.w)));
            *(uint2*)(dsm + stage * F_STAGE + 0 * F_ARR + off) = hi;
            *(uint2*)(dsm + stage * F_STAGE + 1 * F_ARR + off) = lo;
        }
    };
    auto issueB = [&](int it, int stage) {
        int koff = it * 64;
#pragma unroll
        for (int arr = 0; arr < 2; arr++) {
            const __nv_bfloat16* src = arr ? BlT : BhT;
#pragma unroll
            for (int l = 0; l < 4; l++) {
                int q = tid + l * 256;
                int r = q >> 3, c8 = (q & 7) * 8;
                uint32_t dst = sb + stage * F_STAGE + (2 + arr) * F_ARR
                             + (uint32_t)(r * FTS + c8) * 2;
                cp_async16(dst, src + (size_t)(n0 + r) * K + koff + c8);
            }
        }
        cp_commit();
    };
    auto compute = [&](int stage) {
        uint32_t aHb = sb + stage * F_STAGE;
        uint32_t aLb = aHb + F_ARR;
        uint32_t bHb = aHb + 2 * F_ARR;
        uint32_t bLb = aHb + 3 * F_ARR;
#pragma unroll
        for (int ks = 0; ks < 4; ks++) {
            uint32_t a_off = (uint32_t)(((mbase + (lane & 15)) * FTS
                              + ks * 16 + (lane >> 4) * 8) * 2);
            uint32_t aH[4][4], aL[4][4];
#pragma unroll
            for (int i = 0; i < 4; i++) {
                uint32_t o = a_off + (uint32_t)(i * 16 * FTS * 2);
                ldm_x4(aH[i][0], aH[i][1], aH[i][2], aH[i][3], aHb + o);
                ldm_x4(aL[i][0], aL[i][1], aL[i][2], aL[i][3], aLb + o);
            }
            uint32_t b_off = (uint32_t)(((nbase + (lane & 7) + (lane >> 4) * 8) * FTS
                              + ks * 16 + ((lane >> 3) & 1) * 8) * 2);
            uint32_t bH[4][2], bL[4][2];
#pragma unroll
            for (int jp = 0; jp < 2; jp++) {
                uint32_t o = b_off + (uint32_t)(jp * 16 * FTS * 2);
                ldm_x4(bH[jp*2][0], bH[jp*2][1], bH[jp*2+1][0], bH[jp*2+1][1], bHb + o);
                ldm_x4(bL[jp*2][0], bL[jp*2][1], bL[jp*2+1][0], bL[jp*2+1][1], bLb + o);
            }
#pragma unroll
            for (int i = 0; i < 4; i++)
#pragma unroll
                for (int j = 0; j < 4; j++) {
                    mma_bf16(acc[i * 4 + j], aH[i], bH[j]);
                    mma_bf16(acc[i * 4 + j], aH[i], bL[j]);
                    mma_bf16(acc[i * 4 + j], aL[i], bH[j]);
                }
        }
    };

    loadA(0);
    issueB(0, 0);
    if (NIT > 1) issueB(1, 1);
    for (int it = 0; it < NIT; it++) {
        int stage = it & 1;
        if (it >= NIT - 2) cp_wait<0>(); else cp_wait<1>();
        storeA(stage);
        __syncthreads();
        if (it + 1 < NIT) loadA(it + 1);
        compute(stage);
        __syncthreads();
        if (it + 2 < NIT) issueB(it + 2, stage);
    }

#pragma unroll
    for (int i = 0; i < 4; i++) {
        int row0 = m0 + mbase + i * 16 + (lane >> 2);
#pragma unroll
        for (int j = 0; j < 4; j++) {
            int col = n0 + nbase + j * 8 + (lane & 3) * 2;
            if (col >= N) continue;
            const float* c = acc[i * 4 + j];
#pragma unroll
            for (int hrow = 0; hrow < 2; hrow++) {
                int gm = row0 + hrow * 8;
                if (gm >= M) continue;
                float v0 = c[hrow * 2 + 0], v1 = c[hrow * 2 + 1];
                if (MODE == 0) {
                    float b0 = bias ? bias[col] : 0.f;
                    float b1 = bias ? bias[col + 1] : 0.f;
                    C[(size_t)gm * ldc + col]     = v0 + b0;
                    C[(size_t)gm * ldc + col + 1] = v1 + b1;
                } else if (MODE == 1) {
                    Ch[(size_t)gm * ldc + col]     = __float2half_rn(v0);
                    Ch[(size_t)gm * ldc + col + 1] = __float2half_rn(v1);
                } else {   // MODE 3
                    if (gm < 512) {
                        v0 += bias[(size_t)gm * 2048 + col];
                        v1 += bias[(size_t)gm * 2048 + col + 1];
                    }
                    int np0 = (col & 511) * 4 + (col >> 9);
                    int np1 = ((col + 1) & 511) * 4 + ((col + 1) >> 9);
                    __nv_bfloat16 h0 = __float2bfloat16(v0);
                    __nv_bfloat16 h1 = __float2bfloat16(v1);
                    OH[(size_t)np0 * 1024 + gm] = h0;
                    OL[(size_t)np0 * 1024 + gm] =
                        __float2bfloat16(v0 - __bfloat162float(h0));
                    OH[(size_t)np1 * 1024 + gm] = h1;
                    OL[(size_t)np1 * 1024 + gm] =
                        __float2bfloat16(v1 - __bfloat162float(h1));
                }
            }
        }
    }
}

// gemm3: keys->fp16 (120 blocks) + zpre (256) + wbig (128) in one launch.
__global__ void __launch_bounds__(256)
gemm3_kernel(const float* __restrict__ mem,
             const __nv_bfloat16* __restrict__ wmT_h,
             const __nv_bfloat16* __restrict__ wmT_l,
             __half* __restrict__ keysh,
             const float* __restrict__ embA,
             const __nv_bfloat16* __restrict__ wk0T_h,
             const __nv_bfloat16* __restrict__ wk0T_l,
             const float* __restrict__ bk,
             float* __restrict__ zpre,
             const float* __restrict__ Wa,
             const __nv_bfloat16* __restrict__ wkpT_h,
             const __nv_bfloat16* __restrict__ wkpT_l,
             const float* __restrict__ Uk,
             __nv_bfloat16* __restrict__ wkuH,
             __nv_bfloat16* __restrict__ wkuL)
{
    extern __shared__ char dsm[];
    int bid = blockIdx.x;
    if (bid < 120) {            // keys = memory @ Wm -> fp16
        int m0 = (bid % 30) * 128, n0 = (bid / 30) * 128;
        gemm_core<1>(dsm, m0, n0, mem, UNITS, B64 * TIN, UNITS, UNITS,
                     wmT_h, wmT_l, nullptr, nullptr, UNITS, keysh,
                     nullptr, nullptr);
    } else if (bid < 376) {     // zpre = embA @ Wk0 + bk
        int p = bid - 120;
        int m0 = (p % 16) * 128, n0 = (p / 16) * 128;
        gemm_core<0>(dsm, m0, n0, embA, EMBP, ROWS, 2048, EMBP,
                     wk0T_h, wk0T_l, bk, zpre, 2048, nullptr,
                     nullptr, nullptr);
    } else {                    // wbig = Wa@Wk' (+Uk) -> wku interleaved
        int p = bid - 376;
        int m0 = (p % 8) * 128, n0 = (p / 8) * 128;
        gemm_core<3>(dsm, m0, n0, Wa, UNITS, 1024, 2048, UNITS,
                     wkpT_h, wkpT_l, Uk, nullptr, 0, nullptr,
                     wkuH, wkuL);
    }
}

// states GEMM wrapper (MODE 1 fp16 out)
__global__ void __launch_bounds__(256)
gemm_states_kernel(const float* __restrict__ hctx,
                   const __nv_bfloat16* __restrict__ waT_h,
                   const __nv_bfloat16* __restrict__ waT_l,
                   __half* __restrict__ sA_h)
{
    extern __shared__ char dsm[];
    int m0 = blockIdx.x * 128, n0 = blockIdx.y * 128;
    gemm_core<1>(dsm, m0, n0, hctx, 1024, ROWS, UNITS, 1024,
                 waT_h, waT_l, nullptr, nullptr, UNITS, sA_h,
                 nullptr, nullptr);
}

// ---------------------------------------------------------------------------
// PERSISTENT step loop: 128 CTAs x 512 threads.
#define PTS     72
#define P_AH    0
#define P_AL    9216
#define P_BH    18432
#define P_BL    20736
#define P_STAGE 23040
#define P_SMEM  (3 * P_STAGE)    // 69120 B

__global__ void __launch_bounds__(512, 1)
step_loop_kernel(const float* __restrict__ h0,
                 const float* __restrict__ c0,
                 const __nv_bfloat16* __restrict__ uk0H,
                 const __nv_bfloat16* __restrict__ uk0L,
                 const __nv_bfloat16* __restrict__ wkuH,
                 const __nv_bfloat16* __restrict__ wkuL,
                 const float* __restrict__ zpre,
                 float* __restrict__ cbuf,
                 float* __restrict__ hctx,
                 const __half* __restrict__ wqKh,   // [k][n]
                 const __half* __restrict__ keysh,
                 const float* __restrict__ memory,
                 const float* __restrict__ v_att)
{
    extern __shared__ char dsm[];
    const int cta  = blockIdx.x;              // 0..127
    const int tid  = threadIdx.x;
    const int wid  = tid >> 5, lane = tid & 31;
    const int mbase = (wid & 3) * 16;
    const int nbase = (wid >> 2) * 8;
    const int n0   = cta * 16;
    const uint32_t sb = smem_u32(dsm);
    const int nCTA = gridDim.x;

    for (int t = 0; t < TOUT; t++) {
        // ================= gates phase =================
        const float* Aptr; int astride, K;
        const __nv_bfloat16 *BH, *BL;
        if (t == 0) { Aptr = h0; astride = UNITS; K = 512; BH = uk0H; BL = uk0L; }
        else { Aptr = hctx + (size_t)(t - 1) * 1024; astride = HLD; K = 1024;
               BH = wkuH; BL = wkuL; }
        const float* cprev = t ? (cbuf + (size_t)((t - 1) & 1) * B64 * UNITS) : c0;
        float* cnew = cbuf + (size_t)(t & 1) * B64 * UNITS;
        const int NIT = K >> 6;

        float acc[4] = {0.f, 0.f, 0.f, 0.f};
        float4 Areg[2];

        auto issueB = [&](int it, int stage) {
            int koff = it * 64;
            if (tid < 256) {
                int arr = tid >> 7;
                int rem = tid & 127;
                int r   = rem >> 3;
                int c8  = (rem & 7) * 8;
                const __nv_bfloat16* src = arr ? BL : BH;
                uint32_t dst = sb + stage * P_STAGE + (arr ? P_BL : P_BH)
                             + (uint32_t)(r * PTS + c8) * 2;
                cp_async16(dst, src + (size_t)(n0 + r) * K + koff + c8);
            }
            cp_commit();
        };
        auto loadA = [&](int it) {
            int koff = it * 64;
#pragma unroll
            for (int l = 0; l < 2; l++) {
                int q = tid + l * 512;
                int r = q >> 4, c4 = (q & 15) * 4;
                Areg[l] = *(const float4*)(Aptr + (size_t)r * astride + koff + c4);
            }
        };
        auto storeA = [&](int stage) {
#pragma unroll
            for (int l = 0; l < 2; l++) {
                int q = tid + l * 512;
                int r = q >> 4, c4 = (q & 15) * 4;
                float4 v = Areg[l];
                uint32_t off = (uint32_t)(r * PTS + c4) * 2;
                uint2 hi = make_uint2(pack_bf2(v.x, v.y), pack_bf2(v.z, v.w));
                uint2 lo = make_uint2(pack_bf2(bf_res(v.x), bf_res(v.y)),
                                      pack_bf2(bf_res(v.z), bf_res(v.w)));
                *(uint2*)(dsm + stage * P_STAGE + P_AH + off) = hi;
                *(uint2*)(dsm + stage * P_STAGE + P_AL + off) = lo;
            }
        };
        auto compute = [&](int stage) {
            uint32_t aHb = sb + stage * P_STAGE + P_AH;
            uint32_t aLb = sb + stage * P_STAGE + P_AL;
            uint32_t bHb = sb + stage * P_STAGE + P_BH;
            uint32_t bLb = sb + stage * P_STAGE + P_BL;
#pragma unroll
            for (int ks = 0; ks < 4; ks++) {
                uint32_t a_off = (uint32_t)(((mbase + (lane & 15)) * PTS
                                  + ks * 16 + (lane >> 4) * 8) * 2);
                uint32_t aH[4], aL[4];
                ldm_x4(aH[0], aH[1], aH[2], aH[3], aHb + a_off);
                ldm_x4(aL[0], aL[1], aL[2], aL[3], aLb + a_off);
                uint32_t b_off = (uint32_t)(((nbase + (lane & 7)) * PTS
                                  + ks * 16 + ((lane >> 3) & 1) * 8) * 2);
                uint32_t bH[2], bL[2];
                ldm_x2(bH[0], bH[1], bHb + b_off);
                ldm_x2(bL[0], bL[1], bLb + b_off);
                mma_bf16(acc, aH, bH);
                mma_bf16(acc, aH, bL);
                mma_bf16(acc, aL, bH);
            }
        };

        loadA(0);
        issueB(0, 0);
        issueB(1, 1);
        issueB(2, 2);
        for (int it = 0; it < NIT; it++) {
            int stage = it % 3;
            if (it + 3 <= NIT)      cp_wait<2>();
            else if (it + 2 == NIT) cp_wait<1>();
            else                    cp_wait<0>();
            storeA(stage);
            __syncthreads();
            if (it + 1 < NIT) loadA(it + 1);
            if (wid < 8) compute(stage);
            __syncthreads();
            if (it + 3 < NIT) issueB(it + 3, stage);
        }

        // ---- LSTM epilogue ----
        float* zbuf = (float*)dsm;               // [64][20]
        if (wid < 8) {
            int row = mbase + (lane >> 2);
            int col = nbase + (lane & 3) * 2;
            zbuf[row * 20 + col]           = acc[0];
            zbuf[row * 20 + col + 1]       = acc[1];
            zbuf[(row + 8) * 20 + col]     = acc[2];
            zbuf[(row + 8) * 20 + col + 1] = acc[3];
        }
        __syncthreads();
        if (tid < 256) {
            int b  = tid >> 2, ul = tid & 3;
            int u  = cta * 4 + ul;
            const float* ad = zpre + (size_t)t * B64 * 2048 + (size_t)b * 2048;
            float zi = zbuf[b * 20 + ul * 4 + 0] + ad[u];
            float zf = zbuf[b * 20 + ul * 4 + 1] + ad[512 + u];
            float zg = zbuf[b * 20 + ul * 4 + 2] + ad[1024 + u];
            float zo = zbuf[b * 20 + ul * 4 + 3] + ad[1536 + u];
            float si = fast_sigmoid(zi);
            float sf = fast_sigmoid(zf);
            float so = fast_sigmoid(zo);
            float tg = fast_tanh(zg);
            float c  = sf * cprev[(size_t)b * UNITS + u] + si * tg;
            float h  = so * fast_tanh(c);
            cnew[(size_t)b * UNITS + u] = c;
            hctx[(size_t)b * HLD + (size_t)t * 1024 + u] = h;
        }

        grid_barrier(nCTA);

        // ================= attention phase (CTAs 0..63) =================
        if (cta < B64) {
            int b = cta;
            float* sh  = (float*)dsm;
            float* sq  = sh + 512;
            float* ssc = sq + 512;
            float* hrow = hctx + (size_t)b * HLD + (size_t)t * 1024;

            sh[tid] = hrow[tid];
            __syncthreads();
            {   // q[n] = sum_k h[k] * Wq[k][n]; n = tid, COALESCED k-major reads
                float a0 = 0.f, a1 = 0.f, a2 = 0.f, a3 = 0.f;
#pragma unroll 4
                for (int k = 0; k < UNITS; k += 4) {
                    a0 = fmaf(sh[k + 0], __half2float(wqKh[(size_t)(k + 0) * UNITS + tid]), a0);
                    a1 = fmaf(sh[k + 1], __half2float(wqKh[(size_t)(k + 1) * UNITS + tid]), a1);
                    a2 = fmaf(sh[k + 2], __half2float(wqKh[(size_t)(k + 2) * UNITS + tid]), a2);
                    a3 = fmaf(sh[k + 3], __half2float(wqKh[(size_t)(k + 3) * UNITS + tid]), a3);
                }
                sq[tid] = (a0 + a1) + (a2 + a3);
            }
            __syncthreads();

            for (int s = wid; s < TIN; s += 16) {
                const __half* krow = keysh + ((size_t)b * TIN + s) * UNITS;
                float sc = 0.f;
#pragma unroll 4
                for (int u = lane; u < UNITS; u += 32)
                    sc += fast_tanh(__half2float(krow[u]) + sq[u]) * v_att[u];
#pragma unroll
                for (int off = 16; off; off >>= 1)
                    sc += __shfl_xor_sync(~0u, sc, off);
                if (lane == 0) ssc[s] = sc;
            }
            __syncthreads();

            if (tid < 32) {
                float m = -1e30f;
                for (int s = lane; s < TIN; s += 32) m = fmaxf(m, ssc[s]);
#pragma unroll
                for (int off = 16; off; off >>= 1)
                    m = fmaxf(m, __shfl_xor_sync(~0u, m, off));
                float ssum = 0.f;
                for (int s = lane; s < TIN; s += 32) {
                    float e = __expf(ssc[s] - m);
                    ssc[s] = e; ssum += e;
                }
#pragma unroll
                for (int off = 16; off; off >>= 1)
                    ssum += __shfl_xor_sync(~0u, ssum, off);
                float inv = __fdividef(1.f, ssum);
                for (int s = lane; s < TIN; s += 32) ssc[s] *= inv;
            }
            __syncthreads();

            const float* mrow = memory + (size_t)b * TIN * UNITS;
            float accc = 0.f;
#pragma unroll 4
            for (int s = 0; s < TIN; s++)
                accc = fmaf(ssc[s], mrow[(size_t)s * UNITS + tid], accc);
            hrow[512 + tid] = accc;
        }

        grid_barrier(nCTA);
    }
}

// ---------------------------------------------------------------------------
// Vocab GEMM: 1-term fp16. out[1984,34004] = Ah @ Bh^T + bias.
#define V_ARR   (128 * FTS * 2)
#define V_STAGE (2 * V_ARR)
#define V_SMEM  (2 * V_STAGE)

__global__ void __launch_bounds__(256)
gemm_vocab_f16(const __half* __restrict__ Ah,
               const __half* __restrict__ Bh,
               const float* __restrict__ bias,
               float* __restrict__ out)
{
    extern __shared__ char dsm[];
    const int m0 = blockIdx.x * 128;
    const int n0 = blockIdx.y * 128;
    const int tid  = threadIdx.x;
    const int wid  = tid >> 5, lane = tid & 31;
    const int wm   = wid & 1,  wn   = wid >> 1;
    const int mbase = wm * 64, nbase = wn * 32;
    const uint32_t sb = smem_u32(dsm);

    float acc[16][4];
#pragma unroll
    for (int i = 0; i < 16; i++)
#pragma unroll
        for (int j = 0; j < 4; j++) acc[i][j] = 0.f;

    auto issue = [&](int it, int stage) {
        int koff = it * 64;
#pragma unroll
        for (int arr = 0; arr < 2; arr++) {
            const __half* src = arr ? Bh : Ah;
            const int rbase = arr ? n0 : m0;
#pragma unroll
            for (int l = 0; l < 4; l++) {
                int q = tid + l * 256;
                int r = q >> 3, c8 = (q & 7) * 8;
                uint32_t dst = sb + stage * V_STAGE + arr * V_ARR
                             + (uint32_t)(r * FTS + c8) * 2;
                cp_async16(dst, src + (size_t)(rbase + r) * UNITS + koff + c8);
            }
        }
        cp_commit();
    };
    auto compute = [&](int stage) {
        uint32_t aHb = sb + stage * V_STAGE;
        uint32_t bHb = aHb + V_ARR;
#pragma unroll
        for (int ks = 0; ks < 4; ks++) {
            uint32_t a_off = (uint32_t)(((mbase + (lane & 15)) * FTS
                              + ks * 16 + (lane >> 4) * 8) * 2);
            uint32_t aH[4][4];
#pragma unroll
            for (int i = 0; i < 4; i++) {
                uint32_t o = a_off + (uint32_t)(i * 16 * FTS * 2);
                ldm_x4(aH[i][0], aH[i][1], aH[i][2], aH[i][3], aHb + o);
            }
            uint32_t b_off = (uint32_t)(((nbase + (lane & 7) + (lane >> 4) * 8) * FTS
                              + ks * 16 + ((lane >> 3) & 1) * 8) * 2);
            uint32_t bH[4][2];
#pragma unroll
            for (int jp = 0; jp < 2; jp++) {
                uint32_t o = b_off + (uint32_t)(jp * 16 * FTS * 2);
                ldm_x4(bH[jp*2][0], bH[jp*2][1], bH[jp*2+1][0], bH[jp*2+1][1], bHb + o);
            }
#pragma unroll
            for (int i = 0; i < 4; i++)
#pragma unroll
                for (int j = 0; j < 4; j++)
                    mma_f16(acc[i * 4 + j], aH[i], bH[j]);
        }
    };

    issue(0, 0);
    issue(1, 1);
    for (int it = 0; it < 8; it++) {
        int stage = it & 1;
        if (it >= 6) cp_wait<0>(); else cp_wait<1>();
        __syncthreads();
        compute(stage);
        __syncthreads();
        if (it + 2 < 8) issue(it + 2, stage);
    }

#pragma unroll
    for (int i = 0; i < 4; i++) {
        int row0 = m0 + mbase + i * 16 + (lane >> 2);
#pragma unroll
        for (int j = 0; j < 4; j++) {
            int col = n0 + nbase + j * 8 + (lane & 3) * 2;
            if (col >= VOCAB) continue;
            float b0 = bias[col], b1 = bias[col + 1];
            const float* c = acc[i * 4 + j];
            if (row0 < ROWS) {
                out[(size_t)row0 * VOCAB + col]     = c[0] + b0;
                out[(size_t)row0 * VOCAB + col + 1] = c[1] + b1;
            }
            if (row0 + 8 < ROWS) {
                out[(size_t)(row0 + 8) * VOCAB + col]     = c[2] + b0;
                out[(size_t)(row0 + 8) * VOCAB + col + 1] = c[3] + b1;
            }
        }
    }
}

// ---------------------------------------------------------------------------
static inline float* sym_addr(const void* sym) {
    void* p = nullptr;
    cudaGetSymbolAddress(&p, sym);
    return (float*)p;
}
static inline __nv_bfloat16* sym_addr_bf(const void* sym) {
    void* p = nullptr;
    cudaGetSymbolAddress(&p, sym);
    return (__nv_bfloat16*)p;
}
static inline __half* sym_addr_h(const void* sym) {
    void* p = nullptr;
    cudaGetSymbolAddress(&p, sym);
    return (__half*)p;
}

extern "C" void kernel_launch(void* const* d_in, const int* in_sizes, int n_in,
                              void* d_out, int out_size)
{
    const int*   dec = (const int*)  d_in[0];
    const float* h0  = (const float*)d_in[1];
    const float* c0  = (const float*)d_in[2];
    const float* mem = (const float*)d_in[3];
    const float* emb = (const float*)d_in[4];
    const float* Wk  = (const float*)d_in[5];
    const float* Uk  = (const float*)d_in[6];
    const float* bk  = (const float*)d_in[7];
    const float* Wm  = (const float*)d_in[8];
    const float* Wq  = (const float*)d_in[9];
    const float* vat = (const float*)d_in[10];
    const float* Wa  = (const float*)d_in[11];
    const float* Wfc = (const float*)d_in[12];
    const float* bfc = (const float*)d_in[13];
    float* out = (float*)d_out;

    float* embA   = sym_addr(g_embA);
    float* zpre   = sym_addr(g_zpre);
    float* cbuf   = sym_addr(g_cbuf);
    float* hctx   = sym_addr(g_hctx);
    __half* keysh = sym_addr_h(g_keysh);
    __half* wqKh  = sym_addr_h(g_wqKh);
    __half* sA_h  = sym_addr_h(g_sA_h);
    __half* wT_h  = sym_addr_h(g_wT_h);
    __nv_bfloat16* wkuH = sym_addr_bf(g_wkuH);
    __nv_bfloat16* wkuL = sym_addr_bf(g_wkuL);
    __nv_bfloat16* uk0H = sym_addr_bf(g_uk0H);
    __nv_bfloat16* uk0L = sym_addr_bf(g_uk0L);
    __nv_bfloat16* wmT_h  = sym_addr_bf(g_wmT_h);
    __nv_bfloat16* wmT_l  = sym_addr_bf(g_wmT_l);
    __nv_bfloat16* wk0T_h = sym_addr_bf(g_wk0T_h);
    __nv_bfloat16* wk0T_l = sym_addr_bf(g_wk0T_l);
    __nv_bfloat16* wkpT_h = sym_addr_bf(g_wkpT_h);
    __nv_bfloat16* wkpT_l = sym_addr_bf(g_wkpT_l);
    __nv_bfloat16* waT_h  = sym_addr_bf(g_waT_h);
    __nv_bfloat16* waT_l  = sym_addr_bf(g_waT_l);

    cudaFuncSetAttribute(gemm3_kernel,
                         cudaFuncAttributeMaxDynamicSharedMemorySize, F_SMEM);
    cudaFuncSetAttribute(gemm_states_kernel,
                         cudaFuncAttributeMaxDynamicSharedMemorySize, F_SMEM);
    cudaFuncSetAttribute(step_loop_kernel,
                         cudaFuncAttributeMaxDynamicSharedMemorySize, P_SMEM);
    cudaFuncSetAttribute(gemm_vocab_f16,
                         cudaFuncAttributeMaxDynamicSharedMemorySize, V_SMEM);

    // 1: gather
    gather_emb_kernel<<<ROWS, 128>>>(dec, emb, embA);
    // 2: all weight converts (incl Wa split + Wfc fp16)
    mega_convert_kernel<<<20736, 256>>>(Wm, Wk, Uk, Wq, Wa, Wfc,
                                        wmT_h, wmT_l, wk0T_h, wk0T_l,
                                        wkpT_h, wkpT_l, wqKh, uk0H, uk0L,
                                        waT_h, waT_l, wT_h);
    // 3: keys(fp16) + zpre + wbig
    gemm3_kernel<<<504, 256, F_SMEM>>>(mem, wmT_h, wmT_l, keysh,
                                       embA, wk0T_h, wk0T_l, bk, zpre,
                                       Wa, wkpT_h, wkpT_l, Uk, wkuH, wkuL);
    // 4: persistent step loop  <-- ncu capture target
    step_loop_kernel<<<128, 512, P_SMEM>>>(
        h0, c0, uk0H, uk0L, wkuH, wkuL, zpre, cbuf, hctx,
        wqKh, keysh, mem, vat);
    // 5: states = hctx @ Wa -> fp16
    gemm_states_kernel<<<dim3(16, 4), 256, F_SMEM>>>(hctx, waT_h, waT_l, sA_h);
    // 6: vocab projection
    gemm_vocab_f16<<<dim3(MPAD / 128, VPAD / 128), 256, V_SMEM>>>(
        sA_h, wT_h, bfc, out);
}